// round 9
// baseline (speedup 1.0000x reference)
#include <cuda_runtime.h>
#include <cuda_bf16.h>
#include <cstdint>

#define BB 8
#define C_ 256
#define HW_ 4096
#define PHW_ 1024
#define EPS_ 1e-5f

// ---------------- helpers ----------------
__device__ __forceinline__ uint32_t smem_to_u32(const void* p) {
    uint32_t a;
    asm("{ .reg .u64 t; cvta.to.shared.u64 t, %1; cvt.u32.u64 %0, t; }" : "=r"(a) : "l"(p));
    return a;
}
__device__ __forceinline__ void ldsm4(uint32_t* r, uint32_t addr) {
    asm volatile("ldmatrix.sync.aligned.m8n8.x4.shared.b16 {%0,%1,%2,%3}, [%4];"
        : "=r"(r[0]), "=r"(r[1]), "=r"(r[2]), "=r"(r[3]) : "r"(addr));
}
__device__ __forceinline__ void ldsm4t(uint32_t* r, uint32_t addr) {
    asm volatile("ldmatrix.sync.aligned.m8n8.x4.trans.shared.b16 {%0,%1,%2,%3}, [%4];"
        : "=r"(r[0]), "=r"(r[1]), "=r"(r[2]), "=r"(r[3]) : "r"(addr));
}
__device__ __forceinline__ void mma16816(float* d, const uint32_t* a, uint32_t b0, uint32_t b1) {
    asm volatile("mma.sync.aligned.m16n8k16.row.col.f32.bf16.bf16.f32 "
        "{%0,%1,%2,%3}, {%4,%5,%6,%7}, {%8,%9}, {%0,%1,%2,%3};"
        : "+f"(d[0]), "+f"(d[1]), "+f"(d[2]), "+f"(d[3])
        : "r"(a[0]), "r"(a[1]), "r"(a[2]), "r"(a[3]), "r"(b0), "r"(b1));
}
__device__ __forceinline__ void cp16(uint32_t s, const void* g) {
    asm volatile("cp.async.cg.shared.global [%0], [%1], 16;" :: "r"(s), "l"(g));
}
#define CP_COMMIT() asm volatile("cp.async.commit_group;" ::: "memory")
#define CP_WAIT0()  asm volatile("cp.async.wait_group 0;" ::: "memory")
#define CP_WAIT1()  asm volatile("cp.async.wait_group 1;" ::: "memory")

__device__ __forceinline__ void split_bf16(float v, __nv_bfloat16& h, __nv_bfloat16& l) {
    h = __float2bfloat16(v);
    l = __float2bfloat16(v - __bfloat162float(h));
}
__device__ __forceinline__ void split2(float a, float b, uint32_t& hh, uint32_t& ll) {
    __nv_bfloat16 ha, la, hb, lb;
    split_bf16(a, ha, la); split_bf16(b, hb, lb);
    hh = (uint32_t)__bfloat16_as_ushort(ha) | ((uint32_t)__bfloat16_as_ushort(hb) << 16);
    ll = (uint32_t)__bfloat16_as_ushort(la) | ((uint32_t)__bfloat16_as_ushort(lb) << 16);
}

// A-fragment (m16k16) from [m][k] row-major smem, pitch 72
__device__ __forceinline__ uint32_t a_addr(uint32_t base, int row0, int k0, int lane) {
    int r = row0 + (lane & 15), c = k0 + ((lane >> 4) << 3);
    return base + (uint32_t)((r * 72 + c) * 2);
}
// A-fragment (m16k16) from [k][m] storage via trans-ldmatrix, pitch P
__device__ __forceinline__ uint32_t at_addr(uint32_t base, int m0, int k0, int lane, int P) {
    int t = lane >> 3;
    int m = m0 + ((t & 1) << 3);
    int k = k0 + ((t >> 1) << 3) + (lane & 7);
    return base + (uint32_t)((k * P + m) * 2);
}
// B-fragment x4 (two n8k16 tiles) from [n][k] row-major smem, pitch 72
__device__ __forceinline__ uint32_t b_addr(uint32_t base, int n0, int k0, int lane) {
    int r = n0 + (lane & 7) + ((lane >> 4) << 3), c = k0 + (((lane >> 3) & 1) << 3);
    return base + (uint32_t)((r * 72 + c) * 2);
}

// ---------------- scratch ----------------
__device__ __nv_bfloat16 d_xh[BB*C_*HW_], d_xl[BB*C_*HW_];
__device__ __nv_bfloat16 d_Wch[384*256],  d_Wcl[384*256];
__device__ float         d_bc[384];
__device__ __nv_bfloat16 d_Wfh[256*256],  d_Wfl[256*256];
__device__ __nv_bfloat16 d_Qh[BB*HW_*64],  d_Ql[BB*HW_*64];
__device__ __nv_bfloat16 d_Kh[BB*PHW_*64], d_Kl[BB*PHW_*64];
__device__ __nv_bfloat16 d_Vh[BB*C_*PHW_], d_Vl[BB*C_*PHW_];
__device__ __nv_bfloat16 d_Yh[BB*HW_*C_],  d_Yl[BB*HW_*C_];

// ======================================================================
// xsplit + weight packing (unchanged)
// ======================================================================
__global__ __launch_bounds__(256) void xsplit_kernel(
    const float* __restrict__ x, __nv_bfloat16* __restrict__ xh, __nv_bfloat16* __restrict__ xl)
{
    size_t i = ((size_t)blockIdx.x * 256 + threadIdx.x) * 4;
    float4 v = *(const float4*)(x + i);
    uint32_t h0, l0, h1, l1;
    split2(v.x, v.y, h0, l0);
    split2(v.z, v.w, h1, l1);
    *(uint2*)(xh + i) = make_uint2(h0, h1);
    *(uint2*)(xl + i) = make_uint2(l0, l1);
}

__global__ void wpack_conv_kernel(
    const float* __restrict__ g_w, const float* __restrict__ g_b,
    const float* __restrict__ th_w, const float* __restrict__ th_b,
    const float* __restrict__ ph_w, const float* __restrict__ ph_b,
    __nv_bfloat16* __restrict__ Wh, __nv_bfloat16* __restrict__ Wl, float* __restrict__ bc)
{
    int oc = blockIdx.x, k = threadIdx.x;
    float v;
    if (oc < 256)       v = g_w[oc * 256 + k];
    else if (oc < 320)  v = (k < 64) ? th_w[(oc - 256) * 64 + k] : 0.f;
    else                v = (k >= 64) ? ph_w[(oc - 320) * 192 + (k - 64)] : 0.f;
    __nv_bfloat16 h, l; split_bf16(v, h, l);
    Wh[oc * 256 + k] = h; Wl[oc * 256 + k] = l;
    if (k == 0)
        bc[oc] = (oc < 256) ? g_b[oc] : (oc < 320) ? th_b[oc - 256] : ph_b[oc - 320];
}

__global__ void wpack_final_kernel(const float* __restrict__ w,
    __nv_bfloat16* __restrict__ Wh, __nv_bfloat16* __restrict__ Wl)
{
    int i = blockIdx.x * 256 + threadIdx.x;
    __nv_bfloat16 h, l; split_bf16(w[i], h, l);
    Wh[i] = h; Wl[i] = l;
}

// ======================================================================
// conv_mma (unchanged from R7)
// ======================================================================
static constexpr int CONV_STG = 71680;
static constexpr int CONV_SMEM = 2 * CONV_STG;

__global__ __launch_bounds__(512) void conv_mma_kernel(
    const __nv_bfloat16* __restrict__ xh, const __nv_bfloat16* __restrict__ xl,
    const __nv_bfloat16* __restrict__ Wh, const __nv_bfloat16* __restrict__ Wl,
    const float* __restrict__ bc,
    __nv_bfloat16* __restrict__ Vh, __nv_bfloat16* __restrict__ Vl,
    __nv_bfloat16* __restrict__ Qh, __nv_bfloat16* __restrict__ Ql,
    __nv_bfloat16* __restrict__ Kh, __nv_bfloat16* __restrict__ Kl)
{
    extern __shared__ char smem[];
    const uint32_t sb = smem_to_u32(smem);
    float* sRes = (float*)smem;
    const int tid = threadIdx.x, lane = tid & 31, wid = tid >> 5;
    const int wm = wid & 3, wn = wid >> 2;
    const int b = blockIdx.z, pxt = blockIdx.y, oc0 = blockIdx.x * 128;

    auto prefetch = [&](int c) {
        uint32_t base = sb + (c & 1) * CONV_STG;
        const __nv_bfloat16* gxh = xh + ((size_t)b * C_ + c * 64) * HW_ + pxt * 128;
        const __nv_bfloat16* gxl = xl + ((size_t)b * C_ + c * 64) * HW_ + pxt * 128;
        for (int idx = tid; idx < 1024; idx += 512) {
            int r = idx >> 4, u = idx & 15;
            uint32_t so = (uint32_t)((r * 136 + u * 8) * 2);
            cp16(base + so,         gxh + (size_t)r * HW_ + u * 8);
            cp16(base + 17408 + so, gxl + (size_t)r * HW_ + u * 8);
        }
        const __nv_bfloat16* gwh = Wh + (size_t)oc0 * 256 + c * 64;
        const __nv_bfloat16* gwl = Wl + (size_t)oc0 * 256 + c * 64;
        for (int idx = tid; idx < 1024; idx += 512) {
            int r = idx >> 3, u = idx & 7;
            uint32_t so = (uint32_t)((r * 72 + u * 8) * 2);
            cp16(base + 34816 + so, gwh + (size_t)r * 256 + u * 8);
            cp16(base + 53248 + so, gwl + (size_t)r * 256 + u * 8);
        }
        CP_COMMIT();
    };

    float acc[2][4][4];
#pragma unroll
    for (int mt = 0; mt < 2; mt++)
#pragma unroll
        for (int nt = 0; nt < 4; nt++)
#pragma unroll
            for (int e = 0; e < 4; e++) acc[mt][nt][e] = 0.f;

    prefetch(0);
    for (int ck = 0; ck < 4; ck++) {
        if (ck + 1 < 4) { prefetch(ck + 1); CP_WAIT1(); } else CP_WAIT0();
        __syncthreads();
        uint32_t base = sb + (ck & 1) * CONV_STG;
#pragma unroll
        for (int ks = 0; ks < 4; ks++) {
            const int k0 = ks * 16;
            uint32_t ah[2][4], al[2][4], bh[2][4], bl[2][4];
            ldsm4t(ah[0], at_addr(base, wm * 32,      k0, lane, 136));
            ldsm4t(ah[1], at_addr(base, wm * 32 + 16, k0, lane, 136));
            ldsm4(bh[0], b_addr(base + 34816, wn * 32,      k0, lane));
            ldsm4(bh[1], b_addr(base + 34816, wn * 32 + 16, k0, lane));
#pragma unroll
            for (int g = 0; g < 2; g++)
#pragma unroll
                for (int mt = 0; mt < 2; mt++) {
                    mma16816(acc[mt][g*2],   ah[mt], bh[g][0], bh[g][1]);
                    mma16816(acc[mt][g*2+1], ah[mt], bh[g][2], bh[g][3]);
                }
            ldsm4(bl[0], b_addr(base + 53248, wn * 32,      k0, lane));
            ldsm4(bl[1], b_addr(base + 53248, wn * 32 + 16, k0, lane));
#pragma unroll
            for (int g = 0; g < 2; g++)
#pragma unroll
                for (int mt = 0; mt < 2; mt++) {
                    mma16816(acc[mt][g*2],   ah[mt], bl[g][0], bl[g][1]);
                    mma16816(acc[mt][g*2+1], ah[mt], bl[g][2], bl[g][3]);
                }
            ldsm4t(al[0], at_addr(base + 17408, wm * 32,      k0, lane, 136));
            ldsm4t(al[1], at_addr(base + 17408, wm * 32 + 16, k0, lane, 136));
#pragma unroll
            for (int g = 0; g < 2; g++)
#pragma unroll
                for (int mt = 0; mt < 2; mt++) {
                    mma16816(acc[mt][g*2],   al[mt], bh[g][0], bh[g][1]);
                    mma16816(acc[mt][g*2+1], al[mt], bh[g][2], bh[g][3]);
                }
        }
        __syncthreads();
    }

#pragma unroll
    for (int mt = 0; mt < 2; mt++) {
        const int row = wm * 32 + mt * 16 + (lane >> 2);
#pragma unroll
        for (int nt = 0; nt < 4; nt++) {
            const int col = wn * 32 + nt * 8 + (lane & 3) * 2;
            sRes[row * 132 + col]       = acc[mt][nt][0];
            sRes[row * 132 + col + 1]   = acc[mt][nt][1];
            sRes[(row+8) * 132 + col]   = acc[mt][nt][2];
            sRes[(row+8) * 132 + col+1] = acc[mt][nt][3];
        }
    }
    __syncthreads();

    if (oc0 < 256) {
        for (int t = tid; t < 32 * 128; t += 512) {
            int pw = t >> 7, lo = t & 127, oc = oc0 + lo;
            float v = fmaxf(fmaxf(sRes[(2*pw)*132 + lo], sRes[(2*pw+1)*132 + lo]),
                            fmaxf(sRes[(64+2*pw)*132 + lo], sRes[(65+2*pw)*132 + lo]))
                      + bc[oc];
            __nv_bfloat16 h, l; split_bf16(v, h, l);
            size_t oidx = ((size_t)b * C_ + oc) * PHW_ + pxt * 32 + pw;
            Vh[oidx] = h; Vl[oidx] = l;
        }
    } else {
        for (int t = tid; t < 128 * 64; t += 512) {
            int p = t >> 6, o = t & 63;
            float v = sRes[p * 132 + o] + bc[256 + o];
            __nv_bfloat16 h, l; split_bf16(v, h, l);
            size_t oidx = ((size_t)b * HW_ + pxt * 128 + p) * 64 + o;
            Qh[oidx] = h; Ql[oidx] = l;
        }
        for (int t = tid; t < 32 * 64; t += 512) {
            int pw = t >> 6, o = t & 63, lo = 64 + o;
            float v = fmaxf(fmaxf(sRes[(2*pw)*132 + lo], sRes[(2*pw+1)*132 + lo]),
                            fmaxf(sRes[(64+2*pw)*132 + lo], sRes[(65+2*pw)*132 + lo]))
                      + bc[320 + o];
            __nv_bfloat16 h, l; split_bf16(v, h, l);
            size_t oidx = ((size_t)b * PHW_ + pxt * 32 + pw) * 64 + o;
            Kh[oidx] = h; Kl[oidx] = l;
        }
    }
}

// ======================================================================
// fa_mma: fused softmax(Q K^T) @ V — P never leaves smem.
// grid (32, 8), block 512 (16 warps).
// smem: Q hi/lo @0 (36864); K stage s @ 36864+s*18432 (hi, lo@+9216);
//       V hi @73728, lo @110592 (single buffer); P hi @147456, lo @165888;
//       rs float[4][128] @184320.  Total 186368.
// ======================================================================
static constexpr int FA_K    = 36864;
static constexpr int FA_V    = 73728;
static constexpr int FA_P    = 147456;
static constexpr int FA_RS   = 184320;
static constexpr int FA_SMEM = 186368;

__global__ __launch_bounds__(512) void fa_mma_kernel(
    const __nv_bfloat16* __restrict__ Qh, const __nv_bfloat16* __restrict__ Ql,
    const __nv_bfloat16* __restrict__ Kh, const __nv_bfloat16* __restrict__ Kl,
    const __nv_bfloat16* __restrict__ Vh, const __nv_bfloat16* __restrict__ Vl,
    __nv_bfloat16* __restrict__ Yh, __nv_bfloat16* __restrict__ Yl)
{
    extern __shared__ char smem[];
    const uint32_t sb = smem_to_u32(smem);
    const int tid = threadIdx.x, lane = tid & 31, wid = tid >> 5;
    const int wm = wid & 3, wn = wid >> 2;
    const int b = blockIdx.y, n0 = blockIdx.x * 128;

    auto pf_k = [&](int c) {            // 64 rows x 64 k, hi/lo
        uint32_t base = sb + FA_K + (c & 1) * 18432;
        const __nv_bfloat16* gkh = Kh + ((size_t)b * PHW_ + c * 64) * 64;
        const __nv_bfloat16* gkl = Kl + ((size_t)b * PHW_ + c * 64) * 64;
        if (tid < 512) {
            int r = tid >> 3, u = tid & 7;
            uint32_t so = (uint32_t)((r * 72 + u * 8) * 2);
            cp16(base + so,        gkh + r * 64 + u * 8);
            cp16(base + 9216 + so, gkl + r * 64 + u * 8);
        }
        CP_COMMIT();
    };
    auto pf_v = [&](int c) {            // 256 c x 64 m, hi/lo
        const __nv_bfloat16* gvh = Vh + (size_t)b * C_ * PHW_ + c * 64;
        const __nv_bfloat16* gvl = Vl + (size_t)b * C_ * PHW_ + c * 64;
        for (int idx = tid; idx < 2048; idx += 512) {
            int r = idx >> 3, u = idx & 7;
            uint32_t so = (uint32_t)((r * 72 + u * 8) * 2);
            cp16(sb + FA_V + so,          gvh + (size_t)r * PHW_ + u * 8);
            cp16(sb + FA_V + 36864 + so,  gvl + (size_t)r * PHW_ + u * 8);
        }
        CP_COMMIT();
    };

    pf_k(0);
    pf_v(0);
    {   // resident Q tile (plain loads overlap the cp.async)
        const __nv_bfloat16* gqh = Qh + ((size_t)b * HW_ + n0) * 64;
        const __nv_bfloat16* gql = Ql + ((size_t)b * HW_ + n0) * 64;
        for (int idx = tid; idx < 1024; idx += 512) {
            int r = idx >> 3, u = idx & 7;
            *(uint4*)(smem + (r * 72 + u * 8) * 2)          = *(const uint4*)(gqh + r * 64 + u * 8);
            *(uint4*)(smem + 18432 + (r * 72 + u * 8) * 2)  = *(const uint4*)(gql + r * 64 + u * 8);
        }
    }

    float acc[2][8][4];
#pragma unroll
    for (int mt = 0; mt < 2; mt++)
#pragma unroll
        for (int nt = 0; nt < 8; nt++)
#pragma unroll
            for (int e = 0; e < 4; e++) acc[mt][nt][e] = 0.f;
    float rsum[2][2] = {{0.f, 0.f}, {0.f, 0.f}};

    for (int ck = 0; ck < 16; ck++) {
        CP_WAIT1();            // K(ck) complete (V(ck) may still pend)
        __syncthreads();       // K visible to all; prev P-MMA already synced
        const uint32_t kb = sb + FA_K + (ck & 1) * 18432;

        // ---- S = Q · K^T (128 x 64), warp tile 32 x 16 ----
        float sa[2][2][4];
#pragma unroll
        for (int mt = 0; mt < 2; mt++)
#pragma unroll
            for (int nt = 0; nt < 2; nt++)
#pragma unroll
                for (int e = 0; e < 4; e++) sa[mt][nt][e] = 0.f;
#pragma unroll
        for (int ks = 0; ks < 4; ks++) {
            const int k0 = ks * 16;
            uint32_t ah[2][4], al[2][4], bh[4], bl[4];
            ldsm4(ah[0], a_addr(sb,        wm * 32,      k0, lane));
            ldsm4(ah[1], a_addr(sb,        wm * 32 + 16, k0, lane));
            ldsm4(bh, b_addr(kb, wn * 16, k0, lane));
#pragma unroll
            for (int mt = 0; mt < 2; mt++) {
                mma16816(sa[mt][0], ah[mt], bh[0], bh[1]);
                mma16816(sa[mt][1], ah[mt], bh[2], bh[3]);
            }
            ldsm4(bl, b_addr(kb + 9216, wn * 16, k0, lane));
#pragma unroll
            for (int mt = 0; mt < 2; mt++) {
                mma16816(sa[mt][0], ah[mt], bl[0], bl[1]);
                mma16816(sa[mt][1], ah[mt], bl[2], bl[3]);
            }
            ldsm4(al[0], a_addr(sb + 18432, wm * 32,      k0, lane));
            ldsm4(al[1], a_addr(sb + 18432, wm * 32 + 16, k0, lane));
#pragma unroll
            for (int mt = 0; mt < 2; mt++) {
                mma16816(sa[mt][0], al[mt], bh[0], bh[1]);
                mma16816(sa[mt][1], al[mt], bh[2], bh[3]);
            }
        }

        // K(ck+1): its stage buffer was last read at S-MMA(ck-1), already synced
        if (ck + 1 < 16) pf_k(ck + 1);

        // ---- exp + pack P into smem, accumulate row sums ----
#pragma unroll
        for (int mt = 0; mt < 2; mt++) {
            const int row = wm * 32 + mt * 16 + (lane >> 2);
#pragma unroll
            for (int nt = 0; nt < 2; nt++) {
                float e0 = __expf(sa[mt][nt][0]);
                float e1 = __expf(sa[mt][nt][1]);
                float e2 = __expf(sa[mt][nt][2]);
                float e3 = __expf(sa[mt][nt][3]);
                rsum[mt][0] += e0 + e1;
                rsum[mt][1] += e2 + e3;
                const int col = wn * 16 + nt * 8 + (lane & 3) * 2;
                uint32_t hh, ll;
                split2(e0, e1, hh, ll);
                *(uint32_t*)(smem + FA_P + (row * 72 + col) * 2)          = hh;
                *(uint32_t*)(smem + FA_P + 18432 + (row * 72 + col) * 2)  = ll;
                split2(e2, e3, hh, ll);
                *(uint32_t*)(smem + FA_P + ((row+8) * 72 + col) * 2)         = hh;
                *(uint32_t*)(smem + FA_P + 18432 + ((row+8) * 72 + col) * 2) = ll;
            }
        }

        if (ck == 15) CP_WAIT0(); else CP_WAIT1();   // V(ck) complete
        __syncthreads();        // P + V visible to all

        // ---- Y += P · V^T (128 x 256), warp tile 32 x 64 ----
        const uint32_t pb = sb + FA_P, vb = sb + FA_V;
#pragma unroll
        for (int ks = 0; ks < 4; ks++) {
            const int k0 = ks * 16;
            uint32_t ah[2][4], al[2][4], bh[4][4], bt[4];
            ldsm4(ah[0], a_addr(pb, wm * 32,      k0, lane));
            ldsm4(ah[1], a_addr(pb, wm * 32 + 16, k0, lane));
#pragma unroll
            for (int g = 0; g < 4; g++)
                ldsm4(bh[g], b_addr(vb, wn * 64 + g * 16, k0, lane));
#pragma unroll
            for (int g = 0; g < 4; g++)
#pragma unroll
                for (int mt = 0; mt < 2; mt++) {
                    mma16816(acc[mt][g*2],   ah[mt], bh[g][0], bh[g][1]);
                    mma16816(acc[mt][g*2+1], ah[mt], bh[g][2], bh[g][3]);
                }
#pragma unroll
            for (int g = 0; g < 4; g++) {
                ldsm4(bt, b_addr(vb + 36864, wn * 64 + g * 16, k0, lane));
#pragma unroll
                for (int mt = 0; mt < 2; mt++) {
                    mma16816(acc[mt][g*2],   ah[mt], bt[0], bt[1]);
                    mma16816(acc[mt][g*2+1], ah[mt], bt[2], bt[3]);
                }
            }
            ldsm4(al[0], a_addr(pb + 18432, wm * 32,      k0, lane));
            ldsm4(al[1], a_addr(pb + 18432, wm * 32 + 16, k0, lane));
#pragma unroll
            for (int g = 0; g < 4; g++)
#pragma unroll
                for (int mt = 0; mt < 2; mt++) {
                    mma16816(acc[mt][g*2],   al[mt], bh[g][0], bh[g][1]);
                    mma16816(acc[mt][g*2+1], al[mt], bh[g][2], bh[g][3]);
                }
        }
        __syncthreads();        // all done reading P + V
        if (ck + 1 < 16) pf_v(ck + 1);
    }

    // ---- row-sum reduce across wn warps ----
    float* rs = (float*)(smem + FA_RS);     // [4][128]
#pragma unroll
    for (int mt = 0; mt < 2; mt++)
#pragma unroll
        for (int hh = 0; hh < 2; hh++) {
            float s = rsum[mt][hh];
            s += __shfl_xor_sync(0xffffffffu, s, 1);
            s += __shfl_xor_sync(0xffffffffu, s, 2);
            if ((lane & 3) == 0)
                rs[wn * 128 + wm * 32 + mt * 16 + hh * 8 + (lane >> 2)] = s;
        }
    __syncthreads();

    // ---- epilogue: scale 1/rowsum, split hi/lo, store Y [n][c] ----
#pragma unroll
    for (int mt = 0; mt < 2; mt++) {
        const int r0 = wm * 32 + mt * 16 + (lane >> 2);
        const float i0 = 1.f / (rs[r0] + rs[128 + r0] + rs[256 + r0] + rs[384 + r0]);
        const float i1 = 1.f / (rs[r0+8] + rs[128 + r0+8] + rs[256 + r0+8] + rs[384 + r0+8]);
#pragma unroll
        for (int nt = 0; nt < 8; nt++) {
            const int col = wn * 64 + nt * 8 + (lane & 3) * 2;
            uint32_t hh, ll;
            split2(acc[mt][nt][0] * i0, acc[mt][nt][1] * i0, hh, ll);
            *(uint32_t*)&Yh[((size_t)b * HW_ + n0 + r0) * C_ + col] = hh;
            *(uint32_t*)&Yl[((size_t)b * HW_ + n0 + r0) * C_ + col] = ll;
            split2(acc[mt][nt][2] * i1, acc[mt][nt][3] * i1, hh, ll);
            *(uint32_t*)&Yh[((size_t)b * HW_ + n0 + r0 + 8) * C_ + col] = hh;
            *(uint32_t*)&Yl[((size_t)b * HW_ + n0 + r0 + 8) * C_ + col] = ll;
        }
    }
}

// ======================================================================
// final_mma (unchanged from R7)
// ======================================================================
static constexpr int FIN_STG = 73728;
static constexpr int FIN_SMEM = 2 * FIN_STG;

__global__ __launch_bounds__(512) void final_mma_kernel(
    const __nv_bfloat16* __restrict__ Yh, const __nv_bfloat16* __restrict__ Yl,
    const __nv_bfloat16* __restrict__ Wh, const __nv_bfloat16* __restrict__ Wl,
    const float* __restrict__ Wb,
    const float* __restrict__ gamma, const float* __restrict__ beta,
    const float* __restrict__ mean, const float* __restrict__ var,
    const float* __restrict__ x, float* __restrict__ out)
{
    extern __shared__ char smem[];
    const uint32_t sb = smem_to_u32(smem);
    float* sRes = (float*)smem;
    const int tid = threadIdx.x, lane = tid & 31, wid = tid >> 5;
    const int wm = wid & 3, wn = wid >> 2;
    const int b = blockIdx.z, pxt = blockIdx.y, oc0 = blockIdx.x * 128;

    auto prefetch = [&](int c) {
        uint32_t base = sb + (c & 1) * FIN_STG;
        const __nv_bfloat16* gah = Yh + ((size_t)b * HW_ + pxt * 128) * C_ + c * 64;
        const __nv_bfloat16* gal = Yl + ((size_t)b * HW_ + pxt * 128) * C_ + c * 64;
        for (int idx = tid; idx < 1024; idx += 512) {
            int r = idx >> 3, u = idx & 7;
            uint32_t so = (uint32_t)((r * 72 + u * 8) * 2);
            cp16(base + so,         gah + (size_t)r * C_ + u * 8);
            cp16(base + 18432 + so, gal + (size_t)r * C_ + u * 8);
        }
        const __nv_bfloat16* gbh = Wh + (size_t)oc0 * 256 + c * 64;
        const __nv_bfloat16* gbl = Wl + (size_t)oc0 * 256 + c * 64;
        for (int idx = tid; idx < 1024; idx += 512) {
            int r = idx >> 3, u = idx & 7;
            uint32_t so = (uint32_t)((r * 72 + u * 8) * 2);
            cp16(base + 36864 + so, gbh + (size_t)r * 256 + u * 8);
            cp16(base + 55296 + so, gbl + (size_t)r * 256 + u * 8);
        }
        CP_COMMIT();
    };

    float acc[2][4][4];
#pragma unroll
    for (int mt = 0; mt < 2; mt++)
#pragma unroll
        for (int nt = 0; nt < 4; nt++)
#pragma unroll
            for (int e = 0; e < 4; e++) acc[mt][nt][e] = 0.f;

    prefetch(0);
    for (int ck = 0; ck < 4; ck++) {
        if (ck + 1 < 4) { prefetch(ck + 1); CP_WAIT1(); } else CP_WAIT0();
        __syncthreads();
        uint32_t base = sb + (ck & 1) * FIN_STG;
#pragma unroll
        for (int ks = 0; ks < 4; ks++) {
            const int k0 = ks * 16;
            uint32_t ah[2][4], al[2][4], bh[2][4], bl[2][4];
            ldsm4(ah[0], a_addr(base, wm * 32,      k0, lane));
            ldsm4(ah[1], a_addr(base, wm * 32 + 16, k0, lane));
            ldsm4(bh[0], b_addr(base + 36864, wn * 32,      k0, lane));
            ldsm4(bh[1], b_addr(base + 36864, wn * 32 + 16, k0, lane));
#pragma unroll
            for (int g = 0; g < 2; g++)
#pragma unroll
                for (int mt = 0; mt < 2; mt++) {
                    mma16816(acc[mt][g*2],   ah[mt], bh[g][0], bh[g][1]);
                    mma16816(acc[mt][g*2+1], ah[mt], bh[g][2], bh[g][3]);
                }
            ldsm4(bl[0], b_addr(base + 55296, wn * 32,      k0, lane));
            ldsm4(bl[1], b_addr(base + 55296, wn * 32 + 16, k0, lane));
#pragma unroll
            for (int g = 0; g < 2; g++)
#pragma unroll
                for (int mt = 0; mt < 2; mt++) {
                    mma16816(acc[mt][g*2],   ah[mt], bl[g][0], bl[g][1]);
                    mma16816(acc[mt][g*2+1], ah[mt], bl[g][2], bl[g][3]);
                }
            ldsm4(al[0], a_addr(base + 18432, wm * 32,      k0, lane));
            ldsm4(al[1], a_addr(base + 18432, wm * 32 + 16, k0, lane));
#pragma unroll
            for (int g = 0; g < 2; g++)
#pragma unroll
                for (int mt = 0; mt < 2; mt++) {
                    mma16816(acc[mt][g*2],   al[mt], bh[g][0], bh[g][1]);
                    mma16816(acc[mt][g*2+1], al[mt], bh[g][2], bh[g][3]);
                }
        }
        __syncthreads();
    }

#pragma unroll
    for (int mt = 0; mt < 2; mt++) {
        const int row = wm * 32 + mt * 16 + (lane >> 2);
#pragma unroll
        for (int nt = 0; nt < 4; nt++) {
            const int col = wn * 32 + nt * 8 + (lane & 3) * 2;
            sRes[row * 132 + col]       = acc[mt][nt][0];
            sRes[row * 132 + col + 1]   = acc[mt][nt][1];
            sRes[(row+8) * 132 + col]   = acc[mt][nt][2];
            sRes[(row+8) * 132 + col+1] = acc[mt][nt][3];
        }
    }
    __syncthreads();

    for (int t = tid; t < 128 * 128; t += 512) {
        int o = t >> 7, p = t & 127;
        int oc = oc0 + o;
        float scale = gamma[oc] * rsqrtf(var[oc] + EPS_);
        size_t gidx = ((size_t)b * C_ + oc) * HW_ + pxt * 128 + p;
        out[gidx] = (sRes[p * 132 + o] + Wb[oc] - mean[oc]) * scale + beta[oc] + x[gidx];
    }
}

// ======================================================================
extern "C" void kernel_launch(void* const* d_in, const int* in_sizes, int n_in,
                              void* d_out, int out_size)
{
    const float* x       = (const float*)d_in[0];
    const float* g_w     = (const float*)d_in[1];
    const float* g_b     = (const float*)d_in[2];
    const float* theta_w = (const float*)d_in[3];
    const float* theta_b = (const float*)d_in[4];
    const float* phi_w   = (const float*)d_in[5];
    const float* phi_b   = (const float*)d_in[6];
    const float* W_w     = (const float*)d_in[7];
    const float* W_b     = (const float*)d_in[8];
    const float* bn_g    = (const float*)d_in[9];
    const float* bn_b    = (const float*)d_in[10];
    const float* bn_m    = (const float*)d_in[11];
    const float* bn_v    = (const float*)d_in[12];
    float* out = (float*)d_out;

    __nv_bfloat16 *xh, *xl, *Wch, *Wcl, *Wfh, *Wfl;
    __nv_bfloat16 *Qh, *Ql, *Kh, *Kl, *Vh, *Vl, *Yh, *Yl;
    float *bc;
    cudaGetSymbolAddress((void**)&xh,  d_xh);
    cudaGetSymbolAddress((void**)&xl,  d_xl);
    cudaGetSymbolAddress((void**)&Wch, d_Wch);
    cudaGetSymbolAddress((void**)&Wcl, d_Wcl);
    cudaGetSymbolAddress((void**)&bc,  d_bc);
    cudaGetSymbolAddress((void**)&Wfh, d_Wfh);
    cudaGetSymbolAddress((void**)&Wfl, d_Wfl);
    cudaGetSymbolAddress((void**)&Qh,  d_Qh);
    cudaGetSymbolAddress((void**)&Ql,  d_Ql);
    cudaGetSymbolAddress((void**)&Kh,  d_Kh);
    cudaGetSymbolAddress((void**)&Kl,  d_Kl);
    cudaGetSymbolAddress((void**)&Vh,  d_Vh);
    cudaGetSymbolAddress((void**)&Vl,  d_Vl);
    cudaGetSymbolAddress((void**)&Yh,  d_Yh);
    cudaGetSymbolAddress((void**)&Yl,  d_Yl);

    cudaFuncSetAttribute(conv_mma_kernel,  cudaFuncAttributeMaxDynamicSharedMemorySize, CONV_SMEM);
    cudaFuncSetAttribute(fa_mma_kernel,    cudaFuncAttributeMaxDynamicSharedMemorySize, FA_SMEM);
    cudaFuncSetAttribute(final_mma_kernel, cudaFuncAttributeMaxDynamicSharedMemorySize, FIN_SMEM);

    xsplit_kernel<<<BB * C_ * HW_ / 1024, 256>>>(x, xh, xl);
    wpack_conv_kernel<<<384, 256>>>(g_w, g_b, theta_w, theta_b, phi_w, phi_b, Wch, Wcl, bc);
    wpack_final_kernel<<<256, 256>>>(W_w, Wfh, Wfl);
    conv_mma_kernel<<<dim3(3, 32, BB), 512, CONV_SMEM>>>(xh, xl, Wch, Wcl, bc,
                                                         Vh, Vl, Qh, Ql, Kh, Kl);
    fa_mma_kernel<<<dim3(32, BB), 512, FA_SMEM>>>(Qh, Ql, Kh, Kl, Vh, Vl, Yh, Yl);
    final_mma_kernel<<<dim3(2, 32, BB), 512, FIN_SMEM>>>(Yh, Yl, Wfh, Wfl, W_b,
                                                         bn_g, bn_b, bn_m, bn_v, x, out);
}

// round 11
// speedup vs baseline: 1.3660x; 1.3660x over previous
#include <cuda_runtime.h>
#include <cuda_bf16.h>
#include <cstdint>

#define BB 8
#define C_ 256
#define HW_ 4096
#define PHW_ 1024
#define EPS_ 1e-5f

// ---------------- helpers ----------------
__device__ __forceinline__ uint32_t smem_to_u32(const void* p) {
    uint32_t a;
    asm("{ .reg .u64 t; cvta.to.shared.u64 t, %1; cvt.u32.u64 %0, t; }" : "=r"(a) : "l"(p));
    return a;
}
__device__ __forceinline__ void ldsm4(uint32_t* r, uint32_t addr) {
    asm volatile("ldmatrix.sync.aligned.m8n8.x4.shared.b16 {%0,%1,%2,%3}, [%4];"
        : "=r"(r[0]), "=r"(r[1]), "=r"(r[2]), "=r"(r[3]) : "r"(addr));
}
__device__ __forceinline__ void ldsm4t(uint32_t* r, uint32_t addr) {
    asm volatile("ldmatrix.sync.aligned.m8n8.x4.trans.shared.b16 {%0,%1,%2,%3}, [%4];"
        : "=r"(r[0]), "=r"(r[1]), "=r"(r[2]), "=r"(r[3]) : "r"(addr));
}
__device__ __forceinline__ void mma16816(float* d, const uint32_t* a, uint32_t b0, uint32_t b1) {
    asm volatile("mma.sync.aligned.m16n8k16.row.col.f32.bf16.bf16.f32 "
        "{%0,%1,%2,%3}, {%4,%5,%6,%7}, {%8,%9}, {%0,%1,%2,%3};"
        : "+f"(d[0]), "+f"(d[1]), "+f"(d[2]), "+f"(d[3])
        : "r"(a[0]), "r"(a[1]), "r"(a[2]), "r"(a[3]), "r"(b0), "r"(b1));
}
__device__ __forceinline__ void cp16(uint32_t s, const void* g) {
    asm volatile("cp.async.cg.shared.global [%0], [%1], 16;" :: "r"(s), "l"(g));
}
#define CP_COMMIT() asm volatile("cp.async.commit_group;" ::: "memory")
#define CP_WAIT0()  asm volatile("cp.async.wait_group 0;" ::: "memory")
#define CP_WAIT1()  asm volatile("cp.async.wait_group 1;" ::: "memory")

__device__ __forceinline__ void split_bf16(float v, __nv_bfloat16& h, __nv_bfloat16& l) {
    h = __float2bfloat16(v);
    l = __float2bfloat16(v - __bfloat162float(h));
}
__device__ __forceinline__ void split2(float a, float b, uint32_t& hh, uint32_t& ll) {
    __nv_bfloat16 ha, la, hb, lb;
    split_bf16(a, ha, la); split_bf16(b, hb, lb);
    hh = (uint32_t)__bfloat16_as_ushort(ha) | ((uint32_t)__bfloat16_as_ushort(hb) << 16);
    ll = (uint32_t)__bfloat16_as_ushort(la) | ((uint32_t)__bfloat16_as_ushort(lb) << 16);
}

// A-fragment (m16k16) from [m][k] row-major smem, pitch P elems
__device__ __forceinline__ uint32_t a_addrP(uint32_t base, int row0, int k0, int lane, int P) {
    int r = row0 + (lane & 15), c = k0 + ((lane >> 4) << 3);
    return base + (uint32_t)((r * P + c) * 2);
}
// A-fragment (m16k16) from [k][m] storage via trans-ldmatrix, pitch P
__device__ __forceinline__ uint32_t at_addr(uint32_t base, int m0, int k0, int lane, int P) {
    int t = lane >> 3;
    int m = m0 + ((t & 1) << 3);
    int k = k0 + ((t >> 1) << 3) + (lane & 7);
    return base + (uint32_t)((k * P + m) * 2);
}
// B-fragment x4 (two n8k16 tiles) from [n][k] row-major smem, pitch P
__device__ __forceinline__ uint32_t b_addrP(uint32_t base, int n0, int k0, int lane, int P) {
    int r = n0 + (lane & 7) + ((lane >> 4) << 3), c = k0 + (((lane >> 3) & 1) << 3);
    return base + (uint32_t)((r * P + c) * 2);
}

// ---------------- scratch ----------------
__device__ __nv_bfloat16 d_xh[BB*C_*HW_], d_xl[BB*C_*HW_];
__device__ __nv_bfloat16 d_Wch[384*256],  d_Wcl[384*256];
__device__ float         d_bc[384];
__device__ __nv_bfloat16 d_Wfh[256*256],  d_Wfl[256*256];
__device__ __nv_bfloat16 d_Qh[BB*HW_*64],  d_Ql[BB*HW_*64];
__device__ __nv_bfloat16 d_Kh[BB*PHW_*64], d_Kl[BB*PHW_*64];
__device__ __nv_bfloat16 d_Vh[BB*C_*PHW_], d_Vl[BB*C_*PHW_];
__device__ __nv_bfloat16 d_Ph[(size_t)BB*HW_*PHW_], d_Pl[(size_t)BB*HW_*PHW_];
__device__ float         d_rinv[BB*HW_];
__device__ __nv_bfloat16 d_Yh[BB*HW_*C_],  d_Yl[BB*HW_*C_];

// ======================================================================
// xsplit + weight packing
// ======================================================================
__global__ __launch_bounds__(256) void xsplit_kernel(
    const float* __restrict__ x, __nv_bfloat16* __restrict__ xh, __nv_bfloat16* __restrict__ xl)
{
    size_t i = ((size_t)blockIdx.x * 256 + threadIdx.x) * 4;
    float4 v = *(const float4*)(x + i);
    uint32_t h0, l0, h1, l1;
    split2(v.x, v.y, h0, l0);
    split2(v.z, v.w, h1, l1);
    *(uint2*)(xh + i) = make_uint2(h0, h1);
    *(uint2*)(xl + i) = make_uint2(l0, l1);
}

__global__ void wpack_conv_kernel(
    const float* __restrict__ g_w, const float* __restrict__ g_b,
    const float* __restrict__ th_w, const float* __restrict__ th_b,
    const float* __restrict__ ph_w, const float* __restrict__ ph_b,
    __nv_bfloat16* __restrict__ Wh, __nv_bfloat16* __restrict__ Wl, float* __restrict__ bc)
{
    int oc = blockIdx.x, k = threadIdx.x;
    float v;
    if (oc < 256)       v = g_w[oc * 256 + k];
    else if (oc < 320)  v = (k < 64) ? th_w[(oc - 256) * 64 + k] : 0.f;
    else                v = (k >= 64) ? ph_w[(oc - 320) * 192 + (k - 64)] : 0.f;
    __nv_bfloat16 h, l; split_bf16(v, h, l);
    Wh[oc * 256 + k] = h; Wl[oc * 256 + k] = l;
    if (k == 0)
        bc[oc] = (oc < 256) ? g_b[oc] : (oc < 320) ? th_b[oc - 256] : ph_b[oc - 320];
}

__global__ void wpack_final_kernel(const float* __restrict__ w,
    __nv_bfloat16* __restrict__ Wh, __nv_bfloat16* __restrict__ Wl)
{
    int i = blockIdx.x * 256 + threadIdx.x;
    __nv_bfloat16 h, l; split_bf16(w[i], h, l);
    Wh[i] = h; Wl[i] = l;
}

// ======================================================================
// conv_mma: CTA = 128 px x 64 oc, grid (6, 32, 8), block 256 (4m x 2n),
// 2 CTAs/SM.  stage s @ s*53248: Xh[64][136] Xl(+17408)
// Wh[64][72](+34816) Wl(+44032).  sRes [128][68] fp32 union at 0.
// ======================================================================
static constexpr int CONV_STG  = 53248;
static constexpr int CONV_SMEM = 2 * CONV_STG;

__global__ __launch_bounds__(256, 2) void conv_mma_kernel(
    const __nv_bfloat16* __restrict__ xh, const __nv_bfloat16* __restrict__ xl,
    const __nv_bfloat16* __restrict__ Wh, const __nv_bfloat16* __restrict__ Wl,
    const float* __restrict__ bc,
    __nv_bfloat16* __restrict__ Vh, __nv_bfloat16* __restrict__ Vl,
    __nv_bfloat16* __restrict__ Qh, __nv_bfloat16* __restrict__ Ql,
    __nv_bfloat16* __restrict__ Kh, __nv_bfloat16* __restrict__ Kl)
{
    extern __shared__ char smem[];
    const uint32_t sb = smem_to_u32(smem);
    float* sRes = (float*)smem;
    const int tid = threadIdx.x, lane = tid & 31, wid = tid >> 5;
    const int wm = wid & 3, wn = wid >> 2;       // 4m x 2n warps
    const int b = blockIdx.z, pxt = blockIdx.y, oc0 = blockIdx.x * 64;

    auto prefetch = [&](int c) {
        uint32_t base = sb + (c & 1) * CONV_STG;
        const __nv_bfloat16* gxh = xh + ((size_t)b * C_ + c * 64) * HW_ + pxt * 128;
        const __nv_bfloat16* gxl = xl + ((size_t)b * C_ + c * 64) * HW_ + pxt * 128;
        for (int idx = tid; idx < 1024; idx += 256) {
            int r = idx >> 4, u = idx & 15;
            uint32_t so = (uint32_t)((r * 136 + u * 8) * 2);
            cp16(base + so,         gxh + (size_t)r * HW_ + u * 8);
            cp16(base + 17408 + so, gxl + (size_t)r * HW_ + u * 8);
        }
        const __nv_bfloat16* gwh = Wh + (size_t)oc0 * 256 + c * 64;
        const __nv_bfloat16* gwl = Wl + (size_t)oc0 * 256 + c * 64;
        for (int idx = tid; idx < 512; idx += 256) {    // 64 oc x 64 k
            int r = idx >> 3, u = idx & 7;
            uint32_t so = (uint32_t)((r * 72 + u * 8) * 2);
            cp16(base + 34816 + so, gwh + (size_t)r * 256 + u * 8);
            cp16(base + 44032 + so, gwl + (size_t)r * 256 + u * 8);
        }
        CP_COMMIT();
    };

    float acc[2][4][4];
#pragma unroll
    for (int mt = 0; mt < 2; mt++)
#pragma unroll
        for (int nt = 0; nt < 4; nt++)
#pragma unroll
            for (int e = 0; e < 4; e++) acc[mt][nt][e] = 0.f;

    prefetch(0);
    for (int ck = 0; ck < 4; ck++) {
        if (ck + 1 < 4) { prefetch(ck + 1); CP_WAIT1(); } else CP_WAIT0();
        __syncthreads();
        uint32_t base = sb + (ck & 1) * CONV_STG;
#pragma unroll
        for (int ks = 0; ks < 4; ks++) {
            const int k0 = ks * 16;
            uint32_t ah[2][4], al[2][4], bh[2][4], bl[2][4];
            ldsm4t(ah[0], at_addr(base, wm * 32,      k0, lane, 136));
            ldsm4t(ah[1], at_addr(base, wm * 32 + 16, k0, lane, 136));
            ldsm4(bh[0], b_addrP(base + 34816, wn * 32,      k0, lane, 72));
            ldsm4(bh[1], b_addrP(base + 34816, wn * 32 + 16, k0, lane, 72));
#pragma unroll
            for (int g = 0; g < 2; g++)
#pragma unroll
                for (int mt = 0; mt < 2; mt++) {
                    mma16816(acc[mt][g*2],   ah[mt], bh[g][0], bh[g][1]);
                    mma16816(acc[mt][g*2+1], ah[mt], bh[g][2], bh[g][3]);
                }
            ldsm4(bl[0], b_addrP(base + 44032, wn * 32,      k0, lane, 72));
            ldsm4(bl[1], b_addrP(base + 44032, wn * 32 + 16, k0, lane, 72));
#pragma unroll
            for (int g = 0; g < 2; g++)
#pragma unroll
                for (int mt = 0; mt < 2; mt++) {
                    mma16816(acc[mt][g*2],   ah[mt], bl[g][0], bl[g][1]);
                    mma16816(acc[mt][g*2+1], ah[mt], bl[g][2], bl[g][3]);
                }
            ldsm4t(al[0], at_addr(base + 17408, wm * 32,      k0, lane, 136));
            ldsm4t(al[1], at_addr(base + 17408, wm * 32 + 16, k0, lane, 136));
#pragma unroll
            for (int g = 0; g < 2; g++)
#pragma unroll
                for (int mt = 0; mt < 2; mt++) {
                    mma16816(acc[mt][g*2],   al[mt], bh[g][0], bh[g][1]);
                    mma16816(acc[mt][g*2+1], al[mt], bh[g][2], bh[g][3]);
                }
        }
        __syncthreads();
    }

#pragma unroll
    for (int mt = 0; mt < 2; mt++) {
        const int row = wm * 32 + mt * 16 + (lane >> 2);
#pragma unroll
        for (int nt = 0; nt < 4; nt++) {
            const int col = wn * 32 + nt * 8 + (lane & 3) * 2;
            sRes[row * 68 + col]       = acc[mt][nt][0];
            sRes[row * 68 + col + 1]   = acc[mt][nt][1];
            sRes[(row+8) * 68 + col]   = acc[mt][nt][2];
            sRes[(row+8) * 68 + col+1] = acc[mt][nt][3];
        }
    }
    __syncthreads();

    if (oc0 < 256) {
        // g: pool 2x2 -> V [b][oc][m]
        for (int t = tid; t < 32 * 64; t += 256) {
            int pw = t >> 6, o = t & 63, oc = oc0 + o;
            float v = fmaxf(fmaxf(sRes[(2*pw)*68 + o], sRes[(2*pw+1)*68 + o]),
                            fmaxf(sRes[(64+2*pw)*68 + o], sRes[(65+2*pw)*68 + o]))
                      + bc[oc];
            __nv_bfloat16 h, l; split_bf16(v, h, l);
            size_t oidx = ((size_t)b * C_ + oc) * PHW_ + pxt * 32 + pw;
            Vh[oidx] = h; Vl[oidx] = l;
        }
    } else if (oc0 == 256) {
        // theta: no pool -> Q [n][64]
        for (int t = tid; t < 128 * 64; t += 256) {
            int p = t >> 6, o = t & 63;
            float v = sRes[p * 68 + o] + bc[256 + o];
            __nv_bfloat16 h, l; split_bf16(v, h, l);
            size_t oidx = ((size_t)b * HW_ + pxt * 128 + p) * 64 + o;
            Qh[oidx] = h; Ql[oidx] = l;
        }
    } else {
        // phi: pool -> K [m][64]
        for (int t = tid; t < 32 * 64; t += 256) {
            int pw = t >> 6, o = t & 63;
            float v = fmaxf(fmaxf(sRes[(2*pw)*68 + o], sRes[(2*pw+1)*68 + o]),
                            fmaxf(sRes[(64+2*pw)*68 + o], sRes[(65+2*pw)*68 + o]))
                      + bc[320 + o];
            __nv_bfloat16 h, l; split_bf16(v, h, l);
            size_t oidx = ((size_t)b * PHW_ + pxt * 32 + pw) * 64 + o;
            Kh[oidx] = h; Kl[oidx] = l;
        }
    }
}

// ======================================================================
// qk_mma: unchanged from proven R7/R8 version. block 256, 2 CTAs/SM.
// ======================================================================
static constexpr int QK_SMEM = 110592 + 1024;

__global__ __launch_bounds__(256, 2) void qk_mma_kernel(
    const __nv_bfloat16* __restrict__ Qh, const __nv_bfloat16* __restrict__ Ql,
    const __nv_bfloat16* __restrict__ Kh, const __nv_bfloat16* __restrict__ Kl,
    __nv_bfloat16* __restrict__ Ph, __nv_bfloat16* __restrict__ Pl,
    float* __restrict__ rinv)
{
    extern __shared__ char smem[];
    const uint32_t sb = smem_to_u32(smem);
    __nv_bfloat16* sQ = (__nv_bfloat16*)smem;
    float* rs = (float*)(smem + 110592);
    const int tid = threadIdx.x, lane = tid & 31, wid = tid >> 5;
    const int wm = wid & 3, wn = wid >> 2;
    const int b = blockIdx.y, n0 = blockIdx.x * 128;

    auto prefetch = [&](int c) {
        uint32_t base = sb + 36864 + (c & 1) * 36864;
        const __nv_bfloat16* gkh = Kh + ((size_t)b * PHW_ + c * 128) * 64;
        const __nv_bfloat16* gkl = Kl + ((size_t)b * PHW_ + c * 128) * 64;
        for (int idx = tid; idx < 1024; idx += 256) {
            int r = idx >> 3, u = idx & 7;
            uint32_t so = (uint32_t)((r * 72 + u * 8) * 2);
            cp16(base + so,         gkh + r * 64 + u * 8);
            cp16(base + 18432 + so, gkl + r * 64 + u * 8);
        }
        CP_COMMIT();
    };

    prefetch(0);
    {
        const __nv_bfloat16* gqh = Qh + ((size_t)b * HW_ + n0) * 64;
        const __nv_bfloat16* gql = Ql + ((size_t)b * HW_ + n0) * 64;
        for (int idx = tid; idx < 1024; idx += 256) {
            int r = idx >> 3, u = idx & 7;
            *(uint4*)(sQ + r * 72 + u * 8)        = *(const uint4*)(gqh + r * 64 + u * 8);
            *(uint4*)(sQ + 9216 + r * 72 + u * 8) = *(const uint4*)(gql + r * 64 + u * 8);
        }
    }

    float rsum[2][2] = {{0.f, 0.f}, {0.f, 0.f}};

    for (int ck = 0; ck < 8; ck++) {
        const int m0 = ck * 128;
        if (ck + 1 < 8) { prefetch(ck + 1); CP_WAIT1(); } else CP_WAIT0();
        __syncthreads();
        uint32_t kb = sb + 36864 + (ck & 1) * 36864;

        float acc[2][8][4];
#pragma unroll
        for (int mt = 0; mt < 2; mt++)
#pragma unroll
            for (int nt = 0; nt < 8; nt++)
#pragma unroll
                for (int e = 0; e < 4; e++) acc[mt][nt][e] = 0.f;

#pragma unroll
        for (int ks = 0; ks < 4; ks++) {
            const int k0 = ks * 16;
            uint32_t ah[2][4], al[2][4];
            ldsm4(ah[0], a_addrP(sb,         wm * 32,      k0, lane, 72));
            ldsm4(ah[1], a_addrP(sb,         wm * 32 + 16, k0, lane, 72));
            ldsm4(al[0], a_addrP(sb + 18432, wm * 32,      k0, lane, 72));
            ldsm4(al[1], a_addrP(sb + 18432, wm * 32 + 16, k0, lane, 72));
#pragma unroll
            for (int g = 0; g < 4; g++) {
                uint32_t bh[4], bl[4];
                ldsm4(bh, b_addrP(kb,         wn * 64 + g * 16, k0, lane, 72));
                ldsm4(bl, b_addrP(kb + 18432, wn * 64 + g * 16, k0, lane, 72));
#pragma unroll
                for (int mt = 0; mt < 2; mt++) {
                    mma16816(acc[mt][g*2],   ah[mt], bh[0], bh[1]);
                    mma16816(acc[mt][g*2+1], ah[mt], bh[2], bh[3]);
                }
#pragma unroll
                for (int mt = 0; mt < 2; mt++) {
                    mma16816(acc[mt][g*2],   ah[mt], bl[0], bl[1]);
                    mma16816(acc[mt][g*2+1], ah[mt], bl[2], bl[3]);
                }
#pragma unroll
                for (int mt = 0; mt < 2; mt++) {
                    mma16816(acc[mt][g*2],   al[mt], bh[0], bh[1]);
                    mma16816(acc[mt][g*2+1], al[mt], bh[2], bh[3]);
                }
            }
        }

#pragma unroll
        for (int mt = 0; mt < 2; mt++) {
            const int row = n0 + wm * 32 + mt * 16 + (lane >> 2);
#pragma unroll
            for (int nt = 0; nt < 8; nt++) {
                float e0 = __expf(acc[mt][nt][0]);
                float e1 = __expf(acc[mt][nt][1]);
                float e2 = __expf(acc[mt][nt][2]);
                float e3 = __expf(acc[mt][nt][3]);
                rsum[mt][0] += e0 + e1;
                rsum[mt][1] += e2 + e3;
                const int col = m0 + wn * 64 + nt * 8 + (lane & 3) * 2;
                uint32_t hh, ll;
                split2(e0, e1, hh, ll);
                *(uint32_t*)&Ph[((size_t)b * HW_ + row) * PHW_ + col] = hh;
                *(uint32_t*)&Pl[((size_t)b * HW_ + row) * PHW_ + col] = ll;
                split2(e2, e3, hh, ll);
                *(uint32_t*)&Ph[((size_t)b * HW_ + row + 8) * PHW_ + col] = hh;
                *(uint32_t*)&Pl[((size_t)b * HW_ + row + 8) * PHW_ + col] = ll;
            }
        }
        __syncthreads();
    }

#pragma unroll
    for (int mt = 0; mt < 2; mt++)
#pragma unroll
        for (int hh = 0; hh < 2; hh++) {
            float s = rsum[mt][hh];
            s += __shfl_xor_sync(0xffffffffu, s, 1);
            s += __shfl_xor_sync(0xffffffffu, s, 2);
            if ((lane & 3) == 0)
                rs[wn * 128 + wm * 32 + mt * 16 + hh * 8 + (lane >> 2)] = s;
        }
    __syncthreads();
    if (tid < 128)
        rinv[(size_t)b * HW_ + n0 + tid] = 1.f / (rs[tid] + rs[128 + tid]);
}

// ======================================================================
// pv_mma: CTA = 64 rows x 256 cols, grid (64, 8), block 256 (2m x 4n),
// 2 CTAs/SM.  k-chunk 32 (pitch 40).  stage s @ s*51200:
// Ph[64][40] Pl(+5120) Vh[256][40](+10240) Vl(+30720).
// ======================================================================
static constexpr int PV_STG  = 51200;
static constexpr int PV_SMEM = 2 * PV_STG;

__global__ __launch_bounds__(256, 2) void pv_mma_kernel(
    const __nv_bfloat16* __restrict__ Ph, const __nv_bfloat16* __restrict__ Pl,
    const __nv_bfloat16* __restrict__ Vh, const __nv_bfloat16* __restrict__ Vl,
    const float* __restrict__ rinv,
    __nv_bfloat16* __restrict__ Yh, __nv_bfloat16* __restrict__ Yl)
{
    extern __shared__ char smem[];
    const uint32_t sb = smem_to_u32(smem);
    const int tid = threadIdx.x, lane = tid & 31, wid = tid >> 5;
    const int wm = wid & 1, wn = wid >> 1;       // 2m x 4n warps
    const int b = blockIdx.y, n0 = blockIdx.x * 64;

    auto prefetch = [&](int c) {
        uint32_t base = sb + (c & 1) * PV_STG;
        const __nv_bfloat16* gph = Ph + ((size_t)b * HW_ + n0) * PHW_ + c * 32;
        const __nv_bfloat16* gpl = Pl + ((size_t)b * HW_ + n0) * PHW_ + c * 32;
        {   // 64 rows x 32 k -> exactly 256 cp16 per plane
            int r = tid >> 2, u = tid & 3;
            uint32_t so = (uint32_t)((r * 40 + u * 8) * 2);
            cp16(base + so,        gph + (size_t)r * PHW_ + u * 8);
            cp16(base + 5120 + so, gpl + (size_t)r * PHW_ + u * 8);
        }
        const __nv_bfloat16* gvh = Vh + (size_t)b * C_ * PHW_ + c * 32;
        const __nv_bfloat16* gvl = Vl + (size_t)b * C_ * PHW_ + c * 32;
        for (int idx = tid; idx < 1024; idx += 256) {
            int r = idx >> 2, u = idx & 3;
            uint32_t so = (uint32_t)((r * 40 + u * 8) * 2);
            cp16(base + 10240 + so, gvh + (size_t)r * PHW_ + u * 8);
            cp16(base + 30720 + so, gvl + (size_t)r * PHW_ + u * 8);
        }
        CP_COMMIT();
    };

    float acc[2][8][4];
#pragma unroll
    for (int mt = 0; mt < 2; mt++)
#pragma unroll
        for (int nt = 0; nt < 8; nt++)
#pragma unroll
            for (int e = 0; e < 4; e++) acc[mt][nt][e] = 0.f;

    prefetch(0);
    for (int ck = 0; ck < 32; ck++) {
        if (ck + 1 < 32) { prefetch(ck + 1); CP_WAIT1(); } else CP_WAIT0();
        __syncthreads();
        uint32_t base = sb + (ck & 1) * PV_STG;
#pragma unroll
        for (int ks = 0; ks < 2; ks++) {
            const int k0 = ks * 16;
            uint32_t ah[2][4], al[2][4], bh[4][4], bt[4];
            ldsm4(ah[0], a_addrP(base, wm * 32,      k0, lane, 40));
            ldsm4(ah[1], a_addrP(base, wm * 32 + 16, k0, lane, 40));
#pragma unroll
            for (int g = 0; g < 4; g++)
                ldsm4(bh[g], b_addrP(base + 10240, wn * 64 + g * 16, k0, lane, 40));
            // pass 1: hi*hi
#pragma unroll
            for (int g = 0; g < 4; g++)
#pragma unroll
                for (int mt = 0; mt < 2; mt++) {
                    mma16816(acc[mt][g*2],   ah[mt], bh[g][0], bh[g][1]);
                    mma16816(acc[mt][g*2+1], ah[mt], bh[g][2], bh[g][3]);
                }
            // pass 2: lo*hi
            ldsm4(al[0], a_addrP(base + 5120, wm * 32,      k0, lane, 40));
            ldsm4(al[1], a_addrP(base + 5120, wm * 32 + 16, k0, lane, 40));
#pragma unroll
            for (int g = 0; g < 4; g++)
#pragma unroll
                for (int mt = 0; mt < 2; mt++) {
                    mma16816(acc[mt][g*2],   al[mt], bh[g][0], bh[g][1]);
                    mma16816(acc[mt][g*2+1], al[mt], bh[g][2], bh[g][3]);
                }
            // pass 3: hi*lo
#pragma unroll
            for (int g = 0; g < 4; g++) {
                ldsm4(bt, b_addrP(base + 30720, wn * 64 + g * 16, k0, lane, 40));
#pragma unroll
                for (int mt = 0; mt < 2; mt++) {
                    mma16816(acc[mt][g*2],   ah[mt], bt[0], bt[1]);
                    mma16816(acc[mt][g*2+1], ah[mt], bt[2], bt[3]);
                }
            }
        }
        __syncthreads();
    }

#pragma unroll
    for (int mt = 0; mt < 2; mt++) {
        const int r0 = n0 + wm * 32 + mt * 16 + (lane >> 2);
        const float i0 = rinv[(size_t)b * HW_ + r0];
        const float i1 = rinv[(size_t)b * HW_ + r0 + 8];
#pragma unroll
        for (int nt = 0; nt < 8; nt++) {
            const int col = wn * 64 + nt * 8 + (lane & 3) * 2;
            uint32_t hh, ll;
            split2(acc[mt][nt][0] * i0, acc[mt][nt][1] * i0, hh, ll);
            *(uint32_t*)&Yh[((size_t)b * HW_ + r0) * C_ + col] = hh;
            *(uint32_t*)&Yl[((size_t)b * HW_ + r0) * C_ + col] = ll;
            split2(acc[mt][nt][2] * i1, acc[mt][nt][3] * i1, hh, ll);
            *(uint32_t*)&Yh[((size_t)b * HW_ + r0 + 8) * C_ + col] = hh;
            *(uint32_t*)&Yl[((size_t)b * HW_ + r0 + 8) * C_ + col] = ll;
        }
    }
}

// ======================================================================
// final_mma: CTA = 128 px x 64 oc, grid (4, 32, 8), block 256 (4m x 2n),
// 2 CTAs/SM.  stage s @ s*55296: Ah[128][72] Al(+18432)
// Bh[64][72](+36864) Bl(+46080).  sRes [128][68] union at 0.
// ======================================================================
static constexpr int FIN_STG  = 55296;
static constexpr int FIN_SMEM = 2 * FIN_STG;

__global__ __launch_bounds__(256, 2) void final_mma_kernel(
    const __nv_bfloat16* __restrict__ Yh, const __nv_bfloat16* __restrict__ Yl,
    const __nv_bfloat16* __restrict__ Wh, const __nv_bfloat16* __restrict__ Wl,
    const float* __restrict__ Wb,
    const float* __restrict__ gamma, const float* __restrict__ beta,
    const float* __restrict__ mean, const float* __restrict__ var,
    const float* __restrict__ x, float* __restrict__ out)
{
    extern __shared__ char smem[];
    const uint32_t sb = smem_to_u32(smem);
    float* sRes = (float*)smem;
    const int tid = threadIdx.x, lane = tid & 31, wid = tid >> 5;
    const int wm = wid & 3, wn = wid >> 2;
    const int b = blockIdx.z, pxt = blockIdx.y, oc0 = blockIdx.x * 64;

    auto prefetch = [&](int c) {
        uint32_t base = sb + (c & 1) * FIN_STG;
        const __nv_bfloat16* gah = Yh + ((size_t)b * HW_ + pxt * 128) * C_ + c * 64;
        const __nv_bfloat16* gal = Yl + ((size_t)b * HW_ + pxt * 128) * C_ + c * 64;
        for (int idx = tid; idx < 1024; idx += 256) {
            int r = idx >> 3, u = idx & 7;
            uint32_t so = (uint32_t)((r * 72 + u * 8) * 2);
            cp16(base + so,         gah + (size_t)r * C_ + u * 8);
            cp16(base + 18432 + so, gal + (size_t)r * C_ + u * 8);
        }
        const __nv_bfloat16* gbh = Wh + (size_t)oc0 * 256 + c * 64;
        const __nv_bfloat16* gbl = Wl + (size_t)oc0 * 256 + c * 64;
        for (int idx = tid; idx < 512; idx += 256) {    // 64 oc x 64 k
            int r = idx >> 3, u = idx & 7;
            uint32_t so = (uint32_t)((r * 72 + u * 8) * 2);
            cp16(base + 36864 + so, gbh + (size_t)r * 256 + u * 8);
            cp16(base + 46080 + so, gbl + (size_t)r * 256 + u * 8);
        }
        CP_COMMIT();
    };

    float acc[2][4][4];
#pragma unroll
    for (int mt = 0; mt < 2; mt++)
#pragma unroll
        for (int nt = 0; nt < 4; nt++)
#pragma unroll
            for (int e = 0; e < 4; e++) acc[mt][nt][e] = 0.f;

    prefetch(0);
    for (int ck = 0; ck < 4; ck++) {
        if (ck + 1 < 4) { prefetch(ck + 1); CP_WAIT1(); } else CP_WAIT0();
        __syncthreads();
        uint32_t base = sb + (ck & 1) * FIN_STG;
#pragma unroll
        for (int ks = 0; ks < 4; ks++) {
            const int k0 = ks * 16;
            uint32_t ah[2][4], al[2][4], bh[2][4], bl[2][4];
            ldsm4(ah[0], a_addrP(base, wm * 32,      k0, lane, 72));
            ldsm4(ah[1], a_addrP(base, wm * 32 + 16, k0, lane, 72));
            ldsm4(bh[0], b_addrP(base + 36864, wn * 32,      k0, lane, 72));
            ldsm4(bh[1], b_addrP(base + 36864, wn * 32 + 16, k0, lane, 72));
#pragma unroll
            for (int g = 0; g < 2; g++)
#pragma unroll
                for (int mt = 0; mt < 2; mt++) {
                    mma16816(acc[mt][g*2],   ah[mt], bh[g][0], bh[g][1]);
                    mma16816(acc[mt][g*2+1], ah[mt], bh[g][2], bh[g][3]);
                }
            ldsm4(bl[0], b_addrP(base + 46080, wn * 32,      k0, lane, 72));
            ldsm4(bl[1], b_addrP(base + 46080, wn * 32 + 16, k0, lane, 72));
#pragma unroll
            for (int g = 0; g < 2; g++)
#pragma unroll
                for (int mt = 0; mt < 2; mt++) {
                    mma16816(acc[mt][g*2],   ah[mt], bl[g][0], bl[g][1]);
                    mma16816(acc[mt][g*2+1], ah[mt], bl[g][2], bl[g][3]);
                }
            ldsm4(al[0], a_addrP(base + 18432, wm * 32,      k0, lane, 72));
            ldsm4(al[1], a_addrP(base + 18432, wm * 32 + 16, k0, lane, 72));
#pragma unroll
            for (int g = 0; g < 2; g++)
#pragma unroll
                for (int mt = 0; mt < 2; mt++) {
                    mma16816(acc[mt][g*2],   al[mt], bh[g][0], bh[g][1]);
                    mma16816(acc[mt][g*2+1], al[mt], bh[g][2], bh[g][3]);
                }
        }
        __syncthreads();
    }

#pragma unroll
    for (int mt = 0; mt < 2; mt++) {
        const int row = wm * 32 + mt * 16 + (lane >> 2);
#pragma unroll
        for (int nt = 0; nt < 4; nt++) {
            const int col = wn * 32 + nt * 8 + (lane & 3) * 2;
            sRes[row * 68 + col]       = acc[mt][nt][0];
            sRes[row * 68 + col + 1]   = acc[mt][nt][1];
            sRes[(row+8) * 68 + col]   = acc[mt][nt][2];
            sRes[(row+8) * 68 + col+1] = acc[mt][nt][3];
        }
    }
    __syncthreads();

    for (int t = tid; t < 128 * 64; t += 256) {
        int o = t >> 7, p = t & 127;
        int oc = oc0 + o;
        float scale = gamma[oc] * rsqrtf(var[oc] + EPS_);
        size_t gidx = ((size_t)b * C_ + oc) * HW_ + pxt * 128 + p;
        out[gidx] = (sRes[p * 68 + o] + Wb[oc] - mean[oc]) * scale + beta[oc] + x[gidx];
    }
}

// ======================================================================
extern "C" void kernel_launch(void* const* d_in, const int* in_sizes, int n_in,
                              void* d_out, int out_size)
{
    const float* x       = (const float*)d_in[0];
    const float* g_w     = (const float*)d_in[1];
    const float* g_b     = (const float*)d_in[2];
    const float* theta_w = (const float*)d_in[3];
    const float* theta_b = (const float*)d_in[4];
    const float* phi_w   = (const float*)d_in[5];
    const float* phi_b   = (const float*)d_in[6];
    const float* W_w     = (const float*)d_in[7];
    const float* W_b     = (const float*)d_in[8];
    const float* bn_g    = (const float*)d_in[9];
    const float* bn_b    = (const float*)d_in[10];
    const float* bn_m    = (const float*)d_in[11];
    const float* bn_v    = (const float*)d_in[12];
    float* out = (float*)d_out;

    __nv_bfloat16 *xh, *xl, *Wch, *Wcl, *Wfh, *Wfl;
    __nv_bfloat16 *Qh, *Ql, *Kh, *Kl, *Vh, *Vl, *Ph, *Pl, *Yh, *Yl;
    float *rv, *bc;
    cudaGetSymbolAddress((void**)&xh,  d_xh);
    cudaGetSymbolAddress((void**)&xl,  d_xl);
    cudaGetSymbolAddress((void**)&Wch, d_Wch);
    cudaGetSymbolAddress((void**)&Wcl, d_Wcl);
    cudaGetSymbolAddress((void**)&bc,  d_bc);
    cudaGetSymbolAddress((void**)&Wfh, d_Wfh);
    cudaGetSymbolAddress((void**)&Wfl, d_Wfl);
    cudaGetSymbolAddress((void**)&Qh,  d_Qh);
    cudaGetSymbolAddress((void**)&Ql,  d_Ql);
    cudaGetSymbolAddress((void**)&Kh,  d_Kh);
    cudaGetSymbolAddress((void**)&Kl,  d_Kl);
    cudaGetSymbolAddress((void**)&Vh,  d_Vh);
    cudaGetSymbolAddress((void**)&Vl,  d_Vl);
    cudaGetSymbolAddress((void**)&Ph,  d_Ph);
    cudaGetSymbolAddress((void**)&Pl,  d_Pl);
    cudaGetSymbolAddress((void**)&rv,  d_rinv);
    cudaGetSymbolAddress((void**)&Yh,  d_Yh);
    cudaGetSymbolAddress((void**)&Yl,  d_Yl);

    cudaFuncSetAttribute(conv_mma_kernel,  cudaFuncAttributeMaxDynamicSharedMemorySize, CONV_SMEM);
    cudaFuncSetAttribute(qk_mma_kernel,    cudaFuncAttributeMaxDynamicSharedMemorySize, QK_SMEM);
    cudaFuncSetAttribute(pv_mma_kernel,    cudaFuncAttributeMaxDynamicSharedMemorySize, PV_SMEM);
    cudaFuncSetAttribute(final_mma_kernel, cudaFuncAttributeMaxDynamicSharedMemorySize, FIN_SMEM);

    xsplit_kernel<<<BB * C_ * HW_ / 1024, 256>>>(x, xh, xl);
    wpack_conv_kernel<<<384, 256>>>(g_w, g_b, theta_w, theta_b, phi_w, phi_b, Wch, Wcl, bc);
    wpack_final_kernel<<<256, 256>>>(W_w, Wfh, Wfl);
    conv_mma_kernel<<<dim3(6, 32, BB), 256, CONV_SMEM>>>(xh, xl, Wch, Wcl, bc,
                                                         Vh, Vl, Qh, Ql, Kh, Kl);
    qk_mma_kernel<<<dim3(32, BB), 256, QK_SMEM>>>(Qh, Ql, Kh, Kl, Ph, Pl, rv);
    pv_mma_kernel<<<dim3(64, BB), 256, PV_SMEM>>>(Ph, Pl, Vh, Vl, rv, Yh, Yl);
    final_mma_kernel<<<dim3(4, 32, BB), 256, FIN_SMEM>>>(Yh, Yl, Wfh, Wfl, W_b,
                                                         bn_g, bn_b, bn_m, bn_v, x, out);
}

// round 12
// speedup vs baseline: 1.6847x; 1.2333x over previous
#include <cuda_runtime.h>
#include <cuda_bf16.h>
#include <cstdint>

#define BB 8
#define C_ 256
#define HW_ 4096
#define PHW_ 1024
#define EPS_ 1e-5f

// ---------------- helpers ----------------
__device__ __forceinline__ uint32_t smem_to_u32(const void* p) {
    uint32_t a;
    asm("{ .reg .u64 t; cvta.to.shared.u64 t, %1; cvt.u32.u64 %0, t; }" : "=r"(a) : "l"(p));
    return a;
}
__device__ __forceinline__ void ldsm4(uint32_t* r, uint32_t addr) {
    asm volatile("ldmatrix.sync.aligned.m8n8.x4.shared.b16 {%0,%1,%2,%3}, [%4];"
        : "=r"(r[0]), "=r"(r[1]), "=r"(r[2]), "=r"(r[3]) : "r"(addr));
}
__device__ __forceinline__ void ldsm4t(uint32_t* r, uint32_t addr) {
    asm volatile("ldmatrix.sync.aligned.m8n8.x4.trans.shared.b16 {%0,%1,%2,%3}, [%4];"
        : "=r"(r[0]), "=r"(r[1]), "=r"(r[2]), "=r"(r[3]) : "r"(addr));
}
__device__ __forceinline__ void mma16816(float* d, const uint32_t* a, uint32_t b0, uint32_t b1) {
    asm volatile("mma.sync.aligned.m16n8k16.row.col.f32.bf16.bf16.f32 "
        "{%0,%1,%2,%3}, {%4,%5,%6,%7}, {%8,%9}, {%0,%1,%2,%3};"
        : "+f"(d[0]), "+f"(d[1]), "+f"(d[2]), "+f"(d[3])
        : "r"(a[0]), "r"(a[1]), "r"(a[2]), "r"(a[3]), "r"(b0), "r"(b1));
}
// tf32 MMA m16n8k8 (sm_80+ ISA, fp32 range, 2^-11 precision)
__device__ __forceinline__ void mma1688t(float* d, const uint32_t* a, uint32_t b0, uint32_t b1) {
    asm volatile("mma.sync.aligned.m16n8k8.row.col.f32.tf32.tf32.f32 "
        "{%0,%1,%2,%3}, {%4,%5,%6,%7}, {%8,%9}, {%0,%1,%2,%3};"
        : "+f"(d[0]), "+f"(d[1]), "+f"(d[2]), "+f"(d[3])
        : "r"(a[0]), "r"(a[1]), "r"(a[2]), "r"(a[3]), "r"(b0), "r"(b1));
}
__device__ __forceinline__ uint32_t lds32(uint32_t addr) {
    uint32_t v;
    asm volatile("ld.shared.b32 %0, [%1];" : "=r"(v) : "r"(addr));
    return v;
}
__device__ __forceinline__ uint32_t tf32r(float v) {
    uint32_t u;
    asm("cvt.rna.tf32.f32 %0, %1;" : "=r"(u) : "f"(v));
    return u;
}
__device__ __forceinline__ void cp16(uint32_t s, const void* g) {
    asm volatile("cp.async.cg.shared.global [%0], [%1], 16;" :: "r"(s), "l"(g));
}
#define CP_COMMIT() asm volatile("cp.async.commit_group;" ::: "memory")
#define CP_WAIT0()  asm volatile("cp.async.wait_group 0;" ::: "memory")
#define CP_WAIT1()  asm volatile("cp.async.wait_group 1;" ::: "memory")

__device__ __forceinline__ void split_bf16(float v, __nv_bfloat16& h, __nv_bfloat16& l) {
    h = __float2bfloat16(v);
    l = __float2bfloat16(v - __bfloat162float(h));
}
__device__ __forceinline__ void split2(float a, float b, uint32_t& hh, uint32_t& ll) {
    __nv_bfloat16 ha, la, hb, lb;
    split_bf16(a, ha, la); split_bf16(b, hb, lb);
    hh = (uint32_t)__bfloat16_as_ushort(ha) | ((uint32_t)__bfloat16_as_ushort(hb) << 16);
    ll = (uint32_t)__bfloat16_as_ushort(la) | ((uint32_t)__bfloat16_as_ushort(lb) << 16);
}

// A-fragment (m16k16) from [m][k] row-major smem, pitch P elems
__device__ __forceinline__ uint32_t a_addrP(uint32_t base, int row0, int k0, int lane, int P) {
    int r = row0 + (lane & 15), c = k0 + ((lane >> 4) << 3);
    return base + (uint32_t)((r * P + c) * 2);
}
// A-fragment (m16k16) from [k][m] storage via trans-ldmatrix, pitch P
__device__ __forceinline__ uint32_t at_addr(uint32_t base, int m0, int k0, int lane, int P) {
    int t = lane >> 3;
    int m = m0 + ((t & 1) << 3);
    int k = k0 + ((t >> 1) << 3) + (lane & 7);
    return base + (uint32_t)((k * P + m) * 2);
}
// B-fragment x4 (two n8k16 tiles) from [n][k] row-major smem, pitch P
__device__ __forceinline__ uint32_t b_addrP(uint32_t base, int n0, int k0, int lane, int P) {
    int r = n0 + (lane & 7) + ((lane >> 4) << 3), c = k0 + (((lane >> 3) & 1) << 3);
    return base + (uint32_t)((r * P + c) * 2);
}

// ---------------- scratch ----------------
__device__ __nv_bfloat16 d_xh[BB*C_*HW_], d_xl[BB*C_*HW_];
__device__ __nv_bfloat16 d_Wch[384*256],  d_Wcl[384*256];
__device__ float         d_bc[384];
__device__ __nv_bfloat16 d_Wfh[256*256],  d_Wfl[256*256];
__device__ __nv_bfloat16 d_Qh[BB*HW_*64],  d_Ql[BB*HW_*64];
__device__ __nv_bfloat16 d_Kh[BB*PHW_*64], d_Kl[BB*PHW_*64];
__device__ float         d_Vf[BB*C_*PHW_];                 // V fp32 (tf32-rounded)
__device__ float         d_Pf[(size_t)BB*HW_*PHW_];        // P fp32 (tf32-rounded)
__device__ float         d_rinv[BB*HW_];
__device__ __nv_bfloat16 d_Yh[BB*HW_*C_],  d_Yl[BB*HW_*C_];

// ======================================================================
// xsplit + weight packing
// ======================================================================
__global__ __launch_bounds__(256) void xsplit_kernel(
    const float* __restrict__ x, __nv_bfloat16* __restrict__ xh, __nv_bfloat16* __restrict__ xl)
{
    size_t i = ((size_t)blockIdx.x * 256 + threadIdx.x) * 4;
    float4 v = *(const float4*)(x + i);
    uint32_t h0, l0, h1, l1;
    split2(v.x, v.y, h0, l0);
    split2(v.z, v.w, h1, l1);
    *(uint2*)(xh + i) = make_uint2(h0, h1);
    *(uint2*)(xl + i) = make_uint2(l0, l1);
}

__global__ void wpack_conv_kernel(
    const float* __restrict__ g_w, const float* __restrict__ g_b,
    const float* __restrict__ th_w, const float* __restrict__ th_b,
    const float* __restrict__ ph_w, const float* __restrict__ ph_b,
    __nv_bfloat16* __restrict__ Wh, __nv_bfloat16* __restrict__ Wl, float* __restrict__ bc)
{
    int oc = blockIdx.x, k = threadIdx.x;
    float v;
    if (oc < 256)       v = g_w[oc * 256 + k];
    else if (oc < 320)  v = (k < 64) ? th_w[(oc - 256) * 64 + k] : 0.f;
    else                v = (k >= 64) ? ph_w[(oc - 320) * 192 + (k - 64)] : 0.f;
    __nv_bfloat16 h, l; split_bf16(v, h, l);
    Wh[oc * 256 + k] = h; Wl[oc * 256 + k] = l;
    if (k == 0)
        bc[oc] = (oc < 256) ? g_b[oc] : (oc < 320) ? th_b[oc - 256] : ph_b[oc - 320];
}

__global__ void wpack_final_kernel(const float* __restrict__ w,
    __nv_bfloat16* __restrict__ Wh, __nv_bfloat16* __restrict__ Wl)
{
    int i = blockIdx.x * 256 + threadIdx.x;
    __nv_bfloat16 h, l; split_bf16(w[i], h, l);
    Wh[i] = h; Wl[i] = l;
}

// ======================================================================
// conv_mma: CTA = 128 px x 64 oc, grid (6, 32, 8), block 256 (4m x 2n),
// 2 CTAs/SM.  stage s @ s*53248: Xh[64][136] Xl(+17408)
// Wh[64][72](+34816) Wl(+44032).  sRes [128][68] fp32 union at 0.
// ======================================================================
static constexpr int CONV_STG  = 53248;
static constexpr int CONV_SMEM = 2 * CONV_STG;

__global__ __launch_bounds__(256, 2) void conv_mma_kernel(
    const __nv_bfloat16* __restrict__ xh, const __nv_bfloat16* __restrict__ xl,
    const __nv_bfloat16* __restrict__ Wh, const __nv_bfloat16* __restrict__ Wl,
    const float* __restrict__ bc,
    float* __restrict__ Vf,
    __nv_bfloat16* __restrict__ Qh, __nv_bfloat16* __restrict__ Ql,
    __nv_bfloat16* __restrict__ Kh, __nv_bfloat16* __restrict__ Kl)
{
    extern __shared__ char smem[];
    const uint32_t sb = smem_to_u32(smem);
    float* sRes = (float*)smem;
    const int tid = threadIdx.x, lane = tid & 31, wid = tid >> 5;
    const int wm = wid & 3, wn = wid >> 2;
    const int b = blockIdx.z, pxt = blockIdx.y, oc0 = blockIdx.x * 64;

    auto prefetch = [&](int c) {
        uint32_t base = sb + (c & 1) * CONV_STG;
        const __nv_bfloat16* gxh = xh + ((size_t)b * C_ + c * 64) * HW_ + pxt * 128;
        const __nv_bfloat16* gxl = xl + ((size_t)b * C_ + c * 64) * HW_ + pxt * 128;
        for (int idx = tid; idx < 1024; idx += 256) {
            int r = idx >> 4, u = idx & 15;
            uint32_t so = (uint32_t)((r * 136 + u * 8) * 2);
            cp16(base + so,         gxh + (size_t)r * HW_ + u * 8);
            cp16(base + 17408 + so, gxl + (size_t)r * HW_ + u * 8);
        }
        const __nv_bfloat16* gwh = Wh + (size_t)oc0 * 256 + c * 64;
        const __nv_bfloat16* gwl = Wl + (size_t)oc0 * 256 + c * 64;
        for (int idx = tid; idx < 512; idx += 256) {
            int r = idx >> 3, u = idx & 7;
            uint32_t so = (uint32_t)((r * 72 + u * 8) * 2);
            cp16(base + 34816 + so, gwh + (size_t)r * 256 + u * 8);
            cp16(base + 44032 + so, gwl + (size_t)r * 256 + u * 8);
        }
        CP_COMMIT();
    };

    float acc[2][4][4];
#pragma unroll
    for (int mt = 0; mt < 2; mt++)
#pragma unroll
        for (int nt = 0; nt < 4; nt++)
#pragma unroll
            for (int e = 0; e < 4; e++) acc[mt][nt][e] = 0.f;

    prefetch(0);
    for (int ck = 0; ck < 4; ck++) {
        if (ck + 1 < 4) { prefetch(ck + 1); CP_WAIT1(); } else CP_WAIT0();
        __syncthreads();
        uint32_t base = sb + (ck & 1) * CONV_STG;
#pragma unroll
        for (int ks = 0; ks < 4; ks++) {
            const int k0 = ks * 16;
            uint32_t ah[2][4], al[2][4], bh[2][4], bl[2][4];
            ldsm4t(ah[0], at_addr(base, wm * 32,      k0, lane, 136));
            ldsm4t(ah[1], at_addr(base, wm * 32 + 16, k0, lane, 136));
            ldsm4(bh[0], b_addrP(base + 34816, wn * 32,      k0, lane, 72));
            ldsm4(bh[1], b_addrP(base + 34816, wn * 32 + 16, k0, lane, 72));
#pragma unroll
            for (int g = 0; g < 2; g++)
#pragma unroll
                for (int mt = 0; mt < 2; mt++) {
                    mma16816(acc[mt][g*2],   ah[mt], bh[g][0], bh[g][1]);
                    mma16816(acc[mt][g*2+1], ah[mt], bh[g][2], bh[g][3]);
                }
            ldsm4(bl[0], b_addrP(base + 44032, wn * 32,      k0, lane, 72));
            ldsm4(bl[1], b_addrP(base + 44032, wn * 32 + 16, k0, lane, 72));
#pragma unroll
            for (int g = 0; g < 2; g++)
#pragma unroll
                for (int mt = 0; mt < 2; mt++) {
                    mma16816(acc[mt][g*2],   ah[mt], bl[g][0], bl[g][1]);
                    mma16816(acc[mt][g*2+1], ah[mt], bl[g][2], bl[g][3]);
                }
            ldsm4t(al[0], at_addr(base + 17408, wm * 32,      k0, lane, 136));
            ldsm4t(al[1], at_addr(base + 17408, wm * 32 + 16, k0, lane, 136));
#pragma unroll
            for (int g = 0; g < 2; g++)
#pragma unroll
                for (int mt = 0; mt < 2; mt++) {
                    mma16816(acc[mt][g*2],   al[mt], bh[g][0], bh[g][1]);
                    mma16816(acc[mt][g*2+1], al[mt], bh[g][2], bh[g][3]);
                }
        }
        __syncthreads();
    }

#pragma unroll
    for (int mt = 0; mt < 2; mt++) {
        const int row = wm * 32 + mt * 16 + (lane >> 2);
#pragma unroll
        for (int nt = 0; nt < 4; nt++) {
            const int col = wn * 32 + nt * 8 + (lane & 3) * 2;
            sRes[row * 68 + col]       = acc[mt][nt][0];
            sRes[row * 68 + col + 1]   = acc[mt][nt][1];
            sRes[(row+8) * 68 + col]   = acc[mt][nt][2];
            sRes[(row+8) * 68 + col+1] = acc[mt][nt][3];
        }
    }
    __syncthreads();

    if (oc0 < 256) {
        // g: pool 2x2 -> V fp32 [b][oc][m] (tf32-rounded)
        for (int t = tid; t < 32 * 64; t += 256) {
            int pw = t >> 6, o = t & 63, oc = oc0 + o;
            float v = fmaxf(fmaxf(sRes[(2*pw)*68 + o], sRes[(2*pw+1)*68 + o]),
                            fmaxf(sRes[(64+2*pw)*68 + o], sRes[(65+2*pw)*68 + o]))
                      + bc[oc];
            size_t oidx = ((size_t)b * C_ + oc) * PHW_ + pxt * 32 + pw;
            Vf[oidx] = __uint_as_float(tf32r(v));
        }
    } else if (oc0 == 256) {
        // theta: no pool -> Q [n][64]
        for (int t = tid; t < 128 * 64; t += 256) {
            int p = t >> 6, o = t & 63;
            float v = sRes[p * 68 + o] + bc[256 + o];
            __nv_bfloat16 h, l; split_bf16(v, h, l);
            size_t oidx = ((size_t)b * HW_ + pxt * 128 + p) * 64 + o;
            Qh[oidx] = h; Ql[oidx] = l;
        }
    } else {
        // phi: pool -> K [m][64]
        for (int t = tid; t < 32 * 64; t += 256) {
            int pw = t >> 6, o = t & 63;
            float v = fmaxf(fmaxf(sRes[(2*pw)*68 + o], sRes[(2*pw+1)*68 + o]),
                            fmaxf(sRes[(64+2*pw)*68 + o], sRes[(65+2*pw)*68 + o]))
                      + bc[320 + o];
            __nv_bfloat16 h, l; split_bf16(v, h, l);
            size_t oidx = ((size_t)b * PHW_ + pxt * 32 + pw) * 64 + o;
            Kh[oidx] = h; Kl[oidx] = l;
        }
    }
}

// ======================================================================
// qk_mma: split-bf16 3-pass (proven). P stored as tf32-rounded fp32.
// ======================================================================
static constexpr int QK_SMEM = 110592 + 1024;

__global__ __launch_bounds__(256, 2) void qk_mma_kernel(
    const __nv_bfloat16* __restrict__ Qh, const __nv_bfloat16* __restrict__ Ql,
    const __nv_bfloat16* __restrict__ Kh, const __nv_bfloat16* __restrict__ Kl,
    float* __restrict__ Pf, float* __restrict__ rinv)
{
    extern __shared__ char smem[];
    const uint32_t sb = smem_to_u32(smem);
    __nv_bfloat16* sQ = (__nv_bfloat16*)smem;
    float* rs = (float*)(smem + 110592);
    const int tid = threadIdx.x, lane = tid & 31, wid = tid >> 5;
    const int wm = wid & 3, wn = wid >> 2;
    const int b = blockIdx.y, n0 = blockIdx.x * 128;

    auto prefetch = [&](int c) {
        uint32_t base = sb + 36864 + (c & 1) * 36864;
        const __nv_bfloat16* gkh = Kh + ((size_t)b * PHW_ + c * 128) * 64;
        const __nv_bfloat16* gkl = Kl + ((size_t)b * PHW_ + c * 128) * 64;
        for (int idx = tid; idx < 1024; idx += 256) {
            int r = idx >> 3, u = idx & 7;
            uint32_t so = (uint32_t)((r * 72 + u * 8) * 2);
            cp16(base + so,         gkh + r * 64 + u * 8);
            cp16(base + 18432 + so, gkl + r * 64 + u * 8);
        }
        CP_COMMIT();
    };

    prefetch(0);
    {
        const __nv_bfloat16* gqh = Qh + ((size_t)b * HW_ + n0) * 64;
        const __nv_bfloat16* gql = Ql + ((size_t)b * HW_ + n0) * 64;
        for (int idx = tid; idx < 1024; idx += 256) {
            int r = idx >> 3, u = idx & 7;
            *(uint4*)(sQ + r * 72 + u * 8)        = *(const uint4*)(gqh + r * 64 + u * 8);
            *(uint4*)(sQ + 9216 + r * 72 + u * 8) = *(const uint4*)(gql + r * 64 + u * 8);
        }
    }

    float rsum[2][2] = {{0.f, 0.f}, {0.f, 0.f}};

    for (int ck = 0; ck < 8; ck++) {
        const int m0 = ck * 128;
        if (ck + 1 < 8) { prefetch(ck + 1); CP_WAIT1(); } else CP_WAIT0();
        __syncthreads();
        uint32_t kb = sb + 36864 + (ck & 1) * 36864;

        float acc[2][8][4];
#pragma unroll
        for (int mt = 0; mt < 2; mt++)
#pragma unroll
            for (int nt = 0; nt < 8; nt++)
#pragma unroll
                for (int e = 0; e < 4; e++) acc[mt][nt][e] = 0.f;

#pragma unroll
        for (int ks = 0; ks < 4; ks++) {
            const int k0 = ks * 16;
            uint32_t ah[2][4], al[2][4];
            ldsm4(ah[0], a_addrP(sb,         wm * 32,      k0, lane, 72));
            ldsm4(ah[1], a_addrP(sb,         wm * 32 + 16, k0, lane, 72));
            ldsm4(al[0], a_addrP(sb + 18432, wm * 32,      k0, lane, 72));
            ldsm4(al[1], a_addrP(sb + 18432, wm * 32 + 16, k0, lane, 72));
#pragma unroll
            for (int g = 0; g < 4; g++) {
                uint32_t bh[4], bl[4];
                ldsm4(bh, b_addrP(kb,         wn * 64 + g * 16, k0, lane, 72));
                ldsm4(bl, b_addrP(kb + 18432, wn * 64 + g * 16, k0, lane, 72));
#pragma unroll
                for (int mt = 0; mt < 2; mt++) {
                    mma16816(acc[mt][g*2],   ah[mt], bh[0], bh[1]);
                    mma16816(acc[mt][g*2+1], ah[mt], bh[2], bh[3]);
                }
#pragma unroll
                for (int mt = 0; mt < 2; mt++) {
                    mma16816(acc[mt][g*2],   ah[mt], bl[0], bl[1]);
                    mma16816(acc[mt][g*2+1], ah[mt], bl[2], bl[3]);
                }
#pragma unroll
                for (int mt = 0; mt < 2; mt++) {
                    mma16816(acc[mt][g*2],   al[mt], bh[0], bh[1]);
                    mma16816(acc[mt][g*2+1], al[mt], bh[2], bh[3]);
                }
            }
        }

#pragma unroll
        for (int mt = 0; mt < 2; mt++) {
            const int row = n0 + wm * 32 + mt * 16 + (lane >> 2);
#pragma unroll
            for (int nt = 0; nt < 8; nt++) {
                float e0 = __expf(acc[mt][nt][0]);
                float e1 = __expf(acc[mt][nt][1]);
                float e2 = __expf(acc[mt][nt][2]);
                float e3 = __expf(acc[mt][nt][3]);
                rsum[mt][0] += e0 + e1;
                rsum[mt][1] += e2 + e3;
                const int col = m0 + wn * 64 + nt * 8 + (lane & 3) * 2;
                *(float2*)&Pf[((size_t)b * HW_ + row) * PHW_ + col] =
                    make_float2(__uint_as_float(tf32r(e0)), __uint_as_float(tf32r(e1)));
                *(float2*)&Pf[((size_t)b * HW_ + row + 8) * PHW_ + col] =
                    make_float2(__uint_as_float(tf32r(e2)), __uint_as_float(tf32r(e3)));
            }
        }
        __syncthreads();
    }

#pragma unroll
    for (int mt = 0; mt < 2; mt++)
#pragma unroll
        for (int hh = 0; hh < 2; hh++) {
            float s = rsum[mt][hh];
            s += __shfl_xor_sync(0xffffffffu, s, 1);
            s += __shfl_xor_sync(0xffffffffu, s, 2);
            if ((lane & 3) == 0)
                rs[wn * 128 + wm * 32 + mt * 16 + hh * 8 + (lane >> 2)] = s;
        }
    __syncthreads();
    if (tid < 128)
        rinv[(size_t)b * HW_ + n0 + tid] = 1.f / (rs[tid] + rs[128 + tid]);
}

// ======================================================================
// pv_mma (tf32 single-pass): Y = P·V * rinv.
// CTA = 64 rows x 256 cols, grid (64, 8), block 256 (2m x 4n warps,
// warp tile 32x64), 2 CTAs/SM.  k-chunk 32, mma m16n8k8 (4 k-steps).
// stage s @ s*46080: P fp32 [64][36] (9216B), V fp32 [256][36] (+9216).
// Fragments via lds.32 (pitch 36 -> conflict-free).
// ======================================================================
static constexpr int PV_STG  = 46080;
static constexpr int PV_SMEM = 2 * PV_STG;

__global__ __launch_bounds__(256, 2) void pv_mma_kernel(
    const float* __restrict__ Pf, const float* __restrict__ Vf,
    const float* __restrict__ rinv,
    __nv_bfloat16* __restrict__ Yh, __nv_bfloat16* __restrict__ Yl)
{
    extern __shared__ char smem[];
    const uint32_t sb = smem_to_u32(smem);
    const int tid = threadIdx.x, lane = tid & 31, wid = tid >> 5;
    const int wm = wid & 1, wn = wid >> 1;       // 2m x 4n warps
    const int b = blockIdx.y, n0 = blockIdx.x * 64;

    auto prefetch = [&](int c) {
        uint32_t base = sb + (c & 1) * PV_STG;
        const float* gp = Pf + ((size_t)b * HW_ + n0) * PHW_ + c * 32;
        for (int idx = tid; idx < 512; idx += 256) {    // 64 rows x 8 cp16
            int r = idx >> 3, u = idx & 7;
            cp16(base + (uint32_t)(r * 144 + u * 16), gp + (size_t)r * PHW_ + u * 4);
        }
        const float* gv = Vf + (size_t)b * C_ * PHW_ + c * 32;
        for (int idx = tid; idx < 2048; idx += 256) {   // 256 rows x 8 cp16
            int r = idx >> 3, u = idx & 7;
            cp16(base + 9216 + (uint32_t)(r * 144 + u * 16), gv + (size_t)r * PHW_ + u * 4);
        }
        CP_COMMIT();
    };

    float acc[2][8][4];
#pragma unroll
    for (int mt = 0; mt < 2; mt++)
#pragma unroll
        for (int nt = 0; nt < 8; nt++)
#pragma unroll
            for (int e = 0; e < 4; e++) acc[mt][nt][e] = 0.f;

    prefetch(0);
    for (int ck = 0; ck < 32; ck++) {
        if (ck + 1 < 32) { prefetch(ck + 1); CP_WAIT1(); } else CP_WAIT0();
        __syncthreads();
        const uint32_t pb = sb + (ck & 1) * PV_STG;
        const uint32_t vb = pb + 9216;
#pragma unroll
        for (int ks = 0; ks < 4; ks++) {
            const int k0 = ks * 8;
            uint32_t a[2][4], bf[8][2];
#pragma unroll
            for (int mt = 0; mt < 2; mt++) {
                const int ra = wm * 32 + mt * 16 + (lane >> 2);
                const int ca = k0 + (lane & 3);
                a[mt][0] = lds32(pb + (uint32_t)((ra * 36 + ca) * 4));
                a[mt][1] = lds32(pb + (uint32_t)(((ra + 8) * 36 + ca) * 4));
                a[mt][2] = lds32(pb + (uint32_t)((ra * 36 + ca + 4) * 4));
                a[mt][3] = lds32(pb + (uint32_t)(((ra + 8) * 36 + ca + 4) * 4));
            }
#pragma unroll
            for (int g = 0; g < 8; g++) {
                const int nn = wn * 64 + g * 8 + (lane >> 2);
                const int kk = k0 + (lane & 3);
                bf[g][0] = lds32(vb + (uint32_t)((nn * 36 + kk) * 4));
                bf[g][1] = lds32(vb + (uint32_t)((nn * 36 + kk + 4) * 4));
            }
#pragma unroll
            for (int g = 0; g < 8; g++)
#pragma unroll
                for (int mt = 0; mt < 2; mt++)
                    mma1688t(acc[mt][g], a[mt], bf[g][0], bf[g][1]);
        }
        __syncthreads();
    }

#pragma unroll
    for (int mt = 0; mt < 2; mt++) {
        const int r0 = n0 + wm * 32 + mt * 16 + (lane >> 2);
        const float i0 = rinv[(size_t)b * HW_ + r0];
        const float i1 = rinv[(size_t)b * HW_ + r0 + 8];
#pragma unroll
        for (int nt = 0; nt < 8; nt++) {
            const int col = wn * 64 + nt * 8 + (lane & 3) * 2;
            uint32_t hh, ll;
            split2(acc[mt][nt][0] * i0, acc[mt][nt][1] * i0, hh, ll);
            *(uint32_t*)&Yh[((size_t)b * HW_ + r0) * C_ + col] = hh;
            *(uint32_t*)&Yl[((size_t)b * HW_ + r0) * C_ + col] = ll;
            split2(acc[mt][nt][2] * i1, acc[mt][nt][3] * i1, hh, ll);
            *(uint32_t*)&Yh[((size_t)b * HW_ + r0 + 8) * C_ + col] = hh;
            *(uint32_t*)&Yl[((size_t)b * HW_ + r0 + 8) * C_ + col] = ll;
        }
    }
}

// ======================================================================
// final_mma: CTA = 128 px x 64 oc, grid (4, 32, 8), block 256 (4m x 2n),
// 2 CTAs/SM.  stage s @ s*55296: Ah[128][72] Al(+18432)
// Bh[64][72](+36864) Bl(+46080).  sRes [128][68] union at 0.
// ======================================================================
static constexpr int FIN_STG  = 55296;
static constexpr int FIN_SMEM = 2 * FIN_STG;

__global__ __launch_bounds__(256, 2) void final_mma_kernel(
    const __nv_bfloat16* __restrict__ Yh, const __nv_bfloat16* __restrict__ Yl,
    const __nv_bfloat16* __restrict__ Wh, const __nv_bfloat16* __restrict__ Wl,
    const float* __restrict__ Wb,
    const float* __restrict__ gamma, const float* __restrict__ beta,
    const float* __restrict__ mean, const float* __restrict__ var,
    const float* __restrict__ x, float* __restrict__ out)
{
    extern __shared__ char smem[];
    const uint32_t sb = smem_to_u32(smem);
    float* sRes = (float*)smem;
    const int tid = threadIdx.x, lane = tid & 31, wid = tid >> 5;
    const int wm = wid & 3, wn = wid >> 2;
    const int b = blockIdx.z, pxt = blockIdx.y, oc0 = blockIdx.x * 64;

    auto prefetch = [&](int c) {
        uint32_t base = sb + (c & 1) * FIN_STG;
        const __nv_bfloat16* gah = Yh + ((size_t)b * HW_ + pxt * 128) * C_ + c * 64;
        const __nv_bfloat16* gal = Yl + ((size_t)b * HW_ + pxt * 128) * C_ + c * 64;
        for (int idx = tid; idx < 1024; idx += 256) {
            int r = idx >> 3, u = idx & 7;
            uint32_t so = (uint32_t)((r * 72 + u * 8) * 2);
            cp16(base + so,         gah + (size_t)r * C_ + u * 8);
            cp16(base + 18432 + so, gal + (size_t)r * C_ + u * 8);
        }
        const __nv_bfloat16* gbh = Wh + (size_t)oc0 * 256 + c * 64;
        const __nv_bfloat16* gbl = Wl + (size_t)oc0 * 256 + c * 64;
        for (int idx = tid; idx < 512; idx += 256) {
            int r = idx >> 3, u = idx & 7;
            uint32_t so = (uint32_t)((r * 72 + u * 8) * 2);
            cp16(base + 36864 + so, gbh + (size_t)r * 256 + u * 8);
            cp16(base + 46080 + so, gbl + (size_t)r * 256 + u * 8);
        }
        CP_COMMIT();
    };

    float acc[2][4][4];
#pragma unroll
    for (int mt = 0; mt < 2; mt++)
#pragma unroll
        for (int nt = 0; nt < 4; nt++)
#pragma unroll
            for (int e = 0; e < 4; e++) acc[mt][nt][e] = 0.f;

    prefetch(0);
    for (int ck = 0; ck < 4; ck++) {
        if (ck + 1 < 4) { prefetch(ck + 1); CP_WAIT1(); } else CP_WAIT0();
        __syncthreads();
        uint32_t base = sb + (ck & 1) * FIN_STG;
#pragma unroll
        for (int ks = 0; ks < 4; ks++) {
            const int k0 = ks * 16;
            uint32_t ah[2][4], al[2][4], bh[2][4], bl[2][4];
            ldsm4(ah[0], a_addrP(base, wm * 32,      k0, lane, 72));
            ldsm4(ah[1], a_addrP(base, wm * 32 + 16, k0, lane, 72));
            ldsm4(bh[0], b_addrP(base + 36864, wn * 32,      k0, lane, 72));
            ldsm4(bh[1], b_addrP(base + 36864, wn * 32 + 16, k0, lane, 72));
#pragma unroll
            for (int g = 0; g < 2; g++)
#pragma unroll
                for (int mt = 0; mt < 2; mt++) {
                    mma16816(acc[mt][g*2],   ah[mt], bh[g][0], bh[g][1]);
                    mma16816(acc[mt][g*2+1], ah[mt], bh[g][2], bh[g][3]);
                }
            ldsm4(bl[0], b_addrP(base + 46080, wn * 32,      k0, lane, 72));
            ldsm4(bl[1], b_addrP(base + 46080, wn * 32 + 16, k0, lane, 72));
#pragma unroll
            for (int g = 0; g < 2; g++)
#pragma unroll
                for (int mt = 0; mt < 2; mt++) {
                    mma16816(acc[mt][g*2],   ah[mt], bl[g][0], bl[g][1]);
                    mma16816(acc[mt][g*2+1], ah[mt], bl[g][2], bl[g][3]);
                }
            ldsm4(al[0], a_addrP(base + 18432, wm * 32,      k0, lane, 72));
            ldsm4(al[1], a_addrP(base + 18432, wm * 32 + 16, k0, lane, 72));
#pragma unroll
            for (int g = 0; g < 2; g++)
#pragma unroll
                for (int mt = 0; mt < 2; mt++) {
                    mma16816(acc[mt][g*2],   al[mt], bh[g][0], bh[g][1]);
                    mma16816(acc[mt][g*2+1], al[mt], bh[g][2], bh[g][3]);
                }
        }
        __syncthreads();
    }

#pragma unroll
    for (int mt = 0; mt < 2; mt++) {
        const int row = wm * 32 + mt * 16 + (lane >> 2);
#pragma unroll
        for (int nt = 0; nt < 4; nt++) {
            const int col = wn * 32 + nt * 8 + (lane & 3) * 2;
            sRes[row * 68 + col]       = acc[mt][nt][0];
            sRes[row * 68 + col + 1]   = acc[mt][nt][1];
            sRes[(row+8) * 68 + col]   = acc[mt][nt][2];
            sRes[(row+8) * 68 + col+1] = acc[mt][nt][3];
        }
    }
    __syncthreads();

    for (int t = tid; t < 128 * 64; t += 256) {
        int o = t >> 7, p = t & 127;
        int oc = oc0 + o;
        float scale = gamma[oc] * rsqrtf(var[oc] + EPS_);
        size_t gidx = ((size_t)b * C_ + oc) * HW_ + pxt * 128 + p;
        out[gidx] = (sRes[p * 68 + o] + Wb[oc] - mean[oc]) * scale + beta[oc] + x[gidx];
    }
}

// ======================================================================
extern "C" void kernel_launch(void* const* d_in, const int* in_sizes, int n_in,
                              void* d_out, int out_size)
{
    const float* x       = (const float*)d_in[0];
    const float* g_w     = (const float*)d_in[1];
    const float* g_b     = (const float*)d_in[2];
    const float* theta_w = (const float*)d_in[3];
    const float* theta_b = (const float*)d_in[4];
    const float* phi_w   = (const float*)d_in[5];
    const float* phi_b   = (const float*)d_in[6];
    const float* W_w     = (const float*)d_in[7];
    const float* W_b     = (const float*)d_in[8];
    const float* bn_g    = (const float*)d_in[9];
    const float* bn_b    = (const float*)d_in[10];
    const float* bn_m    = (const float*)d_in[11];
    const float* bn_v    = (const float*)d_in[12];
    float* out = (float*)d_out;

    __nv_bfloat16 *xh, *xl, *Wch, *Wcl, *Wfh, *Wfl;
    __nv_bfloat16 *Qh, *Ql, *Kh, *Kl, *Yh, *Yl;
    float *Vf, *Pf, *rv, *bc;
    cudaGetSymbolAddress((void**)&xh,  d_xh);
    cudaGetSymbolAddress((void**)&xl,  d_xl);
    cudaGetSymbolAddress((void**)&Wch, d_Wch);
    cudaGetSymbolAddress((void**)&Wcl, d_Wcl);
    cudaGetSymbolAddress((void**)&bc,  d_bc);
    cudaGetSymbolAddress((void**)&Wfh, d_Wfh);
    cudaGetSymbolAddress((void**)&Wfl, d_Wfl);
    cudaGetSymbolAddress((void**)&Qh,  d_Qh);
    cudaGetSymbolAddress((void**)&Ql,  d_Ql);
    cudaGetSymbolAddress((void**)&Kh,  d_Kh);
    cudaGetSymbolAddress((void**)&Kl,  d_Kl);
    cudaGetSymbolAddress((void**)&Vf,  d_Vf);
    cudaGetSymbolAddress((void**)&Pf,  d_Pf);
    cudaGetSymbolAddress((void**)&rv,  d_rinv);
    cudaGetSymbolAddress((void**)&Yh,  d_Yh);
    cudaGetSymbolAddress((void**)&Yl,  d_Yl);

    cudaFuncSetAttribute(conv_mma_kernel,  cudaFuncAttributeMaxDynamicSharedMemorySize, CONV_SMEM);
    cudaFuncSetAttribute(qk_mma_kernel,    cudaFuncAttributeMaxDynamicSharedMemorySize, QK_SMEM);
    cudaFuncSetAttribute(pv_mma_kernel,    cudaFuncAttributeMaxDynamicSharedMemorySize, PV_SMEM);
    cudaFuncSetAttribute(final_mma_kernel, cudaFuncAttributeMaxDynamicSharedMemorySize, FIN_SMEM);

    xsplit_kernel<<<BB * C_ * HW_ / 1024, 256>>>(x, xh, xl);
    wpack_conv_kernel<<<384, 256>>>(g_w, g_b, theta_w, theta_b, phi_w, phi_b, Wch, Wcl, bc);
    wpack_final_kernel<<<256, 256>>>(W_w, Wfh, Wfl);
    conv_mma_kernel<<<dim3(6, 32, BB), 256, CONV_SMEM>>>(xh, xl, Wch, Wcl, bc,
                                                         Vf, Qh, Ql, Kh, Kl);
    qk_mma_kernel<<<dim3(32, BB), 256, QK_SMEM>>>(Qh, Ql, Kh, Kl, Pf, rv);
    pv_mma_kernel<<<dim3(64, BB), 256, PV_SMEM>>>(Pf, Vf, rv, Yh, Yl);
    final_mma_kernel<<<dim3(4, 32, BB), 256, FIN_SMEM>>>(Yh, Yl, Wfh, Wfl, W_b,
                                                         bn_g, bn_b, bn_m, bn_v, x, out);
}

// round 13
// speedup vs baseline: 1.7925x; 1.0640x over previous
#include <cuda_runtime.h>
#include <cuda_bf16.h>
#include <cuda_fp16.h>
#include <cstdint>

#define BB 8
#define C_ 256
#define HW_ 4096
#define PHW_ 1024
#define EPS_ 1e-5f

// ---------------- helpers ----------------
__device__ __forceinline__ uint32_t smem_to_u32(const void* p) {
    uint32_t a;
    asm("{ .reg .u64 t; cvta.to.shared.u64 t, %1; cvt.u32.u64 %0, t; }" : "=r"(a) : "l"(p));
    return a;
}
__device__ __forceinline__ void ldsm4(uint32_t* r, uint32_t addr) {
    asm volatile("ldmatrix.sync.aligned.m8n8.x4.shared.b16 {%0,%1,%2,%3}, [%4];"
        : "=r"(r[0]), "=r"(r[1]), "=r"(r[2]), "=r"(r[3]) : "r"(addr));
}
__device__ __forceinline__ void ldsm4t(uint32_t* r, uint32_t addr) {
    asm volatile("ldmatrix.sync.aligned.m8n8.x4.trans.shared.b16 {%0,%1,%2,%3}, [%4];"
        : "=r"(r[0]), "=r"(r[1]), "=r"(r[2]), "=r"(r[3]) : "r"(addr));
}
__device__ __forceinline__ void mma16816(float* d, const uint32_t* a, uint32_t b0, uint32_t b1) {
    asm volatile("mma.sync.aligned.m16n8k16.row.col.f32.bf16.bf16.f32 "
        "{%0,%1,%2,%3}, {%4,%5,%6,%7}, {%8,%9}, {%0,%1,%2,%3};"
        : "+f"(d[0]), "+f"(d[1]), "+f"(d[2]), "+f"(d[3])
        : "r"(a[0]), "r"(a[1]), "r"(a[2]), "r"(a[3]), "r"(b0), "r"(b1));
}
__device__ __forceinline__ void mma16816h(float* d, const uint32_t* a, uint32_t b0, uint32_t b1) {
    asm volatile("mma.sync.aligned.m16n8k16.row.col.f32.f16.f16.f32 "
        "{%0,%1,%2,%3}, {%4,%5,%6,%7}, {%8,%9}, {%0,%1,%2,%3};"
        : "+f"(d[0]), "+f"(d[1]), "+f"(d[2]), "+f"(d[3])
        : "r"(a[0]), "r"(a[1]), "r"(a[2]), "r"(a[3]), "r"(b0), "r"(b1));
}
// tf32 MMA m16n8k8
__device__ __forceinline__ void mma1688t(float* d, const uint32_t* a, uint32_t b0, uint32_t b1) {
    asm volatile("mma.sync.aligned.m16n8k8.row.col.f32.tf32.tf32.f32 "
        "{%0,%1,%2,%3}, {%4,%5,%6,%7}, {%8,%9}, {%0,%1,%2,%3};"
        : "+f"(d[0]), "+f"(d[1]), "+f"(d[2]), "+f"(d[3])
        : "r"(a[0]), "r"(a[1]), "r"(a[2]), "r"(a[3]), "r"(b0), "r"(b1));
}
__device__ __forceinline__ uint32_t lds32(uint32_t addr) {
    uint32_t v;
    asm volatile("ld.shared.b32 %0, [%1];" : "=r"(v) : "r"(addr));
    return v;
}
__device__ __forceinline__ uint32_t tf32r(float v) {
    uint32_t u;
    asm("cvt.rna.tf32.f32 %0, %1;" : "=r"(u) : "f"(v));
    return u;
}
__device__ __forceinline__ void cp16(uint32_t s, const void* g) {
    asm volatile("cp.async.cg.shared.global [%0], [%1], 16;" :: "r"(s), "l"(g));
}
#define CP_COMMIT() asm volatile("cp.async.commit_group;" ::: "memory")
#define CP_WAIT0()  asm volatile("cp.async.wait_group 0;" ::: "memory")
#define CP_WAIT1()  asm volatile("cp.async.wait_group 1;" ::: "memory")

__device__ __forceinline__ void split_bf16(float v, __nv_bfloat16& h, __nv_bfloat16& l) {
    h = __float2bfloat16(v);
    l = __float2bfloat16(v - __bfloat162float(h));
}
__device__ __forceinline__ void split2(float a, float b, uint32_t& hh, uint32_t& ll) {
    __nv_bfloat16 ha, la, hb, lb;
    split_bf16(a, ha, la); split_bf16(b, hb, lb);
    hh = (uint32_t)__bfloat16_as_ushort(ha) | ((uint32_t)__bfloat16_as_ushort(hb) << 16);
    ll = (uint32_t)__bfloat16_as_ushort(la) | ((uint32_t)__bfloat16_as_ushort(lb) << 16);
}

// A-fragment (m16k16) from [m][k] row-major smem, pitch P elems (16-bit)
__device__ __forceinline__ uint32_t a_addrP(uint32_t base, int row0, int k0, int lane, int P) {
    int r = row0 + (lane & 15), c = k0 + ((lane >> 4) << 3);
    return base + (uint32_t)((r * P + c) * 2);
}
// A-fragment (m16k16) from [k][m] storage via trans-ldmatrix, pitch P (16-bit)
__device__ __forceinline__ uint32_t at_addr(uint32_t base, int m0, int k0, int lane, int P) {
    int t = lane >> 3;
    int m = m0 + ((t & 1) << 3);
    int k = k0 + ((t >> 1) << 3) + (lane & 7);
    return base + (uint32_t)((k * P + m) * 2);
}
// B-fragment x4 (two n8k16 tiles) from [n][k] row-major smem, pitch P (16-bit)
__device__ __forceinline__ uint32_t b_addrP(uint32_t base, int n0, int k0, int lane, int P) {
    int r = n0 + (lane & 7) + ((lane >> 4) << 3), c = k0 + (((lane >> 3) & 1) << 3);
    return base + (uint32_t)((r * P + c) * 2);
}

// ---------------- scratch ----------------
__device__ __nv_bfloat16 d_xh[BB*C_*HW_], d_xl[BB*C_*HW_];
__device__ float         d_xf[BB*C_*HW_];                  // x tf32-rounded
__device__ __nv_bfloat16 d_Wch[384*256],  d_Wcl[384*256];
__device__ float         d_Wgf[256*256];                   // g weights tf32 fp32
__device__ float         d_bc[384];
__device__ __half        d_Wff[256*256];                   // final weights fp16
__device__ __nv_bfloat16 d_Qh[BB*HW_*64],  d_Ql[BB*HW_*64];
__device__ __nv_bfloat16 d_Kh[BB*PHW_*64], d_Kl[BB*PHW_*64];
__device__ float         d_Vf[BB*C_*PHW_];                 // V tf32 fp32
__device__ float         d_Pf[(size_t)BB*HW_*PHW_];        // P tf32 fp32
__device__ float         d_rinv[BB*HW_];
__device__ __half        d_Yf[BB*HW_*C_];                  // Y fp16

// ======================================================================
// xsplit + weight packing
// ======================================================================
__global__ __launch_bounds__(256) void xsplit_kernel(
    const float* __restrict__ x, __nv_bfloat16* __restrict__ xh,
    __nv_bfloat16* __restrict__ xl, float* __restrict__ xf)
{
    size_t i = ((size_t)blockIdx.x * 256 + threadIdx.x) * 4;
    float4 v = *(const float4*)(x + i);
    uint32_t h0, l0, h1, l1;
    split2(v.x, v.y, h0, l0);
    split2(v.z, v.w, h1, l1);
    *(uint2*)(xh + i) = make_uint2(h0, h1);
    *(uint2*)(xl + i) = make_uint2(l0, l1);
    float4 t;
    t.x = __uint_as_float(tf32r(v.x)); t.y = __uint_as_float(tf32r(v.y));
    t.z = __uint_as_float(tf32r(v.z)); t.w = __uint_as_float(tf32r(v.w));
    *(float4*)(xf + i) = t;
}

__global__ void wpack_conv_kernel(
    const float* __restrict__ g_w, const float* __restrict__ g_b,
    const float* __restrict__ th_w, const float* __restrict__ th_b,
    const float* __restrict__ ph_w, const float* __restrict__ ph_b,
    __nv_bfloat16* __restrict__ Wh, __nv_bfloat16* __restrict__ Wl,
    float* __restrict__ Wgf, float* __restrict__ bc)
{
    int oc = blockIdx.x, k = threadIdx.x;
    float v;
    if (oc < 256)       v = g_w[oc * 256 + k];
    else if (oc < 320)  v = (k < 64) ? th_w[(oc - 256) * 64 + k] : 0.f;
    else                v = (k >= 64) ? ph_w[(oc - 320) * 192 + (k - 64)] : 0.f;
    __nv_bfloat16 h, l; split_bf16(v, h, l);
    Wh[oc * 256 + k] = h; Wl[oc * 256 + k] = l;
    if (oc < 256) Wgf[oc * 256 + k] = __uint_as_float(tf32r(v));
    if (k == 0)
        bc[oc] = (oc < 256) ? g_b[oc] : (oc < 320) ? th_b[oc - 256] : ph_b[oc - 320];
}

__global__ void wpack_final_kernel(const float* __restrict__ w, __half* __restrict__ Wf)
{
    int i = blockIdx.x * 256 + threadIdx.x;
    Wf[i] = __float2half_rn(w[i]);
}

// ======================================================================
// conv_g (tf32 1-pass): V = pool(g_conv(x)).  CTA = 128 px x 64 oc,
// grid (4, 32, 8), block 256 (4m x 2n), 2 CTAs/SM.
// stage s @ s*51200: X fp32 [64c][132] (33792B), W fp32 [64oc][68] (+33792).
// sRes [128][68] fp32 union at 0.
// ======================================================================
static constexpr int CG_STG  = 51200;
static constexpr int CG_SMEM = 2 * CG_STG;

__global__ __launch_bounds__(256, 2) void conv_g_kernel(
    const float* __restrict__ xf, const float* __restrict__ Wg,
    const float* __restrict__ bc, float* __restrict__ Vf)
{
    extern __shared__ char smem[];
    const uint32_t sb = smem_to_u32(smem);
    float* sRes = (float*)smem;
    const int tid = threadIdx.x, lane = tid & 31, wid = tid >> 5;
    const int wm = wid & 3, wn = wid >> 2;
    const int b = blockIdx.z, pxt = blockIdx.y, oc0 = blockIdx.x * 64;

    auto prefetch = [&](int c) {
        uint32_t base = sb + (c & 1) * CG_STG;
        const float* gx = xf + ((size_t)b * C_ + c * 64) * HW_ + pxt * 128;
        for (int idx = tid; idx < 2048; idx += 256) {   // 64 rows x 32 cp16
            int r = idx >> 5, u = idx & 31;
            cp16(base + (uint32_t)((r * 132 + u * 4) * 4), gx + (size_t)r * HW_ + u * 4);
        }
        const float* gw = Wg + (size_t)oc0 * 256 + c * 64;
        for (int idx = tid; idx < 1024; idx += 256) {   // 64 rows x 16 cp16
            int r = idx >> 4, u = idx & 15;
            cp16(base + 33792 + (uint32_t)((r * 68 + u * 4) * 4), gw + (size_t)r * 256 + u * 4);
        }
        CP_COMMIT();
    };

    float acc[2][4][4];
#pragma unroll
    for (int mt = 0; mt < 2; mt++)
#pragma unroll
        for (int nt = 0; nt < 4; nt++)
#pragma unroll
            for (int e = 0; e < 4; e++) acc[mt][nt][e] = 0.f;

    prefetch(0);
    for (int ck = 0; ck < 4; ck++) {
        if (ck + 1 < 4) { prefetch(ck + 1); CP_WAIT1(); } else CP_WAIT0();
        __syncthreads();
        const uint32_t xb = sb + (ck & 1) * CG_STG;
        const uint32_t wb = xb + 33792;
#pragma unroll
        for (int ks = 0; ks < 8; ks++) {
            const int k0 = ks * 8;
            uint32_t a[2][4], bf[4][2];
            const int ca = k0 + (lane & 3);
#pragma unroll
            for (int mt = 0; mt < 2; mt++) {
                const int ra = wm * 32 + mt * 16 + (lane >> 2);
                a[mt][0] = lds32(xb + (uint32_t)((ca * 132 + ra) * 4));
                a[mt][1] = lds32(xb + (uint32_t)((ca * 132 + ra + 8) * 4));
                a[mt][2] = lds32(xb + (uint32_t)(((ca + 4) * 132 + ra) * 4));
                a[mt][3] = lds32(xb + (uint32_t)(((ca + 4) * 132 + ra + 8) * 4));
            }
#pragma unroll
            for (int g = 0; g < 4; g++) {
                const int nn = wn * 32 + g * 8 + (lane >> 2);
                bf[g][0] = lds32(wb + (uint32_t)((nn * 68 + ca) * 4));
                bf[g][1] = lds32(wb + (uint32_t)((nn * 68 + ca + 4) * 4));
            }
#pragma unroll
            for (int g = 0; g < 4; g++)
#pragma unroll
                for (int mt = 0; mt < 2; mt++)
                    mma1688t(acc[mt][g], a[mt], bf[g][0], bf[g][1]);
        }
        __syncthreads();
    }

#pragma unroll
    for (int mt = 0; mt < 2; mt++) {
        const int row = wm * 32 + mt * 16 + (lane >> 2);
#pragma unroll
        for (int nt = 0; nt < 4; nt++) {
            const int col = wn * 32 + nt * 8 + (lane & 3) * 2;
            sRes[row * 68 + col]       = acc[mt][nt][0];
            sRes[row * 68 + col + 1]   = acc[mt][nt][1];
            sRes[(row+8) * 68 + col]   = acc[mt][nt][2];
            sRes[(row+8) * 68 + col+1] = acc[mt][nt][3];
        }
    }
    __syncthreads();

    for (int t = tid; t < 32 * 64; t += 256) {
        int pw = t >> 6, o = t & 63, oc = oc0 + o;
        float v = fmaxf(fmaxf(sRes[(2*pw)*68 + o], sRes[(2*pw+1)*68 + o]),
                        fmaxf(sRes[(64+2*pw)*68 + o], sRes[(65+2*pw)*68 + o]))
                  + bc[oc];
        size_t oidx = ((size_t)b * C_ + oc) * PHW_ + pxt * 32 + pw;
        Vf[oidx] = __uint_as_float(tf32r(v));
    }
}

// ======================================================================
// conv_qk (bf16 3-pass): theta + phi convs.  CTA = 128 px x 64 oc,
// grid (2, 32, 8), block 256, 2 CTAs/SM.  Same stage as old conv.
// ======================================================================
static constexpr int CONV_STG  = 53248;
static constexpr int CONV_SMEM = 2 * CONV_STG;

__global__ __launch_bounds__(256, 2) void conv_qk_kernel(
    const __nv_bfloat16* __restrict__ xh, const __nv_bfloat16* __restrict__ xl,
    const __nv_bfloat16* __restrict__ Wh, const __nv_bfloat16* __restrict__ Wl,
    const float* __restrict__ bc,
    __nv_bfloat16* __restrict__ Qh, __nv_bfloat16* __restrict__ Ql,
    __nv_bfloat16* __restrict__ Kh, __nv_bfloat16* __restrict__ Kl)
{
    extern __shared__ char smem[];
    const uint32_t sb = smem_to_u32(smem);
    float* sRes = (float*)smem;
    const int tid = threadIdx.x, lane = tid & 31, wid = tid >> 5;
    const int wm = wid & 3, wn = wid >> 2;
    const int b = blockIdx.z, pxt = blockIdx.y, oc0 = 256 + blockIdx.x * 64;

    auto prefetch = [&](int c) {
        uint32_t base = sb + (c & 1) * CONV_STG;
        const __nv_bfloat16* gxh = xh + ((size_t)b * C_ + c * 64) * HW_ + pxt * 128;
        const __nv_bfloat16* gxl = xl + ((size_t)b * C_ + c * 64) * HW_ + pxt * 128;
        for (int idx = tid; idx < 1024; idx += 256) {
            int r = idx >> 4, u = idx & 15;
            uint32_t so = (uint32_t)((r * 136 + u * 8) * 2);
            cp16(base + so,         gxh + (size_t)r * HW_ + u * 8);
            cp16(base + 17408 + so, gxl + (size_t)r * HW_ + u * 8);
        }
        const __nv_bfloat16* gwh = Wh + (size_t)oc0 * 256 + c * 64;
        const __nv_bfloat16* gwl = Wl + (size_t)oc0 * 256 + c * 64;
        for (int idx = tid; idx < 512; idx += 256) {
            int r = idx >> 3, u = idx & 7;
            uint32_t so = (uint32_t)((r * 72 + u * 8) * 2);
            cp16(base + 34816 + so, gwh + (size_t)r * 256 + u * 8);
            cp16(base + 44032 + so, gwl + (size_t)r * 256 + u * 8);
        }
        CP_COMMIT();
    };

    float acc[2][4][4];
#pragma unroll
    for (int mt = 0; mt < 2; mt++)
#pragma unroll
        for (int nt = 0; nt < 4; nt++)
#pragma unroll
            for (int e = 0; e < 4; e++) acc[mt][nt][e] = 0.f;

    prefetch(0);
    for (int ck = 0; ck < 4; ck++) {
        if (ck + 1 < 4) { prefetch(ck + 1); CP_WAIT1(); } else CP_WAIT0();
        __syncthreads();
        uint32_t base = sb + (ck & 1) * CONV_STG;
#pragma unroll
        for (int ks = 0; ks < 4; ks++) {
            const int k0 = ks * 16;
            uint32_t ah[2][4], al[2][4], bh[2][4], bl[2][4];
            ldsm4t(ah[0], at_addr(base, wm * 32,      k0, lane, 136));
            ldsm4t(ah[1], at_addr(base, wm * 32 + 16, k0, lane, 136));
            ldsm4(bh[0], b_addrP(base + 34816, wn * 32,      k0, lane, 72));
            ldsm4(bh[1], b_addrP(base + 34816, wn * 32 + 16, k0, lane, 72));
#pragma unroll
            for (int g = 0; g < 2; g++)
#pragma unroll
                for (int mt = 0; mt < 2; mt++) {
                    mma16816(acc[mt][g*2],   ah[mt], bh[g][0], bh[g][1]);
                    mma16816(acc[mt][g*2+1], ah[mt], bh[g][2], bh[g][3]);
                }
            ldsm4(bl[0], b_addrP(base + 44032, wn * 32,      k0, lane, 72));
            ldsm4(bl[1], b_addrP(base + 44032, wn * 32 + 16, k0, lane, 72));
#pragma unroll
            for (int g = 0; g < 2; g++)
#pragma unroll
                for (int mt = 0; mt < 2; mt++) {
                    mma16816(acc[mt][g*2],   ah[mt], bl[g][0], bl[g][1]);
                    mma16816(acc[mt][g*2+1], ah[mt], bl[g][2], bl[g][3]);
                }
            ldsm4t(al[0], at_addr(base + 17408, wm * 32,      k0, lane, 136));
            ldsm4t(al[1], at_addr(base + 17408, wm * 32 + 16, k0, lane, 136));
#pragma unroll
            for (int g = 0; g < 2; g++)
#pragma unroll
                for (int mt = 0; mt < 2; mt++) {
                    mma16816(acc[mt][g*2],   al[mt], bh[g][0], bh[g][1]);
                    mma16816(acc[mt][g*2+1], al[mt], bh[g][2], bh[g][3]);
                }
        }
        __syncthreads();
    }

#pragma unroll
    for (int mt = 0; mt < 2; mt++) {
        const int row = wm * 32 + mt * 16 + (lane >> 2);
#pragma unroll
        for (int nt = 0; nt < 4; nt++) {
            const int col = wn * 32 + nt * 8 + (lane & 3) * 2;
            sRes[row * 68 + col]       = acc[mt][nt][0];
            sRes[row * 68 + col + 1]   = acc[mt][nt][1];
            sRes[(row+8) * 68 + col]   = acc[mt][nt][2];
            sRes[(row+8) * 68 + col+1] = acc[mt][nt][3];
        }
    }
    __syncthreads();

    if (blockIdx.x == 0) {
        // theta: no pool -> Q [n][64]
        for (int t = tid; t < 128 * 64; t += 256) {
            int p = t >> 6, o = t & 63;
            float v = sRes[p * 68 + o] + bc[256 + o];
            __nv_bfloat16 h, l; split_bf16(v, h, l);
            size_t oidx = ((size_t)b * HW_ + pxt * 128 + p) * 64 + o;
            Qh[oidx] = h; Ql[oidx] = l;
        }
    } else {
        // phi: pool -> K [m][64]
        for (int t = tid; t < 32 * 64; t += 256) {
            int pw = t >> 6, o = t & 63;
            float v = fmaxf(fmaxf(sRes[(2*pw)*68 + o], sRes[(2*pw+1)*68 + o]),
                            fmaxf(sRes[(64+2*pw)*68 + o], sRes[(65+2*pw)*68 + o]))
                      + bc[320 + o];
            __nv_bfloat16 h, l; split_bf16(v, h, l);
            size_t oidx = ((size_t)b * PHW_ + pxt * 32 + pw) * 64 + o;
            Kh[oidx] = h; Kl[oidx] = l;
        }
    }
}

// ======================================================================
// qk_mma: split-bf16 3-pass (proven). P stored tf32 fp32.
// ======================================================================
static constexpr int QK_SMEM = 110592 + 1024;

__global__ __launch_bounds__(256, 2) void qk_mma_kernel(
    const __nv_bfloat16* __restrict__ Qh, const __nv_bfloat16* __restrict__ Ql,
    const __nv_bfloat16* __restrict__ Kh, const __nv_bfloat16* __restrict__ Kl,
    float* __restrict__ Pf, float* __restrict__ rinv)
{
    extern __shared__ char smem[];
    const uint32_t sb = smem_to_u32(smem);
    __nv_bfloat16* sQ = (__nv_bfloat16*)smem;
    float* rs = (float*)(smem + 110592);
    const int tid = threadIdx.x, lane = tid & 31, wid = tid >> 5;
    const int wm = wid & 3, wn = wid >> 2;
    const int b = blockIdx.y, n0 = blockIdx.x * 128;

    auto prefetch = [&](int c) {
        uint32_t base = sb + 36864 + (c & 1) * 36864;
        const __nv_bfloat16* gkh = Kh + ((size_t)b * PHW_ + c * 128) * 64;
        const __nv_bfloat16* gkl = Kl + ((size_t)b * PHW_ + c * 128) * 64;
        for (int idx = tid; idx < 1024; idx += 256) {
            int r = idx >> 3, u = idx & 7;
            uint32_t so = (uint32_t)((r * 72 + u * 8) * 2);
            cp16(base + so,         gkh + r * 64 + u * 8);
            cp16(base + 18432 + so, gkl + r * 64 + u * 8);
        }
        CP_COMMIT();
    };

    prefetch(0);
    {
        const __nv_bfloat16* gqh = Qh + ((size_t)b * HW_ + n0) * 64;
        const __nv_bfloat16* gql = Ql + ((size_t)b * HW_ + n0) * 64;
        for (int idx = tid; idx < 1024; idx += 256) {
            int r = idx >> 3, u = idx & 7;
            *(uint4*)(sQ + r * 72 + u * 8)        = *(const uint4*)(gqh + r * 64 + u * 8);
            *(uint4*)(sQ + 9216 + r * 72 + u * 8) = *(const uint4*)(gql + r * 64 + u * 8);
        }
    }

    float rsum[2][2] = {{0.f, 0.f}, {0.f, 0.f}};

    for (int ck = 0; ck < 8; ck++) {
        const int m0 = ck * 128;
        if (ck + 1 < 8) { prefetch(ck + 1); CP_WAIT1(); } else CP_WAIT0();
        __syncthreads();
        uint32_t kb = sb + 36864 + (ck & 1) * 36864;

        float acc[2][8][4];
#pragma unroll
        for (int mt = 0; mt < 2; mt++)
#pragma unroll
            for (int nt = 0; nt < 8; nt++)
#pragma unroll
                for (int e = 0; e < 4; e++) acc[mt][nt][e] = 0.f;

#pragma unroll
        for (int ks = 0; ks < 4; ks++) {
            const int k0 = ks * 16;
            uint32_t ah[2][4], al[2][4];
            ldsm4(ah[0], a_addrP(sb,         wm * 32,      k0, lane, 72));
            ldsm4(ah[1], a_addrP(sb,         wm * 32 + 16, k0, lane, 72));
            ldsm4(al[0], a_addrP(sb + 18432, wm * 32,      k0, lane, 72));
            ldsm4(al[1], a_addrP(sb + 18432, wm * 32 + 16, k0, lane, 72));
#pragma unroll
            for (int g = 0; g < 4; g++) {
                uint32_t bh[4], bl[4];
                ldsm4(bh, b_addrP(kb,         wn * 64 + g * 16, k0, lane, 72));
                ldsm4(bl, b_addrP(kb + 18432, wn * 64 + g * 16, k0, lane, 72));
#pragma unroll
                for (int mt = 0; mt < 2; mt++) {
                    mma16816(acc[mt][g*2],   ah[mt], bh[0], bh[1]);
                    mma16816(acc[mt][g*2+1], ah[mt], bh[2], bh[3]);
                }
#pragma unroll
                for (int mt = 0; mt < 2; mt++) {
                    mma16816(acc[mt][g*2],   ah[mt], bl[0], bl[1]);
                    mma16816(acc[mt][g*2+1], ah[mt], bl[2], bl[3]);
                }
#pragma unroll
                for (int mt = 0; mt < 2; mt++) {
                    mma16816(acc[mt][g*2],   al[mt], bh[0], bh[1]);
                    mma16816(acc[mt][g*2+1], al[mt], bh[2], bh[3]);
                }
            }
        }

#pragma unroll
        for (int mt = 0; mt < 2; mt++) {
            const int row = n0 + wm * 32 + mt * 16 + (lane >> 2);
#pragma unroll
            for (int nt = 0; nt < 8; nt++) {
                float e0 = __expf(acc[mt][nt][0]);
                float e1 = __expf(acc[mt][nt][1]);
                float e2 = __expf(acc[mt][nt][2]);
                float e3 = __expf(acc[mt][nt][3]);
                rsum[mt][0] += e0 + e1;
                rsum[mt][1] += e2 + e3;
                const int col = m0 + wn * 64 + nt * 8 + (lane & 3) * 2;
                *(float2*)&Pf[((size_t)b * HW_ + row) * PHW_ + col] =
                    make_float2(__uint_as_float(tf32r(e0)), __uint_as_float(tf32r(e1)));
                *(float2*)&Pf[((size_t)b * HW_ + row + 8) * PHW_ + col] =
                    make_float2(__uint_as_float(tf32r(e2)), __uint_as_float(tf32r(e3)));
            }
        }
        __syncthreads();
    }

#pragma unroll
    for (int mt = 0; mt < 2; mt++)
#pragma unroll
        for (int hh = 0; hh < 2; hh++) {
            float s = rsum[mt][hh];
            s += __shfl_xor_sync(0xffffffffu, s, 1);
            s += __shfl_xor_sync(0xffffffffu, s, 2);
            if ((lane & 3) == 0)
                rs[wn * 128 + wm * 32 + mt * 16 + hh * 8 + (lane >> 2)] = s;
        }
    __syncthreads();
    if (tid < 128)
        rinv[(size_t)b * HW_ + n0 + tid] = 1.f / (rs[tid] + rs[128 + tid]);
}

// ======================================================================
// pv_mma (tf32 1-pass): Y = P·V * rinv -> fp16.  Same as R11 mainloop.
// ======================================================================
static constexpr int PV_STG  = 46080;
static constexpr int PV_SMEM = 2 * PV_STG;

__global__ __launch_bounds__(256, 2) void pv_mma_kernel(
    const float* __restrict__ Pf, const float* __restrict__ Vf,
    const float* __restrict__ rinv, __half* __restrict__ Yf)
{
    extern __shared__ char smem[];
    const uint32_t sb = smem_to_u32(smem);
    const int tid = threadIdx.x, lane = tid & 31, wid = tid >> 5;
    const int wm = wid & 1, wn = wid >> 1;
    const int b = blockIdx.y, n0 = blockIdx.x * 64;

    auto prefetch = [&](int c) {
        uint32_t base = sb + (c & 1) * PV_STG;
        const float* gp = Pf + ((size_t)b * HW_ + n0) * PHW_ + c * 32;
        for (int idx = tid; idx < 512; idx += 256) {
            int r = idx >> 3, u = idx & 7;
            cp16(base + (uint32_t)(r * 144 + u * 16), gp + (size_t)r * PHW_ + u * 4);
        }
        const float* gv = Vf + (size_t)b * C_ * PHW_ + c * 32;
        for (int idx = tid; idx < 2048; idx += 256) {
            int r = idx >> 3, u = idx & 7;
            cp16(base + 9216 + (uint32_t)(r * 144 + u * 16), gv + (size_t)r * PHW_ + u * 4);
        }
        CP_COMMIT();
    };

    float acc[2][8][4];
#pragma unroll
    for (int mt = 0; mt < 2; mt++)
#pragma unroll
        for (int nt = 0; nt < 8; nt++)
#pragma unroll
            for (int e = 0; e < 4; e++) acc[mt][nt][e] = 0.f;

    prefetch(0);
    for (int ck = 0; ck < 32; ck++) {
        if (ck + 1 < 32) { prefetch(ck + 1); CP_WAIT1(); } else CP_WAIT0();
        __syncthreads();
        const uint32_t pb = sb + (ck & 1) * PV_STG;
        const uint32_t vb = pb + 9216;
#pragma unroll
        for (int ks = 0; ks < 4; ks++) {
            const int k0 = ks * 8;
            uint32_t a[2][4], bf[8][2];
#pragma unroll
            for (int mt = 0; mt < 2; mt++) {
                const int ra = wm * 32 + mt * 16 + (lane >> 2);
                const int ca = k0 + (lane & 3);
                a[mt][0] = lds32(pb + (uint32_t)((ra * 36 + ca) * 4));
                a[mt][1] = lds32(pb + (uint32_t)(((ra + 8) * 36 + ca) * 4));
                a[mt][2] = lds32(pb + (uint32_t)((ra * 36 + ca + 4) * 4));
                a[mt][3] = lds32(pb + (uint32_t)(((ra + 8) * 36 + ca + 4) * 4));
            }
#pragma unroll
            for (int g = 0; g < 8; g++) {
                const int nn = wn * 64 + g * 8 + (lane >> 2);
                const int kk = k0 + (lane & 3);
                bf[g][0] = lds32(vb + (uint32_t)((nn * 36 + kk) * 4));
                bf[g][1] = lds32(vb + (uint32_t)((nn * 36 + kk + 4) * 4));
            }
#pragma unroll
            for (int g = 0; g < 8; g++)
#pragma unroll
                for (int mt = 0; mt < 2; mt++)
                    mma1688t(acc[mt][g], a[mt], bf[g][0], bf[g][1]);
        }
        __syncthreads();
    }

#pragma unroll
    for (int mt = 0; mt < 2; mt++) {
        const int r0 = n0 + wm * 32 + mt * 16 + (lane >> 2);
        const float i0 = rinv[(size_t)b * HW_ + r0];
        const float i1 = rinv[(size_t)b * HW_ + r0 + 8];
#pragma unroll
        for (int nt = 0; nt < 8; nt++) {
            const int col = wn * 64 + nt * 8 + (lane & 3) * 2;
            __half2 p0 = __floats2half2_rn(acc[mt][nt][0] * i0, acc[mt][nt][1] * i0);
            __half2 p1 = __floats2half2_rn(acc[mt][nt][2] * i1, acc[mt][nt][3] * i1);
            *(__half2*)&Yf[((size_t)b * HW_ + r0) * C_ + col] = p0;
            *(__half2*)&Yf[((size_t)b * HW_ + r0 + 8) * C_ + col] = p1;
        }
    }
}

// ======================================================================
// final_mma (fp16 1-pass): out = BN(Y @ W^T + Wb) + x.
// CTA = 128 px x 64 oc, grid (4, 32, 8), block 256 (4m x 2n), 2 CTAs/SM.
// stage s @ s*27648: A fp16 [128][72] (18432B), B fp16 [64][72] (+18432).
// sRes [128][68] fp32 union at 0 (overlaps stage 1 -- used only at end).
// ======================================================================
static constexpr int FIN_STG  = 27648;
static constexpr int FIN_SMEM = 2 * FIN_STG;

__global__ __launch_bounds__(256, 2) void final_mma_kernel(
    const __half* __restrict__ Yf, const __half* __restrict__ Wf,
    const float* __restrict__ Wb,
    const float* __restrict__ gamma, const float* __restrict__ beta,
    const float* __restrict__ mean, const float* __restrict__ var,
    const float* __restrict__ x, float* __restrict__ out)
{
    extern __shared__ char smem[];
    const uint32_t sb = smem_to_u32(smem);
    float* sRes = (float*)smem;
    const int tid = threadIdx.x, lane = tid & 31, wid = tid >> 5;
    const int wm = wid & 3, wn = wid >> 2;
    const int b = blockIdx.z, pxt = blockIdx.y, oc0 = blockIdx.x * 64;

    auto prefetch = [&](int c) {
        uint32_t base = sb + (c & 1) * FIN_STG;
        const __half* gA = Yf + ((size_t)b * HW_ + pxt * 128) * C_ + c * 64;
        for (int idx = tid; idx < 1024; idx += 256) {
            int r = idx >> 3, u = idx & 7;
            cp16(base + (uint32_t)((r * 72 + u * 8) * 2), gA + (size_t)r * C_ + u * 8);
        }
        const __half* gB = Wf + (size_t)oc0 * 256 + c * 64;
        for (int idx = tid; idx < 512; idx += 256) {
            int r = idx >> 3, u = idx & 7;
            cp16(base + 18432 + (uint32_t)((r * 72 + u * 8) * 2), gB + (size_t)r * 256 + u * 8);
        }
        CP_COMMIT();
    };

    float acc[2][4][4];
#pragma unroll
    for (int mt = 0; mt < 2; mt++)
#pragma unroll
        for (int nt = 0; nt < 4; nt++)
#pragma unroll
            for (int e = 0; e < 4; e++) acc[mt][nt][e] = 0.f;

    prefetch(0);
    for (int ck = 0; ck < 4; ck++) {
        if (ck + 1 < 4) { prefetch(ck + 1); CP_WAIT1(); } else CP_WAIT0();
        __syncthreads();
        uint32_t base = sb + (ck & 1) * FIN_STG;
#pragma unroll
        for (int ks = 0; ks < 4; ks++) {
            const int k0 = ks * 16;
            uint32_t a[2][4], bb[2][4];
            ldsm4(a[0], a_addrP(base, wm * 32,      k0, lane, 72));
            ldsm4(a[1], a_addrP(base, wm * 32 + 16, k0, lane, 72));
            ldsm4(bb[0], b_addrP(base + 18432, wn * 32,      k0, lane, 72));
            ldsm4(bb[1], b_addrP(base + 18432, wn * 32 + 16, k0, lane, 72));
#pragma unroll
            for (int g = 0; g < 2; g++)
#pragma unroll
                for (int mt = 0; mt < 2; mt++) {
                    mma16816h(acc[mt][g*2],   a[mt], bb[g][0], bb[g][1]);
                    mma16816h(acc[mt][g*2+1], a[mt], bb[g][2], bb[g][3]);
                }
        }
        __syncthreads();
    }

#pragma unroll
    for (int mt = 0; mt < 2; mt++) {
        const int row = wm * 32 + mt * 16 + (lane >> 2);
#pragma unroll
        for (int nt = 0; nt < 4; nt++) {
            const int col = wn * 32 + nt * 8 + (lane & 3) * 2;
            sRes[row * 68 + col]       = acc[mt][nt][0];
            sRes[row * 68 + col + 1]   = acc[mt][nt][1];
            sRes[(row+8) * 68 + col]   = acc[mt][nt][2];
            sRes[(row+8) * 68 + col+1] = acc[mt][nt][3];
        }
    }
    __syncthreads();

    for (int t = tid; t < 128 * 64; t += 256) {
        int o = t >> 7, p = t & 127;
        int oc = oc0 + o;
        float scale = gamma[oc] * rsqrtf(var[oc] + EPS_);
        size_t gidx = ((size_t)b * C_ + oc) * HW_ + pxt * 128 + p;
        out[gidx] = (sRes[p * 68 + o] + Wb[oc] - mean[oc]) * scale + beta[oc] + x[gidx];
    }
}

// ======================================================================
extern "C" void kernel_launch(void* const* d_in, const int* in_sizes, int n_in,
                              void* d_out, int out_size)
{
    const float* x       = (const float*)d_in[0];
    const float* g_w     = (const float*)d_in[1];
    const float* g_b     = (const float*)d_in[2];
    const float* theta_w = (const float*)d_in[3];
    const float* theta_b = (const float*)d_in[4];
    const float* phi_w   = (const float*)d_in[5];
    const float* phi_b   = (const float*)d_in[6];
    const float* W_w     = (const float*)d_in[7];
    const float* W_b     = (const float*)d_in[8];
    const float* bn_g    = (const float*)d_in[9];
    const float* bn_b    = (const float*)d_in[10];
    const float* bn_m    = (const float*)d_in[11];
    const float* bn_v    = (const float*)d_in[12];
    float* out = (float*)d_out;

    __nv_bfloat16 *xh, *xl, *Wch, *Wcl, *Qh, *Ql, *Kh, *Kl;
    float *xf, *Wgf, *Vf, *Pf, *rv, *bc;
    __half *Wff, *Yf;
    cudaGetSymbolAddress((void**)&xh,  d_xh);
    cudaGetSymbolAddress((void**)&xl,  d_xl);
    cudaGetSymbolAddress((void**)&xf,  d_xf);
    cudaGetSymbolAddress((void**)&Wch, d_Wch);
    cudaGetSymbolAddress((void**)&Wcl, d_Wcl);
    cudaGetSymbolAddress((void**)&Wgf, d_Wgf);
    cudaGetSymbolAddress((void**)&bc,  d_bc);
    cudaGetSymbolAddress((void**)&Wff, d_Wff);
    cudaGetSymbolAddress((void**)&Qh,  d_Qh);
    cudaGetSymbolAddress((void**)&Ql,  d_Ql);
    cudaGetSymbolAddress((void**)&Kh,  d_Kh);
    cudaGetSymbolAddress((void**)&Kl,  d_Kl);
    cudaGetSymbolAddress((void**)&Vf,  d_Vf);
    cudaGetSymbolAddress((void**)&Pf,  d_Pf);
    cudaGetSymbolAddress((void**)&rv,  d_rinv);
    cudaGetSymbolAddress((void**)&Yf,  d_Yf);

    cudaFuncSetAttribute(conv_g_kernel,    cudaFuncAttributeMaxDynamicSharedMemorySize, CG_SMEM);
    cudaFuncSetAttribute(conv_qk_kernel,   cudaFuncAttributeMaxDynamicSharedMemorySize, CONV_SMEM);
    cudaFuncSetAttribute(qk_mma_kernel,    cudaFuncAttributeMaxDynamicSharedMemorySize, QK_SMEM);
    cudaFuncSetAttribute(pv_mma_kernel,    cudaFuncAttributeMaxDynamicSharedMemorySize, PV_SMEM);
    cudaFuncSetAttribute(final_mma_kernel, cudaFuncAttributeMaxDynamicSharedMemorySize, FIN_SMEM);

    xsplit_kernel<<<BB * C_ * HW_ / 1024, 256>>>(x, xh, xl, xf);
    wpack_conv_kernel<<<384, 256>>>(g_w, g_b, theta_w, theta_b, phi_w, phi_b,
                                    Wch, Wcl, Wgf, bc);
    wpack_final_kernel<<<256, 256>>>(W_w, Wff);
    conv_g_kernel<<<dim3(4, 32, BB), 256, CG_SMEM>>>(xf, Wgf, bc, Vf);
    conv_qk_kernel<<<dim3(2, 32, BB), 256, CONV_SMEM>>>(xh, xl, Wch, Wcl, bc,
                                                        Qh, Ql, Kh, Kl);
    qk_mma_kernel<<<dim3(32, BB), 256, QK_SMEM>>>(Qh, Ql, Kh, Kl, Pf, rv);
    pv_mma_kernel<<<dim3(64, BB), 256, PV_SMEM>>>(Pf, Vf, rv, Yf);
    final_mma_kernel<<<dim3(4, 32, BB), 256, FIN_SMEM>>>(Yf, Wff, W_b,
                                                         bn_g, bn_b, bn_m, bn_v, x, out);
}

// round 14
// speedup vs baseline: 2.1286x; 1.1875x over previous
#include <cuda_runtime.h>
#include <cuda_bf16.h>
#include <cuda_fp16.h>
#include <cstdint>

#define BB 8
#define C_ 256
#define HW_ 4096
#define PHW_ 1024
#define EPS_ 1e-5f

// ---------------- helpers ----------------
__device__ __forceinline__ uint32_t smem_to_u32(const void* p) {
    uint32_t a;
    asm("{ .reg .u64 t; cvta.to.shared.u64 t, %1; cvt.u32.u64 %0, t; }" : "=r"(a) : "l"(p));
    return a;
}
__device__ __forceinline__ void ldsm4(uint32_t* r, uint32_t addr) {
    asm volatile("ldmatrix.sync.aligned.m8n8.x4.shared.b16 {%0,%1,%2,%3}, [%4];"
        : "=r"(r[0]), "=r"(r[1]), "=r"(r[2]), "=r"(r[3]) : "r"(addr));
}
__device__ __forceinline__ void ldsm4t(uint32_t* r, uint32_t addr) {
    asm volatile("ldmatrix.sync.aligned.m8n8.x4.trans.shared.b16 {%0,%1,%2,%3}, [%4];"
        : "=r"(r[0]), "=r"(r[1]), "=r"(r[2]), "=r"(r[3]) : "r"(addr));
}
__device__ __forceinline__ void mma16816(float* d, const uint32_t* a, uint32_t b0, uint32_t b1) {
    asm volatile("mma.sync.aligned.m16n8k16.row.col.f32.bf16.bf16.f32 "
        "{%0,%1,%2,%3}, {%4,%5,%6,%7}, {%8,%9}, {%0,%1,%2,%3};"
        : "+f"(d[0]), "+f"(d[1]), "+f"(d[2]), "+f"(d[3])
        : "r"(a[0]), "r"(a[1]), "r"(a[2]), "r"(a[3]), "r"(b0), "r"(b1));
}
__device__ __forceinline__ void mma16816h(float* d, const uint32_t* a, uint32_t b0, uint32_t b1) {
    asm volatile("mma.sync.aligned.m16n8k16.row.col.f32.f16.f16.f32 "
        "{%0,%1,%2,%3}, {%4,%5,%6,%7}, {%8,%9}, {%0,%1,%2,%3};"
        : "+f"(d[0]), "+f"(d[1]), "+f"(d[2]), "+f"(d[3])
        : "r"(a[0]), "r"(a[1]), "r"(a[2]), "r"(a[3]), "r"(b0), "r"(b1));
}
// tf32 MMA m16n8k8
__device__ __forceinline__ void mma1688t(float* d, const uint32_t* a, uint32_t b0, uint32_t b1) {
    asm volatile("mma.sync.aligned.m16n8k8.row.col.f32.tf32.tf32.f32 "
        "{%0,%1,%2,%3}, {%4,%5,%6,%7}, {%8,%9}, {%0,%1,%2,%3};"
        : "+f"(d[0]), "+f"(d[1]), "+f"(d[2]), "+f"(d[3])
        : "r"(a[0]), "r"(a[1]), "r"(a[2]), "r"(a[3]), "r"(b0), "r"(b1));
}
__device__ __forceinline__ uint32_t lds32(uint32_t addr) {
    uint32_t v;
    asm volatile("ld.shared.b32 %0, [%1];" : "=r"(v) : "r"(addr));
    return v;
}
__device__ __forceinline__ uint32_t tf32r(float v) {
    uint32_t u;
    asm("cvt.rna.tf32.f32 %0, %1;" : "=r"(u) : "f"(v));
    return u;
}
__device__ __forceinline__ void cp16(uint32_t s, const void* g) {
    asm volatile("cp.async.cg.shared.global [%0], [%1], 16;" :: "r"(s), "l"(g));
}
#define CP_COMMIT() asm volatile("cp.async.commit_group;" ::: "memory")
#define CP_WAIT0()  asm volatile("cp.async.wait_group 0;" ::: "memory")
#define CP_WAIT1()  asm volatile("cp.async.wait_group 1;" ::: "memory")

__device__ __forceinline__ void split_bf16(float v, __nv_bfloat16& h, __nv_bfloat16& l) {
    h = __float2bfloat16(v);
    l = __float2bfloat16(v - __bfloat162float(h));
}
__device__ __forceinline__ void split2(float a, float b, uint32_t& hh, uint32_t& ll) {
    __nv_bfloat16 ha, la, hb, lb;
    split_bf16(a, ha, la); split_bf16(b, hb, lb);
    hh = (uint32_t)__bfloat16_as_ushort(ha) | ((uint32_t)__bfloat16_as_ushort(hb) << 16);
    ll = (uint32_t)__bfloat16_as_ushort(la) | ((uint32_t)__bfloat16_as_ushort(lb) << 16);
}

// A-fragment (m16k16) from [m][k] row-major smem, pitch P elems (16-bit)
__device__ __forceinline__ uint32_t a_addrP(uint32_t base, int row0, int k0, int lane, int P) {
    int r = row0 + (lane & 15), c = k0 + ((lane >> 4) << 3);
    return base + (uint32_t)((r * P + c) * 2);
}
// A-fragment (m16k16) from [k][m] storage via trans-ldmatrix, pitch P (16-bit)
__device__ __forceinline__ uint32_t at_addr(uint32_t base, int m0, int k0, int lane, int P) {
    int t = lane >> 3;
    int m = m0 + ((t & 1) << 3);
    int k = k0 + ((t >> 1) << 3) + (lane & 7);
    return base + (uint32_t)((k * P + m) * 2);
}
// B-fragment x4 (two n8k16 tiles) from [n][k] row-major smem, pitch P (16-bit)
__device__ __forceinline__ uint32_t b_addrP(uint32_t base, int n0, int k0, int lane, int P) {
    int r = n0 + (lane & 7) + ((lane >> 4) << 3), c = k0 + (((lane >> 3) & 1) << 3);
    return base + (uint32_t)((r * P + c) * 2);
}

// ---------------- scratch ----------------
__device__ __nv_bfloat16 d_xh[BB*C_*HW_], d_xl[BB*C_*HW_];
__device__ float         d_xf[BB*C_*HW_];
__device__ __nv_bfloat16 d_Wch[384*256],  d_Wcl[384*256];
__device__ float         d_Wgf[256*256];
__device__ float         d_bc[384];
__device__ __half        d_Wff[256*256];
__device__ __nv_bfloat16 d_Qh[BB*HW_*64],  d_Ql[BB*HW_*64];
__device__ __nv_bfloat16 d_Kh[BB*PHW_*64], d_Kl[BB*PHW_*64];
__device__ __half        d_V16[BB*C_*PHW_];                // V fp16
__device__ float         d_Sf[(size_t)BB*HW_*PHW_];        // raw S fp32
__device__ float         d_rmax[BB*HW_];
__device__ __half        d_Yf[BB*HW_*C_];

// ======================================================================
// xsplit + weight packing
// ======================================================================
__global__ __launch_bounds__(256) void xsplit_kernel(
    const float* __restrict__ x, __nv_bfloat16* __restrict__ xh,
    __nv_bfloat16* __restrict__ xl, float* __restrict__ xf)
{
    size_t i = ((size_t)blockIdx.x * 256 + threadIdx.x) * 4;
    float4 v = *(const float4*)(x + i);
    uint32_t h0, l0, h1, l1;
    split2(v.x, v.y, h0, l0);
    split2(v.z, v.w, h1, l1);
    *(uint2*)(xh + i) = make_uint2(h0, h1);
    *(uint2*)(xl + i) = make_uint2(l0, l1);
    float4 t;
    t.x = __uint_as_float(tf32r(v.x)); t.y = __uint_as_float(tf32r(v.y));
    t.z = __uint_as_float(tf32r(v.z)); t.w = __uint_as_float(tf32r(v.w));
    *(float4*)(xf + i) = t;
}

__global__ void wpack_conv_kernel(
    const float* __restrict__ g_w, const float* __restrict__ g_b,
    const float* __restrict__ th_w, const float* __restrict__ th_b,
    const float* __restrict__ ph_w, const float* __restrict__ ph_b,
    __nv_bfloat16* __restrict__ Wh, __nv_bfloat16* __restrict__ Wl,
    float* __restrict__ Wgf, float* __restrict__ bc)
{
    int oc = blockIdx.x, k = threadIdx.x;
    float v;
    if (oc < 256)       v = g_w[oc * 256 + k];
    else if (oc < 320)  v = (k < 64) ? th_w[(oc - 256) * 64 + k] : 0.f;
    else                v = (k >= 64) ? ph_w[(oc - 320) * 192 + (k - 64)] : 0.f;
    __nv_bfloat16 h, l; split_bf16(v, h, l);
    Wh[oc * 256 + k] = h; Wl[oc * 256 + k] = l;
    if (oc < 256) Wgf[oc * 256 + k] = __uint_as_float(tf32r(v));
    if (k == 0)
        bc[oc] = (oc < 256) ? g_b[oc] : (oc < 320) ? th_b[oc - 256] : ph_b[oc - 320];
}

__global__ void wpack_final_kernel(const float* __restrict__ w, __half* __restrict__ Wf)
{
    int i = blockIdx.x * 256 + threadIdx.x;
    Wf[i] = __float2half_rn(w[i]);
}

// ======================================================================
// conv_g (tf32 1-pass): V = pool(g_conv(x)) -> fp16.
// CTA = 128 px x 64 oc, grid (4, 32, 8), block 256, 2 CTAs/SM.
// ======================================================================
static constexpr int CG_STG  = 51200;
static constexpr int CG_SMEM = 2 * CG_STG;

__global__ __launch_bounds__(256, 2) void conv_g_kernel(
    const float* __restrict__ xf, const float* __restrict__ Wg,
    const float* __restrict__ bc, __half* __restrict__ V16)
{
    extern __shared__ char smem[];
    const uint32_t sb = smem_to_u32(smem);
    float* sRes = (float*)smem;
    const int tid = threadIdx.x, lane = tid & 31, wid = tid >> 5;
    const int wm = wid & 3, wn = wid >> 2;
    const int b = blockIdx.z, pxt = blockIdx.y, oc0 = blockIdx.x * 64;

    auto prefetch = [&](int c) {
        uint32_t base = sb + (c & 1) * CG_STG;
        const float* gx = xf + ((size_t)b * C_ + c * 64) * HW_ + pxt * 128;
        for (int idx = tid; idx < 2048; idx += 256) {
            int r = idx >> 5, u = idx & 31;
            cp16(base + (uint32_t)((r * 132 + u * 4) * 4), gx + (size_t)r * HW_ + u * 4);
        }
        const float* gw = Wg + (size_t)oc0 * 256 + c * 64;
        for (int idx = tid; idx < 1024; idx += 256) {
            int r = idx >> 4, u = idx & 15;
            cp16(base + 33792 + (uint32_t)((r * 68 + u * 4) * 4), gw + (size_t)r * 256 + u * 4);
        }
        CP_COMMIT();
    };

    float acc[2][4][4];
#pragma unroll
    for (int mt = 0; mt < 2; mt++)
#pragma unroll
        for (int nt = 0; nt < 4; nt++)
#pragma unroll
            for (int e = 0; e < 4; e++) acc[mt][nt][e] = 0.f;

    prefetch(0);
    for (int ck = 0; ck < 4; ck++) {
        if (ck + 1 < 4) { prefetch(ck + 1); CP_WAIT1(); } else CP_WAIT0();
        __syncthreads();
        const uint32_t xb = sb + (ck & 1) * CG_STG;
        const uint32_t wb = xb + 33792;
#pragma unroll
        for (int ks = 0; ks < 8; ks++) {
            const int k0 = ks * 8;
            uint32_t a[2][4], bf[4][2];
            const int ca = k0 + (lane & 3);
#pragma unroll
            for (int mt = 0; mt < 2; mt++) {
                const int ra = wm * 32 + mt * 16 + (lane >> 2);
                a[mt][0] = lds32(xb + (uint32_t)((ca * 132 + ra) * 4));
                a[mt][1] = lds32(xb + (uint32_t)((ca * 132 + ra + 8) * 4));
                a[mt][2] = lds32(xb + (uint32_t)(((ca + 4) * 132 + ra) * 4));
                a[mt][3] = lds32(xb + (uint32_t)(((ca + 4) * 132 + ra + 8) * 4));
            }
#pragma unroll
            for (int g = 0; g < 4; g++) {
                const int nn = wn * 32 + g * 8 + (lane >> 2);
                bf[g][0] = lds32(wb + (uint32_t)((nn * 68 + ca) * 4));
                bf[g][1] = lds32(wb + (uint32_t)((nn * 68 + ca + 4) * 4));
            }
#pragma unroll
            for (int g = 0; g < 4; g++)
#pragma unroll
                for (int mt = 0; mt < 2; mt++)
                    mma1688t(acc[mt][g], a[mt], bf[g][0], bf[g][1]);
        }
        __syncthreads();
    }

#pragma unroll
    for (int mt = 0; mt < 2; mt++) {
        const int row = wm * 32 + mt * 16 + (lane >> 2);
#pragma unroll
        for (int nt = 0; nt < 4; nt++) {
            const int col = wn * 32 + nt * 8 + (lane & 3) * 2;
            sRes[row * 68 + col]       = acc[mt][nt][0];
            sRes[row * 68 + col + 1]   = acc[mt][nt][1];
            sRes[(row+8) * 68 + col]   = acc[mt][nt][2];
            sRes[(row+8) * 68 + col+1] = acc[mt][nt][3];
        }
    }
    __syncthreads();

    for (int t = tid; t < 32 * 64; t += 256) {
        int pw = t >> 6, o = t & 63, oc = oc0 + o;
        float v = fmaxf(fmaxf(sRes[(2*pw)*68 + o], sRes[(2*pw+1)*68 + o]),
                        fmaxf(sRes[(64+2*pw)*68 + o], sRes[(65+2*pw)*68 + o]))
                  + bc[oc];
        size_t oidx = ((size_t)b * C_ + oc) * PHW_ + pxt * 32 + pw;
        V16[oidx] = __float2half_rn(v);
    }
}

// ======================================================================
// conv_qk (bf16 3-pass): theta + phi convs (unchanged)
// ======================================================================
static constexpr int CONV_STG  = 53248;
static constexpr int CONV_SMEM = 2 * CONV_STG;

__global__ __launch_bounds__(256, 2) void conv_qk_kernel(
    const __nv_bfloat16* __restrict__ xh, const __nv_bfloat16* __restrict__ xl,
    const __nv_bfloat16* __restrict__ Wh, const __nv_bfloat16* __restrict__ Wl,
    const float* __restrict__ bc,
    __nv_bfloat16* __restrict__ Qh, __nv_bfloat16* __restrict__ Ql,
    __nv_bfloat16* __restrict__ Kh, __nv_bfloat16* __restrict__ Kl)
{
    extern __shared__ char smem[];
    const uint32_t sb = smem_to_u32(smem);
    float* sRes = (float*)smem;
    const int tid = threadIdx.x, lane = tid & 31, wid = tid >> 5;
    const int wm = wid & 3, wn = wid >> 2;
    const int b = blockIdx.z, pxt = blockIdx.y, oc0 = 256 + blockIdx.x * 64;

    auto prefetch = [&](int c) {
        uint32_t base = sb + (c & 1) * CONV_STG;
        const __nv_bfloat16* gxh = xh + ((size_t)b * C_ + c * 64) * HW_ + pxt * 128;
        const __nv_bfloat16* gxl = xl + ((size_t)b * C_ + c * 64) * HW_ + pxt * 128;
        for (int idx = tid; idx < 1024; idx += 256) {
            int r = idx >> 4, u = idx & 15;
            uint32_t so = (uint32_t)((r * 136 + u * 8) * 2);
            cp16(base + so,         gxh + (size_t)r * HW_ + u * 8);
            cp16(base + 17408 + so, gxl + (size_t)r * HW_ + u * 8);
        }
        const __nv_bfloat16* gwh = Wh + (size_t)oc0 * 256 + c * 64;
        const __nv_bfloat16* gwl = Wl + (size_t)oc0 * 256 + c * 64;
        for (int idx = tid; idx < 512; idx += 256) {
            int r = idx >> 3, u = idx & 7;
            uint32_t so = (uint32_t)((r * 72 + u * 8) * 2);
            cp16(base + 34816 + so, gwh + (size_t)r * 256 + u * 8);
            cp16(base + 44032 + so, gwl + (size_t)r * 256 + u * 8);
        }
        CP_COMMIT();
    };

    float acc[2][4][4];
#pragma unroll
    for (int mt = 0; mt < 2; mt++)
#pragma unroll
        for (int nt = 0; nt < 4; nt++)
#pragma unroll
            for (int e = 0; e < 4; e++) acc[mt][nt][e] = 0.f;

    prefetch(0);
    for (int ck = 0; ck < 4; ck++) {
        if (ck + 1 < 4) { prefetch(ck + 1); CP_WAIT1(); } else CP_WAIT0();
        __syncthreads();
        uint32_t base = sb + (ck & 1) * CONV_STG;
#pragma unroll
        for (int ks = 0; ks < 4; ks++) {
            const int k0 = ks * 16;
            uint32_t ah[2][4], al[2][4], bh[2][4], bl[2][4];
            ldsm4t(ah[0], at_addr(base, wm * 32,      k0, lane, 136));
            ldsm4t(ah[1], at_addr(base, wm * 32 + 16, k0, lane, 136));
            ldsm4(bh[0], b_addrP(base + 34816, wn * 32,      k0, lane, 72));
            ldsm4(bh[1], b_addrP(base + 34816, wn * 32 + 16, k0, lane, 72));
#pragma unroll
            for (int g = 0; g < 2; g++)
#pragma unroll
                for (int mt = 0; mt < 2; mt++) {
                    mma16816(acc[mt][g*2],   ah[mt], bh[g][0], bh[g][1]);
                    mma16816(acc[mt][g*2+1], ah[mt], bh[g][2], bh[g][3]);
                }
            ldsm4(bl[0], b_addrP(base + 44032, wn * 32,      k0, lane, 72));
            ldsm4(bl[1], b_addrP(base + 44032, wn * 32 + 16, k0, lane, 72));
#pragma unroll
            for (int g = 0; g < 2; g++)
#pragma unroll
                for (int mt = 0; mt < 2; mt++) {
                    mma16816(acc[mt][g*2],   ah[mt], bl[g][0], bl[g][1]);
                    mma16816(acc[mt][g*2+1], ah[mt], bl[g][2], bl[g][3]);
                }
            ldsm4t(al[0], at_addr(base + 17408, wm * 32,      k0, lane, 136));
            ldsm4t(al[1], at_addr(base + 17408, wm * 32 + 16, k0, lane, 136));
#pragma unroll
            for (int g = 0; g < 2; g++)
#pragma unroll
                for (int mt = 0; mt < 2; mt++) {
                    mma16816(acc[mt][g*2],   al[mt], bh[g][0], bh[g][1]);
                    mma16816(acc[mt][g*2+1], al[mt], bh[g][2], bh[g][3]);
                }
        }
        __syncthreads();
    }

#pragma unroll
    for (int mt = 0; mt < 2; mt++) {
        const int row = wm * 32 + mt * 16 + (lane >> 2);
#pragma unroll
        for (int nt = 0; nt < 4; nt++) {
            const int col = wn * 32 + nt * 8 + (lane & 3) * 2;
            sRes[row * 68 + col]       = acc[mt][nt][0];
            sRes[row * 68 + col + 1]   = acc[mt][nt][1];
            sRes[(row+8) * 68 + col]   = acc[mt][nt][2];
            sRes[(row+8) * 68 + col+1] = acc[mt][nt][3];
        }
    }
    __syncthreads();

    if (blockIdx.x == 0) {
        for (int t = tid; t < 128 * 64; t += 256) {
            int p = t >> 6, o = t & 63;
            float v = sRes[p * 68 + o] + bc[256 + o];
            __nv_bfloat16 h, l; split_bf16(v, h, l);
            size_t oidx = ((size_t)b * HW_ + pxt * 128 + p) * 64 + o;
            Qh[oidx] = h; Ql[oidx] = l;
        }
    } else {
        for (int t = tid; t < 32 * 64; t += 256) {
            int pw = t >> 6, o = t & 63;
            float v = fmaxf(fmaxf(sRes[(2*pw)*68 + o], sRes[(2*pw+1)*68 + o]),
                            fmaxf(sRes[(64+2*pw)*68 + o], sRes[(65+2*pw)*68 + o]))
                      + bc[320 + o];
            __nv_bfloat16 h, l; split_bf16(v, h, l);
            size_t oidx = ((size_t)b * PHW_ + pxt * 32 + pw) * 64 + o;
            Kh[oidx] = h; Kl[oidx] = l;
        }
    }
}

// ======================================================================
// qk_mma: split-bf16 3-pass. Stores RAW S fp32 + per-row max.
// ======================================================================
static constexpr int QK_SMEM = 110592 + 1024;

__global__ __launch_bounds__(256, 2) void qk_mma_kernel(
    const __nv_bfloat16* __restrict__ Qh, const __nv_bfloat16* __restrict__ Ql,
    const __nv_bfloat16* __restrict__ Kh, const __nv_bfloat16* __restrict__ Kl,
    float* __restrict__ Sf, float* __restrict__ rmax)
{
    extern __shared__ char smem[];
    const uint32_t sb = smem_to_u32(smem);
    __nv_bfloat16* sQ = (__nv_bfloat16*)smem;
    float* rs = (float*)(smem + 110592);
    const int tid = threadIdx.x, lane = tid & 31, wid = tid >> 5;
    const int wm = wid & 3, wn = wid >> 2;
    const int b = blockIdx.y, n0 = blockIdx.x * 128;

    auto prefetch = [&](int c) {
        uint32_t base = sb + 36864 + (c & 1) * 36864;
        const __nv_bfloat16* gkh = Kh + ((size_t)b * PHW_ + c * 128) * 64;
        const __nv_bfloat16* gkl = Kl + ((size_t)b * PHW_ + c * 128) * 64;
        for (int idx = tid; idx < 1024; idx += 256) {
            int r = idx >> 3, u = idx & 7;
            uint32_t so = (uint32_t)((r * 72 + u * 8) * 2);
            cp16(base + so,         gkh + r * 64 + u * 8);
            cp16(base + 18432 + so, gkl + r * 64 + u * 8);
        }
        CP_COMMIT();
    };

    prefetch(0);
    {
        const __nv_bfloat16* gqh = Qh + ((size_t)b * HW_ + n0) * 64;
        const __nv_bfloat16* gql = Ql + ((size_t)b * HW_ + n0) * 64;
        for (int idx = tid; idx < 1024; idx += 256) {
            int r = idx >> 3, u = idx & 7;
            *(uint4*)(sQ + r * 72 + u * 8)        = *(const uint4*)(gqh + r * 64 + u * 8);
            *(uint4*)(sQ + 9216 + r * 72 + u * 8) = *(const uint4*)(gql + r * 64 + u * 8);
        }
    }

    float rmx[2][2] = {{-1e30f, -1e30f}, {-1e30f, -1e30f}};

    for (int ck = 0; ck < 8; ck++) {
        const int m0 = ck * 128;
        if (ck + 1 < 8) { prefetch(ck + 1); CP_WAIT1(); } else CP_WAIT0();
        __syncthreads();
        uint32_t kb = sb + 36864 + (ck & 1) * 36864;

        float acc[2][8][4];
#pragma unroll
        for (int mt = 0; mt < 2; mt++)
#pragma unroll
            for (int nt = 0; nt < 8; nt++)
#pragma unroll
                for (int e = 0; e < 4; e++) acc[mt][nt][e] = 0.f;

#pragma unroll
        for (int ks = 0; ks < 4; ks++) {
            const int k0 = ks * 16;
            uint32_t ah[2][4], al[2][4];
            ldsm4(ah[0], a_addrP(sb,         wm * 32,      k0, lane, 72));
            ldsm4(ah[1], a_addrP(sb,         wm * 32 + 16, k0, lane, 72));
            ldsm4(al[0], a_addrP(sb + 18432, wm * 32,      k0, lane, 72));
            ldsm4(al[1], a_addrP(sb + 18432, wm * 32 + 16, k0, lane, 72));
#pragma unroll
            for (int g = 0; g < 4; g++) {
                uint32_t bh[4], bl[4];
                ldsm4(bh, b_addrP(kb,         wn * 64 + g * 16, k0, lane, 72));
                ldsm4(bl, b_addrP(kb + 18432, wn * 64 + g * 16, k0, lane, 72));
#pragma unroll
                for (int mt = 0; mt < 2; mt++) {
                    mma16816(acc[mt][g*2],   ah[mt], bh[0], bh[1]);
                    mma16816(acc[mt][g*2+1], ah[mt], bh[2], bh[3]);
                }
#pragma unroll
                for (int mt = 0; mt < 2; mt++) {
                    mma16816(acc[mt][g*2],   ah[mt], bl[0], bl[1]);
                    mma16816(acc[mt][g*2+1], ah[mt], bl[2], bl[3]);
                }
#pragma unroll
                for (int mt = 0; mt < 2; mt++) {
                    mma16816(acc[mt][g*2],   al[mt], bh[0], bh[1]);
                    mma16816(acc[mt][g*2+1], al[mt], bh[2], bh[3]);
                }
            }
        }

#pragma unroll
        for (int mt = 0; mt < 2; mt++) {
            const int row = n0 + wm * 32 + mt * 16 + (lane >> 2);
#pragma unroll
            for (int nt = 0; nt < 8; nt++) {
                float s0 = acc[mt][nt][0], s1 = acc[mt][nt][1];
                float s2 = acc[mt][nt][2], s3 = acc[mt][nt][3];
                rmx[mt][0] = fmaxf(rmx[mt][0], fmaxf(s0, s1));
                rmx[mt][1] = fmaxf(rmx[mt][1], fmaxf(s2, s3));
                const int col = m0 + wn * 64 + nt * 8 + (lane & 3) * 2;
                *(float2*)&Sf[((size_t)b * HW_ + row) * PHW_ + col] = make_float2(s0, s1);
                *(float2*)&Sf[((size_t)b * HW_ + row + 8) * PHW_ + col] = make_float2(s2, s3);
            }
        }
        __syncthreads();
    }

#pragma unroll
    for (int mt = 0; mt < 2; mt++)
#pragma unroll
        for (int hh = 0; hh < 2; hh++) {
            float m = rmx[mt][hh];
            m = fmaxf(m, __shfl_xor_sync(0xffffffffu, m, 1));
            m = fmaxf(m, __shfl_xor_sync(0xffffffffu, m, 2));
            if ((lane & 3) == 0)
                rs[wn * 128 + wm * 32 + mt * 16 + hh * 8 + (lane >> 2)] = m;
        }
    __syncthreads();
    if (tid < 128)
        rmax[(size_t)b * HW_ + n0 + tid] = fmaxf(rs[tid], rs[128 + tid]);
}

// ======================================================================
// pv_mma (fp16 1-pass): Y = softmax(S) · V -> fp16 Y.
// CTA = 64 rows x 256 cols, grid (64, 8), block 256 (2m x 4n), 2 CTAs/SM.
// k-chunk 32.  stage s @ s*29696: S fp32 [64][36] (9216B),
// V fp16 [256][40] (+9216, 20480B).  P fp16 [64][40] @59392 (5120B).
// rsum float[64] @64512.  Total 64768.
// Per chunk: wait(S,V) -> sync -> prefetch next -> exp-convert S->P (fp16,
// rowmax-subtracted, accumulate rowsum) -> sync -> fp16 MMA.
// ======================================================================
static constexpr int PV_STG  = 29696;
static constexpr int PV_P16  = 2 * PV_STG;      // 59392
static constexpr int PV_RS   = PV_P16 + 5120;   // 64512
static constexpr int PV_SMEM = PV_RS + 256;     // 64768

__global__ __launch_bounds__(256, 2) void pv_mma_kernel(
    const float* __restrict__ Sf, const __half* __restrict__ V16,
    const float* __restrict__ rmax, __half* __restrict__ Yf)
{
    extern __shared__ char smem[];
    const uint32_t sb = smem_to_u32(smem);
    const int tid = threadIdx.x, lane = tid & 31, wid = tid >> 5;
    const int wm = wid & 1, wn = wid >> 1;
    const int b = blockIdx.y, n0 = blockIdx.x * 64;

    auto prefetch = [&](int c) {
        uint32_t base = sb + (c & 1) * PV_STG;
        const float* gs = Sf + ((size_t)b * HW_ + n0) * PHW_ + c * 32;
        for (int idx = tid; idx < 512; idx += 256) {    // 64 rows x 8 cp16
            int r = idx >> 3, u = idx & 7;
            cp16(base + (uint32_t)((r * 36 + u * 4) * 4), gs + (size_t)r * PHW_ + u * 4);
        }
        const __half* gv = V16 + (size_t)b * C_ * PHW_ + c * 32;
        for (int idx = tid; idx < 1024; idx += 256) {   // 256 rows x 4 cp16
            int r = idx >> 2, u = idx & 3;
            cp16(base + 9216 + (uint32_t)((r * 40 + u * 8) * 2), gv + (size_t)r * PHW_ + u * 8);
        }
        CP_COMMIT();
    };

    // each thread owns one row segment: row = tid>>2, cols u*8..u*8+7
    const int crow = tid >> 2, cu = tid & 3;
    const float rmx = rmax[(size_t)b * HW_ + n0 + crow];
    float rsum_loc = 0.f;

    float acc[2][8][4];
#pragma unroll
    for (int mt = 0; mt < 2; mt++)
#pragma unroll
        for (int nt = 0; nt < 8; nt++)
#pragma unroll
            for (int e = 0; e < 4; e++) acc[mt][nt][e] = 0.f;

    prefetch(0);
    for (int ck = 0; ck < 32; ck++) {
        CP_WAIT0();
        __syncthreads();                    // stage ck visible; P16 free
        if (ck + 1 < 32) prefetch(ck + 1);
        {   // exp-convert S -> P fp16
            const float* srow = (const float*)(smem + (ck & 1) * PV_STG) + crow * 36 + cu * 8;
            float4 s0 = *(const float4*)(srow);
            float4 s1 = *(const float4*)(srow + 4);
            float p0 = __expf(s0.x - rmx), p1 = __expf(s0.y - rmx);
            float p2 = __expf(s0.z - rmx), p3 = __expf(s0.w - rmx);
            float p4 = __expf(s1.x - rmx), p5 = __expf(s1.y - rmx);
            float p6 = __expf(s1.z - rmx), p7 = __expf(s1.w - rmx);
            rsum_loc += (p0 + p1 + p2 + p3) + (p4 + p5 + p6 + p7);
            __half2 h0 = __floats2half2_rn(p0, p1), h1 = __floats2half2_rn(p2, p3);
            __half2 h2 = __floats2half2_rn(p4, p5), h3 = __floats2half2_rn(p6, p7);
            uint4 pk;
            pk.x = *(uint32_t*)&h0; pk.y = *(uint32_t*)&h1;
            pk.z = *(uint32_t*)&h2; pk.w = *(uint32_t*)&h3;
            *(uint4*)(smem + PV_P16 + (crow * 40 + cu * 8) * 2) = pk;
        }
        __syncthreads();                    // P16 visible
        const uint32_t pb = sb + PV_P16;
        const uint32_t vb = sb + (ck & 1) * PV_STG + 9216;
#pragma unroll
        for (int ks = 0; ks < 2; ks++) {
            const int k0 = ks * 16;
            uint32_t a[2][4], bh[4][4];
            ldsm4(a[0], a_addrP(pb, wm * 32,      k0, lane, 40));
            ldsm4(a[1], a_addrP(pb, wm * 32 + 16, k0, lane, 40));
#pragma unroll
            for (int g = 0; g < 4; g++)
                ldsm4(bh[g], b_addrP(vb, wn * 64 + g * 16, k0, lane, 40));
#pragma unroll
            for (int g = 0; g < 4; g++)
#pragma unroll
                for (int mt = 0; mt < 2; mt++) {
                    mma16816h(acc[mt][g*2],   a[mt], bh[g][0], bh[g][1]);
                    mma16816h(acc[mt][g*2+1], a[mt], bh[g][2], bh[g][3]);
                }
        }
    }

    // rowsum reduce: quad (4 threads per row) then store
    {
        float s = rsum_loc;
        s += __shfl_xor_sync(0xffffffffu, s, 1);
        s += __shfl_xor_sync(0xffffffffu, s, 2);
        if (cu == 0) ((float*)(smem + PV_RS))[crow] = s;
    }
    __syncthreads();
    const float* rsArr = (const float*)(smem + PV_RS);

#pragma unroll
    for (int mt = 0; mt < 2; mt++) {
        const int rl = wm * 32 + mt * 16 + (lane >> 2);
        const int r0 = n0 + rl;
        const float i0 = 1.f / rsArr[rl];
        const float i1 = 1.f / rsArr[rl + 8];
#pragma unroll
        for (int nt = 0; nt < 8; nt++) {
            const int col = wn * 64 + nt * 8 + (lane & 3) * 2;
            __half2 p0 = __floats2half2_rn(acc[mt][nt][0] * i0, acc[mt][nt][1] * i0);
            __half2 p1 = __floats2half2_rn(acc[mt][nt][2] * i1, acc[mt][nt][3] * i1);
            *(__half2*)&Yf[((size_t)b * HW_ + r0) * C_ + col] = p0;
            *(__half2*)&Yf[((size_t)b * HW_ + r0 + 8) * C_ + col] = p1;
        }
    }
}

// ======================================================================
// final_mma (fp16 1-pass): unchanged from R12
// ======================================================================
static constexpr int FIN_STG  = 27648;
static constexpr int FIN_SMEM = 2 * FIN_STG;

__global__ __launch_bounds__(256, 2) void final_mma_kernel(
    const __half* __restrict__ Yf, const __half* __restrict__ Wf,
    const float* __restrict__ Wb,
    const float* __restrict__ gamma, const float* __restrict__ beta,
    const float* __restrict__ mean, const float* __restrict__ var,
    const float* __restrict__ x, float* __restrict__ out)
{
    extern __shared__ char smem[];
    const uint32_t sb = smem_to_u32(smem);
    float* sRes = (float*)smem;
    const int tid = threadIdx.x, lane = tid & 31, wid = tid >> 5;
    const int wm = wid & 3, wn = wid >> 2;
    const int b = blockIdx.z, pxt = blockIdx.y, oc0 = blockIdx.x * 64;

    auto prefetch = [&](int c) {
        uint32_t base = sb + (c & 1) * FIN_STG;
        const __half* gA = Yf + ((size_t)b * HW_ + pxt * 128) * C_ + c * 64;
        for (int idx = tid; idx < 1024; idx += 256) {
            int r = idx >> 3, u = idx & 7;
            cp16(base + (uint32_t)((r * 72 + u * 8) * 2), gA + (size_t)r * C_ + u * 8);
        }
        const __half* gB = Wf + (size_t)oc0 * 256 + c * 64;
        for (int idx = tid; idx < 512; idx += 256) {
            int r = idx >> 3, u = idx & 7;
            cp16(base + 18432 + (uint32_t)((r * 72 + u * 8) * 2), gB + (size_t)r * 256 + u * 8);
        }
        CP_COMMIT();
    };

    float acc[2][4][4];
#pragma unroll
    for (int mt = 0; mt < 2; mt++)
#pragma unroll
        for (int nt = 0; nt < 4; nt++)
#pragma unroll
            for (int e = 0; e < 4; e++) acc[mt][nt][e] = 0.f;

    prefetch(0);
    for (int ck = 0; ck < 4; ck++) {
        if (ck + 1 < 4) { prefetch(ck + 1); CP_WAIT1(); } else CP_WAIT0();
        __syncthreads();
        uint32_t base = sb + (ck & 1) * FIN_STG;
#pragma unroll
        for (int ks = 0; ks < 4; ks++) {
            const int k0 = ks * 16;
            uint32_t a[2][4], bb[2][4];
            ldsm4(a[0], a_addrP(base, wm * 32,      k0, lane, 72));
            ldsm4(a[1], a_addrP(base, wm * 32 + 16, k0, lane, 72));
            ldsm4(bb[0], b_addrP(base + 18432, wn * 32,      k0, lane, 72));
            ldsm4(bb[1], b_addrP(base + 18432, wn * 32 + 16, k0, lane, 72));
#pragma unroll
            for (int g = 0; g < 2; g++)
#pragma unroll
                for (int mt = 0; mt < 2; mt++) {
                    mma16816h(acc[mt][g*2],   a[mt], bb[g][0], bb[g][1]);
                    mma16816h(acc[mt][g*2+1], a[mt], bb[g][2], bb[g][3]);
                }
        }
        __syncthreads();
    }

#pragma unroll
    for (int mt = 0; mt < 2; mt++) {
        const int row = wm * 32 + mt * 16 + (lane >> 2);
#pragma unroll
        for (int nt = 0; nt < 4; nt++) {
            const int col = wn * 32 + nt * 8 + (lane & 3) * 2;
            sRes[row * 68 + col]       = acc[mt][nt][0];
            sRes[row * 68 + col + 1]   = acc[mt][nt][1];
            sRes[(row+8) * 68 + col]   = acc[mt][nt][2];
            sRes[(row+8) * 68 + col+1] = acc[mt][nt][3];
        }
    }
    __syncthreads();

    for (int t = tid; t < 128 * 64; t += 256) {
        int o = t >> 7, p = t & 127;
        int oc = oc0 + o;
        float scale = gamma[oc] * rsqrtf(var[oc] + EPS_);
        size_t gidx = ((size_t)b * C_ + oc) * HW_ + pxt * 128 + p;
        out[gidx] = (sRes[p * 68 + o] + Wb[oc] - mean[oc]) * scale + beta[oc] + x[gidx];
    }
}

// ======================================================================
extern "C" void kernel_launch(void* const* d_in, const int* in_sizes, int n_in,
                              void* d_out, int out_size)
{
    const float* x       = (const float*)d_in[0];
    const float* g_w     = (const float*)d_in[1];
    const float* g_b     = (const float*)d_in[2];
    const float* theta_w = (const float*)d_in[3];
    const float* theta_b = (const float*)d_in[4];
    const float* phi_w   = (const float*)d_in[5];
    const float* phi_b   = (const float*)d_in[6];
    const float* W_w     = (const float*)d_in[7];
    const float* W_b     = (const float*)d_in[8];
    const float* bn_g    = (const float*)d_in[9];
    const float* bn_b    = (const float*)d_in[10];
    const float* bn_m    = (const float*)d_in[11];
    const float* bn_v    = (const float*)d_in[12];
    float* out = (float*)d_out;

    __nv_bfloat16 *xh, *xl, *Wch, *Wcl, *Qh, *Ql, *Kh, *Kl;
    float *xf, *Wgf, *Sf, *rmx, *bc;
    __half *Wff, *V16, *Yf;
    cudaGetSymbolAddress((void**)&xh,  d_xh);
    cudaGetSymbolAddress((void**)&xl,  d_xl);
    cudaGetSymbolAddress((void**)&xf,  d_xf);
    cudaGetSymbolAddress((void**)&Wch, d_Wch);
    cudaGetSymbolAddress((void**)&Wcl, d_Wcl);
    cudaGetSymbolAddress((void**)&Wgf, d_Wgf);
    cudaGetSymbolAddress((void**)&bc,  d_bc);
    cudaGetSymbolAddress((void**)&Wff, d_Wff);
    cudaGetSymbolAddress((void**)&Qh,  d_Qh);
    cudaGetSymbolAddress((void**)&Ql,  d_Ql);
    cudaGetSymbolAddress((void**)&Kh,  d_Kh);
    cudaGetSymbolAddress((void**)&Kl,  d_Kl);
    cudaGetSymbolAddress((void**)&V16, d_V16);
    cudaGetSymbolAddress((void**)&Sf,  d_Sf);
    cudaGetSymbolAddress((void**)&rmx, d_rmax);
    cudaGetSymbolAddress((void**)&Yf,  d_Yf);

    cudaFuncSetAttribute(conv_g_kernel,    cudaFuncAttributeMaxDynamicSharedMemorySize, CG_SMEM);
    cudaFuncSetAttribute(conv_qk_kernel,   cudaFuncAttributeMaxDynamicSharedMemorySize, CONV_SMEM);
    cudaFuncSetAttribute(qk_mma_kernel,    cudaFuncAttributeMaxDynamicSharedMemorySize, QK_SMEM);
    cudaFuncSetAttribute(pv_mma_kernel,    cudaFuncAttributeMaxDynamicSharedMemorySize, PV_SMEM);
    cudaFuncSetAttribute(final_mma_kernel, cudaFuncAttributeMaxDynamicSharedMemorySize, FIN_SMEM);

    xsplit_kernel<<<BB * C_ * HW_ / 1024, 256>>>(x, xh, xl, xf);
    wpack_conv_kernel<<<384, 256>>>(g_w, g_b, theta_w, theta_b, phi_w, phi_b,
                                    Wch, Wcl, Wgf, bc);
    wpack_final_kernel<<<256, 256>>>(W_w, Wff);
    conv_g_kernel<<<dim3(4, 32, BB), 256, CG_SMEM>>>(xf, Wgf, bc, V16);
    conv_qk_kernel<<<dim3(2, 32, BB), 256, CONV_SMEM>>>(xh, xl, Wch, Wcl, bc,
                                                        Qh, Ql, Kh, Kl);
    qk_mma_kernel<<<dim3(32, BB), 256, QK_SMEM>>>(Qh, Ql, Kh, Kl, Sf, rmx);
    pv_mma_kernel<<<dim3(64, BB), 256, PV_SMEM>>>(Sf, V16, rmx, Yf);
    final_mma_kernel<<<dim3(4, 32, BB), 256, FIN_SMEM>>>(Yf, Wff, W_b,
                                                         bn_g, bn_b, bn_m, bn_v, x, out);
}

// round 15
// speedup vs baseline: 2.3024x; 1.0817x over previous
#include <cuda_runtime.h>
#include <cuda_bf16.h>
#include <cuda_fp16.h>
#include <cstdint>

#define BB 8
#define C_ 256
#define HW_ 4096
#define PHW_ 1024
#define EPS_ 1e-5f

// ---------------- helpers ----------------
__device__ __forceinline__ uint32_t smem_to_u32(const void* p) {
    uint32_t a;
    asm("{ .reg .u64 t; cvta.to.shared.u64 t, %1; cvt.u32.u64 %0, t; }" : "=r"(a) : "l"(p));
    return a;
}
__device__ __forceinline__ void ldsm4(uint32_t* r, uint32_t addr) {
    asm volatile("ldmatrix.sync.aligned.m8n8.x4.shared.b16 {%0,%1,%2,%3}, [%4];"
        : "=r"(r[0]), "=r"(r[1]), "=r"(r[2]), "=r"(r[3]) : "r"(addr));
}
__device__ __forceinline__ void ldsm4t(uint32_t* r, uint32_t addr) {
    asm volatile("ldmatrix.sync.aligned.m8n8.x4.trans.shared.b16 {%0,%1,%2,%3}, [%4];"
        : "=r"(r[0]), "=r"(r[1]), "=r"(r[2]), "=r"(r[3]) : "r"(addr));
}
__device__ __forceinline__ void mma16816(float* d, const uint32_t* a, uint32_t b0, uint32_t b1) {
    asm volatile("mma.sync.aligned.m16n8k16.row.col.f32.bf16.bf16.f32 "
        "{%0,%1,%2,%3}, {%4,%5,%6,%7}, {%8,%9}, {%0,%1,%2,%3};"
        : "+f"(d[0]), "+f"(d[1]), "+f"(d[2]), "+f"(d[3])
        : "r"(a[0]), "r"(a[1]), "r"(a[2]), "r"(a[3]), "r"(b0), "r"(b1));
}
__device__ __forceinline__ void mma16816h(float* d, const uint32_t* a, uint32_t b0, uint32_t b1) {
    asm volatile("mma.sync.aligned.m16n8k16.row.col.f32.f16.f16.f32 "
        "{%0,%1,%2,%3}, {%4,%5,%6,%7}, {%8,%9}, {%0,%1,%2,%3};"
        : "+f"(d[0]), "+f"(d[1]), "+f"(d[2]), "+f"(d[3])
        : "r"(a[0]), "r"(a[1]), "r"(a[2]), "r"(a[3]), "r"(b0), "r"(b1));
}
__device__ __forceinline__ uint32_t lds32(uint32_t addr) {
    uint32_t v;
    asm volatile("ld.shared.b32 %0, [%1];" : "=r"(v) : "r"(addr));
    return v;
}
__device__ __forceinline__ void cp16(uint32_t s, const void* g) {
    asm volatile("cp.async.cg.shared.global [%0], [%1], 16;" :: "r"(s), "l"(g));
}
#define CP_COMMIT() asm volatile("cp.async.commit_group;" ::: "memory")
#define CP_WAIT0()  asm volatile("cp.async.wait_group 0;" ::: "memory")
#define CP_WAIT1()  asm volatile("cp.async.wait_group 1;" ::: "memory")

__device__ __forceinline__ void split_bf16(float v, __nv_bfloat16& h, __nv_bfloat16& l) {
    h = __float2bfloat16(v);
    l = __float2bfloat16(v - __bfloat162float(h));
}
__device__ __forceinline__ void split2(float a, float b, uint32_t& hh, uint32_t& ll) {
    __nv_bfloat16 ha, la, hb, lb;
    split_bf16(a, ha, la); split_bf16(b, hb, lb);
    hh = (uint32_t)__bfloat16_as_ushort(ha) | ((uint32_t)__bfloat16_as_ushort(hb) << 16);
    ll = (uint32_t)__bfloat16_as_ushort(la) | ((uint32_t)__bfloat16_as_ushort(lb) << 16);
}

// A-fragment (m16k16) from [m][k] row-major smem, pitch P elems (16-bit)
__device__ __forceinline__ uint32_t a_addrP(uint32_t base, int row0, int k0, int lane, int P) {
    int r = row0 + (lane & 15), c = k0 + ((lane >> 4) << 3);
    return base + (uint32_t)((r * P + c) * 2);
}
// A-fragment (m16k16) from [k][m] storage via trans-ldmatrix, pitch P (16-bit)
__device__ __forceinline__ uint32_t at_addr(uint32_t base, int m0, int k0, int lane, int P) {
    int t = lane >> 3;
    int m = m0 + ((t & 1) << 3);
    int k = k0 + ((t >> 1) << 3) + (lane & 7);
    return base + (uint32_t)((k * P + m) * 2);
}
// B-fragment x4 (two n8k16 tiles) from [n][k] row-major smem, pitch P (16-bit)
__device__ __forceinline__ uint32_t b_addrP(uint32_t base, int n0, int k0, int lane, int P) {
    int r = n0 + (lane & 7) + ((lane >> 4) << 3), c = k0 + (((lane >> 3) & 1) << 3);
    return base + (uint32_t)((r * P + c) * 2);
}

// ---------------- scratch ----------------
__device__ __nv_bfloat16 d_xh[BB*C_*HW_], d_xl[BB*C_*HW_];
__device__ __half        d_x16[BB*C_*HW_];                 // x fp16
__device__ __nv_bfloat16 d_Wch[384*256],  d_Wcl[384*256];
__device__ __half        d_Wg16[256*256];                  // g weights fp16
__device__ float         d_bc[384];
__device__ __half        d_Wff[256*256];
__device__ __nv_bfloat16 d_Qh[BB*HW_*64],  d_Ql[BB*HW_*64];
__device__ __nv_bfloat16 d_Kh[BB*PHW_*64], d_Kl[BB*PHW_*64];
__device__ __half        d_V16[BB*C_*PHW_];
__device__ float         d_Sf[(size_t)BB*HW_*PHW_];
__device__ float         d_rmax[BB*HW_];
__device__ __half        d_Yf[BB*HW_*C_];

// ======================================================================
// xsplit + weight packing
// ======================================================================
__global__ __launch_bounds__(256) void xsplit_kernel(
    const float* __restrict__ x, __nv_bfloat16* __restrict__ xh,
    __nv_bfloat16* __restrict__ xl, __half* __restrict__ x16)
{
    size_t i = ((size_t)blockIdx.x * 256 + threadIdx.x) * 4;
    float4 v = *(const float4*)(x + i);
    uint32_t h0, l0, h1, l1;
    split2(v.x, v.y, h0, l0);
    split2(v.z, v.w, h1, l1);
    *(uint2*)(xh + i) = make_uint2(h0, h1);
    *(uint2*)(xl + i) = make_uint2(l0, l1);
    __half2 f0 = __floats2half2_rn(v.x, v.y);
    __half2 f1 = __floats2half2_rn(v.z, v.w);
    *(uint2*)(x16 + i) = make_uint2(*(uint32_t*)&f0, *(uint32_t*)&f1);
}

__global__ void wpack_conv_kernel(
    const float* __restrict__ g_w, const float* __restrict__ g_b,
    const float* __restrict__ th_w, const float* __restrict__ th_b,
    const float* __restrict__ ph_w, const float* __restrict__ ph_b,
    __nv_bfloat16* __restrict__ Wh, __nv_bfloat16* __restrict__ Wl,
    __half* __restrict__ Wg16, float* __restrict__ bc)
{
    int oc = blockIdx.x, k = threadIdx.x;
    float v;
    if (oc < 256)       v = g_w[oc * 256 + k];
    else if (oc < 320)  v = (k < 64) ? th_w[(oc - 256) * 64 + k] : 0.f;
    else                v = (k >= 64) ? ph_w[(oc - 320) * 192 + (k - 64)] : 0.f;
    __nv_bfloat16 h, l; split_bf16(v, h, l);
    Wh[oc * 256 + k] = h; Wl[oc * 256 + k] = l;
    if (oc < 256) Wg16[oc * 256 + k] = __float2half_rn(v);
    if (k == 0)
        bc[oc] = (oc < 256) ? g_b[oc] : (oc < 320) ? th_b[oc - 256] : ph_b[oc - 320];
}

__global__ void wpack_final_kernel(const float* __restrict__ w, __half* __restrict__ Wf)
{
    int i = blockIdx.x * 256 + threadIdx.x;
    Wf[i] = __float2half_rn(w[i]);
}

// ======================================================================
// conv_g (fp16 1-pass): V = pool(g_conv(x)) -> fp16.
// CTA = 128 px x 64 oc, grid (4, 32, 8), block 256 (4m x 2n), 2 CTAs/SM.
// stage s @ s*26624: X fp16 [64c][136] (17408B), W fp16 [64oc][72] (+17408).
// sRes [128][68] fp32 union at 0.
// ======================================================================
static constexpr int CG_STG  = 26624;
static constexpr int CG_SMEM = 2 * CG_STG;

__global__ __launch_bounds__(256, 2) void conv_g_kernel(
    const __half* __restrict__ x16, const __half* __restrict__ Wg,
    const float* __restrict__ bc, __half* __restrict__ V16)
{
    extern __shared__ char smem[];
    const uint32_t sb = smem_to_u32(smem);
    float* sRes = (float*)smem;
    const int tid = threadIdx.x, lane = tid & 31, wid = tid >> 5;
    const int wm = wid & 3, wn = wid >> 2;
    const int b = blockIdx.z, pxt = blockIdx.y, oc0 = blockIdx.x * 64;

    auto prefetch = [&](int c) {
        uint32_t base = sb + (c & 1) * CG_STG;
        const __half* gx = x16 + ((size_t)b * C_ + c * 64) * HW_ + pxt * 128;
        for (int idx = tid; idx < 1024; idx += 256) {   // 64 rows x 16 cp16
            int r = idx >> 4, u = idx & 15;
            cp16(base + (uint32_t)((r * 136 + u * 8) * 2), gx + (size_t)r * HW_ + u * 8);
        }
        const __half* gw = Wg + (size_t)oc0 * 256 + c * 64;
        for (int idx = tid; idx < 512; idx += 256) {    // 64 rows x 8 cp16
            int r = idx >> 3, u = idx & 7;
            cp16(base + 17408 + (uint32_t)((r * 72 + u * 8) * 2), gw + (size_t)r * 256 + u * 8);
        }
        CP_COMMIT();
    };

    float acc[2][4][4];
#pragma unroll
    for (int mt = 0; mt < 2; mt++)
#pragma unroll
        for (int nt = 0; nt < 4; nt++)
#pragma unroll
            for (int e = 0; e < 4; e++) acc[mt][nt][e] = 0.f;

    prefetch(0);
    for (int ck = 0; ck < 4; ck++) {
        if (ck + 1 < 4) { prefetch(ck + 1); CP_WAIT1(); } else CP_WAIT0();
        __syncthreads();
        const uint32_t xb = sb + (ck & 1) * CG_STG;
        const uint32_t wb = xb + 17408;
#pragma unroll
        for (int ks = 0; ks < 4; ks++) {
            const int k0 = ks * 16;
            uint32_t a[2][4], bb[2][4];
            ldsm4t(a[0], at_addr(xb, wm * 32,      k0, lane, 136));
            ldsm4t(a[1], at_addr(xb, wm * 32 + 16, k0, lane, 136));
            ldsm4(bb[0], b_addrP(wb, wn * 32,      k0, lane, 72));
            ldsm4(bb[1], b_addrP(wb, wn * 32 + 16, k0, lane, 72));
#pragma unroll
            for (int g = 0; g < 2; g++)
#pragma unroll
                for (int mt = 0; mt < 2; mt++) {
                    mma16816h(acc[mt][g*2],   a[mt], bb[g][0], bb[g][1]);
                    mma16816h(acc[mt][g*2+1], a[mt], bb[g][2], bb[g][3]);
                }
        }
        __syncthreads();
    }

#pragma unroll
    for (int mt = 0; mt < 2; mt++) {
        const int row = wm * 32 + mt * 16 + (lane >> 2);
#pragma unroll
        for (int nt = 0; nt < 4; nt++) {
            const int col = wn * 32 + nt * 8 + (lane & 3) * 2;
            sRes[row * 68 + col]       = acc[mt][nt][0];
            sRes[row * 68 + col + 1]   = acc[mt][nt][1];
            sRes[(row+8) * 68 + col]   = acc[mt][nt][2];
            sRes[(row+8) * 68 + col+1] = acc[mt][nt][3];
        }
    }
    __syncthreads();

    for (int t = tid; t < 32 * 64; t += 256) {
        int pw = t >> 6, o = t & 63, oc = oc0 + o;
        float v = fmaxf(fmaxf(sRes[(2*pw)*68 + o], sRes[(2*pw+1)*68 + o]),
                        fmaxf(sRes[(64+2*pw)*68 + o], sRes[(65+2*pw)*68 + o]))
                  + bc[oc];
        size_t oidx = ((size_t)b * C_ + oc) * PHW_ + pxt * 32 + pw;
        V16[oidx] = __float2half_rn(v);
    }
}

// ======================================================================
// conv_qk (bf16 3-pass): theta + phi convs (unchanged)
// ======================================================================
static constexpr int CONV_STG  = 53248;
static constexpr int CONV_SMEM = 2 * CONV_STG;

__global__ __launch_bounds__(256, 2) void conv_qk_kernel(
    const __nv_bfloat16* __restrict__ xh, const __nv_bfloat16* __restrict__ xl,
    const __nv_bfloat16* __restrict__ Wh, const __nv_bfloat16* __restrict__ Wl,
    const float* __restrict__ bc,
    __nv_bfloat16* __restrict__ Qh, __nv_bfloat16* __restrict__ Ql,
    __nv_bfloat16* __restrict__ Kh, __nv_bfloat16* __restrict__ Kl)
{
    extern __shared__ char smem[];
    const uint32_t sb = smem_to_u32(smem);
    float* sRes = (float*)smem;
    const int tid = threadIdx.x, lane = tid & 31, wid = tid >> 5;
    const int wm = wid & 3, wn = wid >> 2;
    const int b = blockIdx.z, pxt = blockIdx.y, oc0 = 256 + blockIdx.x * 64;

    auto prefetch = [&](int c) {
        uint32_t base = sb + (c & 1) * CONV_STG;
        const __nv_bfloat16* gxh = xh + ((size_t)b * C_ + c * 64) * HW_ + pxt * 128;
        const __nv_bfloat16* gxl = xl + ((size_t)b * C_ + c * 64) * HW_ + pxt * 128;
        for (int idx = tid; idx < 1024; idx += 256) {
            int r = idx >> 4, u = idx & 15;
            uint32_t so = (uint32_t)((r * 136 + u * 8) * 2);
            cp16(base + so,         gxh + (size_t)r * HW_ + u * 8);
            cp16(base + 17408 + so, gxl + (size_t)r * HW_ + u * 8);
        }
        const __nv_bfloat16* gwh = Wh + (size_t)oc0 * 256 + c * 64;
        const __nv_bfloat16* gwl = Wl + (size_t)oc0 * 256 + c * 64;
        for (int idx = tid; idx < 512; idx += 256) {
            int r = idx >> 3, u = idx & 7;
            uint32_t so = (uint32_t)((r * 72 + u * 8) * 2);
            cp16(base + 34816 + so, gwh + (size_t)r * 256 + u * 8);
            cp16(base + 44032 + so, gwl + (size_t)r * 256 + u * 8);
        }
        CP_COMMIT();
    };

    float acc[2][4][4];
#pragma unroll
    for (int mt = 0; mt < 2; mt++)
#pragma unroll
        for (int nt = 0; nt < 4; nt++)
#pragma unroll
            for (int e = 0; e < 4; e++) acc[mt][nt][e] = 0.f;

    prefetch(0);
    for (int ck = 0; ck < 4; ck++) {
        if (ck + 1 < 4) { prefetch(ck + 1); CP_WAIT1(); } else CP_WAIT0();
        __syncthreads();
        uint32_t base = sb + (ck & 1) * CONV_STG;
#pragma unroll
        for (int ks = 0; ks < 4; ks++) {
            const int k0 = ks * 16;
            uint32_t ah[2][4], al[2][4], bh[2][4], bl[2][4];
            ldsm4t(ah[0], at_addr(base, wm * 32,      k0, lane, 136));
            ldsm4t(ah[1], at_addr(base, wm * 32 + 16, k0, lane, 136));
            ldsm4(bh[0], b_addrP(base + 34816, wn * 32,      k0, lane, 72));
            ldsm4(bh[1], b_addrP(base + 34816, wn * 32 + 16, k0, lane, 72));
#pragma unroll
            for (int g = 0; g < 2; g++)
#pragma unroll
                for (int mt = 0; mt < 2; mt++) {
                    mma16816(acc[mt][g*2],   ah[mt], bh[g][0], bh[g][1]);
                    mma16816(acc[mt][g*2+1], ah[mt], bh[g][2], bh[g][3]);
                }
            ldsm4(bl[0], b_addrP(base + 44032, wn * 32,      k0, lane, 72));
            ldsm4(bl[1], b_addrP(base + 44032, wn * 32 + 16, k0, lane, 72));
#pragma unroll
            for (int g = 0; g < 2; g++)
#pragma unroll
                for (int mt = 0; mt < 2; mt++) {
                    mma16816(acc[mt][g*2],   ah[mt], bl[g][0], bl[g][1]);
                    mma16816(acc[mt][g*2+1], ah[mt], bl[g][2], bl[g][3]);
                }
            ldsm4t(al[0], at_addr(base + 17408, wm * 32,      k0, lane, 136));
            ldsm4t(al[1], at_addr(base + 17408, wm * 32 + 16, k0, lane, 136));
#pragma unroll
            for (int g = 0; g < 2; g++)
#pragma unroll
                for (int mt = 0; mt < 2; mt++) {
                    mma16816(acc[mt][g*2],   al[mt], bh[g][0], bh[g][1]);
                    mma16816(acc[mt][g*2+1], al[mt], bh[g][2], bh[g][3]);
                }
        }
        __syncthreads();
    }

#pragma unroll
    for (int mt = 0; mt < 2; mt++) {
        const int row = wm * 32 + mt * 16 + (lane >> 2);
#pragma unroll
        for (int nt = 0; nt < 4; nt++) {
            const int col = wn * 32 + nt * 8 + (lane & 3) * 2;
            sRes[row * 68 + col]       = acc[mt][nt][0];
            sRes[row * 68 + col + 1]   = acc[mt][nt][1];
            sRes[(row+8) * 68 + col]   = acc[mt][nt][2];
            sRes[(row+8) * 68 + col+1] = acc[mt][nt][3];
        }
    }
    __syncthreads();

    if (blockIdx.x == 0) {
        for (int t = tid; t < 128 * 64; t += 256) {
            int p = t >> 6, o = t & 63;
            float v = sRes[p * 68 + o] + bc[256 + o];
            __nv_bfloat16 h, l; split_bf16(v, h, l);
            size_t oidx = ((size_t)b * HW_ + pxt * 128 + p) * 64 + o;
            Qh[oidx] = h; Ql[oidx] = l;
        }
    } else {
        for (int t = tid; t < 32 * 64; t += 256) {
            int pw = t >> 6, o = t & 63;
            float v = fmaxf(fmaxf(sRes[(2*pw)*68 + o], sRes[(2*pw+1)*68 + o]),
                            fmaxf(sRes[(64+2*pw)*68 + o], sRes[(65+2*pw)*68 + o]))
                      + bc[320 + o];
            __nv_bfloat16 h, l; split_bf16(v, h, l);
            size_t oidx = ((size_t)b * PHW_ + pxt * 32 + pw) * 64 + o;
            Kh[oidx] = h; Kl[oidx] = l;
        }
    }
}

// ======================================================================
// qk_mma: split-bf16 3-pass. Stores RAW S fp32 + per-row max. (unchanged)
// ======================================================================
static constexpr int QK_SMEM = 110592 + 1024;

__global__ __launch_bounds__(256, 2) void qk_mma_kernel(
    const __nv_bfloat16* __restrict__ Qh, const __nv_bfloat16* __restrict__ Ql,
    const __nv_bfloat16* __restrict__ Kh, const __nv_bfloat16* __restrict__ Kl,
    float* __restrict__ Sf, float* __restrict__ rmax)
{
    extern __shared__ char smem[];
    const uint32_t sb = smem_to_u32(smem);
    __nv_bfloat16* sQ = (__nv_bfloat16*)smem;
    float* rs = (float*)(smem + 110592);
    const int tid = threadIdx.x, lane = tid & 31, wid = tid >> 5;
    const int wm = wid & 3, wn = wid >> 2;
    const int b = blockIdx.y, n0 = blockIdx.x * 128;

    auto prefetch = [&](int c) {
        uint32_t base = sb + 36864 + (c & 1) * 36864;
        const __nv_bfloat16* gkh = Kh + ((size_t)b * PHW_ + c * 128) * 64;
        const __nv_bfloat16* gkl = Kl + ((size_t)b * PHW_ + c * 128) * 64;
        for (int idx = tid; idx < 1024; idx += 256) {
            int r = idx >> 3, u = idx & 7;
            uint32_t so = (uint32_t)((r * 72 + u * 8) * 2);
            cp16(base + so,         gkh + r * 64 + u * 8);
            cp16(base + 18432 + so, gkl + r * 64 + u * 8);
        }
        CP_COMMIT();
    };

    prefetch(0);
    {
        const __nv_bfloat16* gqh = Qh + ((size_t)b * HW_ + n0) * 64;
        const __nv_bfloat16* gql = Ql + ((size_t)b * HW_ + n0) * 64;
        for (int idx = tid; idx < 1024; idx += 256) {
            int r = idx >> 3, u = idx & 7;
            *(uint4*)(sQ + r * 72 + u * 8)        = *(const uint4*)(gqh + r * 64 + u * 8);
            *(uint4*)(sQ + 9216 + r * 72 + u * 8) = *(const uint4*)(gql + r * 64 + u * 8);
        }
    }

    float rmx[2][2] = {{-1e30f, -1e30f}, {-1e30f, -1e30f}};

    for (int ck = 0; ck < 8; ck++) {
        const int m0 = ck * 128;
        if (ck + 1 < 8) { prefetch(ck + 1); CP_WAIT1(); } else CP_WAIT0();
        __syncthreads();
        uint32_t kb = sb + 36864 + (ck & 1) * 36864;

        float acc[2][8][4];
#pragma unroll
        for (int mt = 0; mt < 2; mt++)
#pragma unroll
            for (int nt = 0; nt < 8; nt++)
#pragma unroll
                for (int e = 0; e < 4; e++) acc[mt][nt][e] = 0.f;

#pragma unroll
        for (int ks = 0; ks < 4; ks++) {
            const int k0 = ks * 16;
            uint32_t ah[2][4], al[2][4];
            ldsm4(ah[0], a_addrP(sb,         wm * 32,      k0, lane, 72));
            ldsm4(ah[1], a_addrP(sb,         wm * 32 + 16, k0, lane, 72));
            ldsm4(al[0], a_addrP(sb + 18432, wm * 32,      k0, lane, 72));
            ldsm4(al[1], a_addrP(sb + 18432, wm * 32 + 16, k0, lane, 72));
#pragma unroll
            for (int g = 0; g < 4; g++) {
                uint32_t bh[4], bl[4];
                ldsm4(bh, b_addrP(kb,         wn * 64 + g * 16, k0, lane, 72));
                ldsm4(bl, b_addrP(kb + 18432, wn * 64 + g * 16, k0, lane, 72));
#pragma unroll
                for (int mt = 0; mt < 2; mt++) {
                    mma16816(acc[mt][g*2],   ah[mt], bh[0], bh[1]);
                    mma16816(acc[mt][g*2+1], ah[mt], bh[2], bh[3]);
                }
#pragma unroll
                for (int mt = 0; mt < 2; mt++) {
                    mma16816(acc[mt][g*2],   ah[mt], bl[0], bl[1]);
                    mma16816(acc[mt][g*2+1], ah[mt], bl[2], bl[3]);
                }
#pragma unroll
                for (int mt = 0; mt < 2; mt++) {
                    mma16816(acc[mt][g*2],   al[mt], bh[0], bh[1]);
                    mma16816(acc[mt][g*2+1], al[mt], bh[2], bh[3]);
                }
            }
        }

#pragma unroll
        for (int mt = 0; mt < 2; mt++) {
            const int row = n0 + wm * 32 + mt * 16 + (lane >> 2);
#pragma unroll
            for (int nt = 0; nt < 8; nt++) {
                float s0 = acc[mt][nt][0], s1 = acc[mt][nt][1];
                float s2 = acc[mt][nt][2], s3 = acc[mt][nt][3];
                rmx[mt][0] = fmaxf(rmx[mt][0], fmaxf(s0, s1));
                rmx[mt][1] = fmaxf(rmx[mt][1], fmaxf(s2, s3));
                const int col = m0 + wn * 64 + nt * 8 + (lane & 3) * 2;
                *(float2*)&Sf[((size_t)b * HW_ + row) * PHW_ + col] = make_float2(s0, s1);
                *(float2*)&Sf[((size_t)b * HW_ + row + 8) * PHW_ + col] = make_float2(s2, s3);
            }
        }
        __syncthreads();
    }

#pragma unroll
    for (int mt = 0; mt < 2; mt++)
#pragma unroll
        for (int hh = 0; hh < 2; hh++) {
            float m = rmx[mt][hh];
            m = fmaxf(m, __shfl_xor_sync(0xffffffffu, m, 1));
            m = fmaxf(m, __shfl_xor_sync(0xffffffffu, m, 2));
            if ((lane & 3) == 0)
                rs[wn * 128 + wm * 32 + mt * 16 + hh * 8 + (lane >> 2)] = m;
        }
    __syncthreads();
    if (tid < 128)
        rmax[(size_t)b * HW_ + n0 + tid] = fmaxf(rs[tid], rs[128 + tid]);
}

// ======================================================================
// pv_mma (fp16 1-pass): unchanged from R13
// ======================================================================
static constexpr int PV_STG  = 29696;
static constexpr int PV_P16  = 2 * PV_STG;
static constexpr int PV_RS   = PV_P16 + 5120;
static constexpr int PV_SMEM = PV_RS + 256;

__global__ __launch_bounds__(256, 2) void pv_mma_kernel(
    const float* __restrict__ Sf, const __half* __restrict__ V16,
    const float* __restrict__ rmax, __half* __restrict__ Yf)
{
    extern __shared__ char smem[];
    const uint32_t sb = smem_to_u32(smem);
    const int tid = threadIdx.x, lane = tid & 31, wid = tid >> 5;
    const int wm = wid & 1, wn = wid >> 1;
    const int b = blockIdx.y, n0 = blockIdx.x * 64;

    auto prefetch = [&](int c) {
        uint32_t base = sb + (c & 1) * PV_STG;
        const float* gs = Sf + ((size_t)b * HW_ + n0) * PHW_ + c * 32;
        for (int idx = tid; idx < 512; idx += 256) {
            int r = idx >> 3, u = idx & 7;
            cp16(base + (uint32_t)((r * 36 + u * 4) * 4), gs + (size_t)r * PHW_ + u * 4);
        }
        const __half* gv = V16 + (size_t)b * C_ * PHW_ + c * 32;
        for (int idx = tid; idx < 1024; idx += 256) {
            int r = idx >> 2, u = idx & 3;
            cp16(base + 9216 + (uint32_t)((r * 40 + u * 8) * 2), gv + (size_t)r * PHW_ + u * 8);
        }
        CP_COMMIT();
    };

    const int crow = tid >> 2, cu = tid & 3;
    const float rmx = rmax[(size_t)b * HW_ + n0 + crow];
    float rsum_loc = 0.f;

    float acc[2][8][4];
#pragma unroll
    for (int mt = 0; mt < 2; mt++)
#pragma unroll
        for (int nt = 0; nt < 8; nt++)
#pragma unroll
            for (int e = 0; e < 4; e++) acc[mt][nt][e] = 0.f;

    prefetch(0);
    for (int ck = 0; ck < 32; ck++) {
        CP_WAIT0();
        __syncthreads();
        if (ck + 1 < 32) prefetch(ck + 1);
        {
            const float* srow = (const float*)(smem + (ck & 1) * PV_STG) + crow * 36 + cu * 8;
            float4 s0 = *(const float4*)(srow);
            float4 s1 = *(const float4*)(srow + 4);
            float p0 = __expf(s0.x - rmx), p1 = __expf(s0.y - rmx);
            float p2 = __expf(s0.z - rmx), p3 = __expf(s0.w - rmx);
            float p4 = __expf(s1.x - rmx), p5 = __expf(s1.y - rmx);
            float p6 = __expf(s1.z - rmx), p7 = __expf(s1.w - rmx);
            rsum_loc += (p0 + p1 + p2 + p3) + (p4 + p5 + p6 + p7);
            __half2 h0 = __floats2half2_rn(p0, p1), h1 = __floats2half2_rn(p2, p3);
            __half2 h2 = __floats2half2_rn(p4, p5), h3 = __floats2half2_rn(p6, p7);
            uint4 pk;
            pk.x = *(uint32_t*)&h0; pk.y = *(uint32_t*)&h1;
            pk.z = *(uint32_t*)&h2; pk.w = *(uint32_t*)&h3;
            *(uint4*)(smem + PV_P16 + (crow * 40 + cu * 8) * 2) = pk;
        }
        __syncthreads();
        const uint32_t pb = sb + PV_P16;
        const uint32_t vb = sb + (ck & 1) * PV_STG + 9216;
#pragma unroll
        for (int ks = 0; ks < 2; ks++) {
            const int k0 = ks * 16;
            uint32_t a[2][4], bh[4][4];
            ldsm4(a[0], a_addrP(pb, wm * 32,      k0, lane, 40));
            ldsm4(a[1], a_addrP(pb, wm * 32 + 16, k0, lane, 40));
#pragma unroll
            for (int g = 0; g < 4; g++)
                ldsm4(bh[g], b_addrP(vb, wn * 64 + g * 16, k0, lane, 40));
#pragma unroll
            for (int g = 0; g < 4; g++)
#pragma unroll
                for (int mt = 0; mt < 2; mt++) {
                    mma16816h(acc[mt][g*2],   a[mt], bh[g][0], bh[g][1]);
                    mma16816h(acc[mt][g*2+1], a[mt], bh[g][2], bh[g][3]);
                }
        }
    }

    {
        float s = rsum_loc;
        s += __shfl_xor_sync(0xffffffffu, s, 1);
        s += __shfl_xor_sync(0xffffffffu, s, 2);
        if (cu == 0) ((float*)(smem + PV_RS))[crow] = s;
    }
    __syncthreads();
    const float* rsArr = (const float*)(smem + PV_RS);

#pragma unroll
    for (int mt = 0; mt < 2; mt++) {
        const int rl = wm * 32 + mt * 16 + (lane >> 2);
        const int r0 = n0 + rl;
        const float i0 = 1.f / rsArr[rl];
        const float i1 = 1.f / rsArr[rl + 8];
#pragma unroll
        for (int nt = 0; nt < 8; nt++) {
            const int col = wn * 64 + nt * 8 + (lane & 3) * 2;
            __half2 p0 = __floats2half2_rn(acc[mt][nt][0] * i0, acc[mt][nt][1] * i0);
            __half2 p1 = __floats2half2_rn(acc[mt][nt][2] * i1, acc[mt][nt][3] * i1);
            *(__half2*)&Yf[((size_t)b * HW_ + r0) * C_ + col] = p0;
            *(__half2*)&Yf[((size_t)b * HW_ + r0 + 8) * C_ + col] = p1;
        }
    }
}

// ======================================================================
// final_mma (fp16 1-pass): unchanged
// ======================================================================
static constexpr int FIN_STG  = 27648;
static constexpr int FIN_SMEM = 2 * FIN_STG;

__global__ __launch_bounds__(256, 2) void final_mma_kernel(
    const __half* __restrict__ Yf, const __half* __restrict__ Wf,
    const float* __restrict__ Wb,
    const float* __restrict__ gamma, const float* __restrict__ beta,
    const float* __restrict__ mean, const float* __restrict__ var,
    const float* __restrict__ x, float* __restrict__ out)
{
    extern __shared__ char smem[];
    const uint32_t sb = smem_to_u32(smem);
    float* sRes = (float*)smem;
    const int tid = threadIdx.x, lane = tid & 31, wid = tid >> 5;
    const int wm = wid & 3, wn = wid >> 2;
    const int b = blockIdx.z, pxt = blockIdx.y, oc0 = blockIdx.x * 64;

    auto prefetch = [&](int c) {
        uint32_t base = sb + (c & 1) * FIN_STG;
        const __half* gA = Yf + ((size_t)b * HW_ + pxt * 128) * C_ + c * 64;
        for (int idx = tid; idx < 1024; idx += 256) {
            int r = idx >> 3, u = idx & 7;
            cp16(base + (uint32_t)((r * 72 + u * 8) * 2), gA + (size_t)r * C_ + u * 8);
        }
        const __half* gB = Wf + (size_t)oc0 * 256 + c * 64;
        for (int idx = tid; idx < 512; idx += 256) {
            int r = idx >> 3, u = idx & 7;
            cp16(base + 18432 + (uint32_t)((r * 72 + u * 8) * 2), gB + (size_t)r * 256 + u * 8);
        }
        CP_COMMIT();
    };

    float acc[2][4][4];
#pragma unroll
    for (int mt = 0; mt < 2; mt++)
#pragma unroll
        for (int nt = 0; nt < 4; nt++)
#pragma unroll
            for (int e = 0; e < 4; e++) acc[mt][nt][e] = 0.f;

    prefetch(0);
    for (int ck = 0; ck < 4; ck++) {
        if (ck + 1 < 4) { prefetch(ck + 1); CP_WAIT1(); } else CP_WAIT0();
        __syncthreads();
        uint32_t base = sb + (ck & 1) * FIN_STG;
#pragma unroll
        for (int ks = 0; ks < 4; ks++) {
            const int k0 = ks * 16;
            uint32_t a[2][4], bb[2][4];
            ldsm4(a[0], a_addrP(base, wm * 32,      k0, lane, 72));
            ldsm4(a[1], a_addrP(base, wm * 32 + 16, k0, lane, 72));
            ldsm4(bb[0], b_addrP(base + 18432, wn * 32,      k0, lane, 72));
            ldsm4(bb[1], b_addrP(base + 18432, wn * 32 + 16, k0, lane, 72));
#pragma unroll
            for (int g = 0; g < 2; g++)
#pragma unroll
                for (int mt = 0; mt < 2; mt++) {
                    mma16816h(acc[mt][g*2],   a[mt], bb[g][0], bb[g][1]);
                    mma16816h(acc[mt][g*2+1], a[mt], bb[g][2], bb[g][3]);
                }
        }
        __syncthreads();
    }

#pragma unroll
    for (int mt = 0; mt < 2; mt++) {
        const int row = wm * 32 + mt * 16 + (lane >> 2);
#pragma unroll
        for (int nt = 0; nt < 4; nt++) {
            const int col = wn * 32 + nt * 8 + (lane & 3) * 2;
            sRes[row * 68 + col]       = acc[mt][nt][0];
            sRes[row * 68 + col + 1]   = acc[mt][nt][1];
            sRes[(row+8) * 68 + col]   = acc[mt][nt][2];
            sRes[(row+8) * 68 + col+1] = acc[mt][nt][3];
        }
    }
    __syncthreads();

    for (int t = tid; t < 128 * 64; t += 256) {
        int o = t >> 7, p = t & 127;
        int oc = oc0 + o;
        float scale = gamma[oc] * rsqrtf(var[oc] + EPS_);
        size_t gidx = ((size_t)b * C_ + oc) * HW_ + pxt * 128 + p;
        out[gidx] = (sRes[p * 68 + o] + Wb[oc] - mean[oc]) * scale + beta[oc] + x[gidx];
    }
}

// ======================================================================
extern "C" void kernel_launch(void* const* d_in, const int* in_sizes, int n_in,
                              void* d_out, int out_size)
{
    const float* x       = (const float*)d_in[0];
    const float* g_w     = (const float*)d_in[1];
    const float* g_b     = (const float*)d_in[2];
    const float* theta_w = (const float*)d_in[3];
    const float* theta_b = (const float*)d_in[4];
    const float* phi_w   = (const float*)d_in[5];
    const float* phi_b   = (const float*)d_in[6];
    const float* W_w     = (const float*)d_in[7];
    const float* W_b     = (const float*)d_in[8];
    const float* bn_g    = (const float*)d_in[9];
    const float* bn_b    = (const float*)d_in[10];
    const float* bn_m    = (const float*)d_in[11];
    const float* bn_v    = (const float*)d_in[12];
    float* out = (float*)d_out;

    __nv_bfloat16 *xh, *xl, *Wch, *Wcl, *Qh, *Ql, *Kh, *Kl;
    float *Sf, *rmx, *bc;
    __half *x16, *Wg16, *Wff, *V16, *Yf;
    cudaGetSymbolAddress((void**)&xh,   d_xh);
    cudaGetSymbolAddress((void**)&xl,   d_xl);
    cudaGetSymbolAddress((void**)&x16,  d_x16);
    cudaGetSymbolAddress((void**)&Wch,  d_Wch);
    cudaGetSymbolAddress((void**)&Wcl,  d_Wcl);
    cudaGetSymbolAddress((void**)&Wg16, d_Wg16);
    cudaGetSymbolAddress((void**)&bc,   d_bc);
    cudaGetSymbolAddress((void**)&Wff,  d_Wff);
    cudaGetSymbolAddress((void**)&Qh,   d_Qh);
    cudaGetSymbolAddress((void**)&Ql,   d_Ql);
    cudaGetSymbolAddress((void**)&Kh,   d_Kh);
    cudaGetSymbolAddress((void**)&Kl,   d_Kl);
    cudaGetSymbolAddress((void**)&V16,  d_V16);
    cudaGetSymbolAddress((void**)&Sf,   d_Sf);
    cudaGetSymbolAddress((void**)&rmx,  d_rmax);
    cudaGetSymbolAddress((void**)&Yf,   d_Yf);

    cudaFuncSetAttribute(conv_g_kernel,    cudaFuncAttributeMaxDynamicSharedMemorySize, CG_SMEM);
    cudaFuncSetAttribute(conv_qk_kernel,   cudaFuncAttributeMaxDynamicSharedMemorySize, CONV_SMEM);
    cudaFuncSetAttribute(qk_mma_kernel,    cudaFuncAttributeMaxDynamicSharedMemorySize, QK_SMEM);
    cudaFuncSetAttribute(pv_mma_kernel,    cudaFuncAttributeMaxDynamicSharedMemorySize, PV_SMEM);
    cudaFuncSetAttribute(final_mma_kernel, cudaFuncAttributeMaxDynamicSharedMemorySize, FIN_SMEM);

    xsplit_kernel<<<BB * C_ * HW_ / 1024, 256>>>(x, xh, xl, x16);
    wpack_conv_kernel<<<384, 256>>>(g_w, g_b, theta_w, theta_b, phi_w, phi_b,
                                    Wch, Wcl, Wg16, bc);
    wpack_final_kernel<<<256, 256>>>(W_w, Wff);
    conv_g_kernel<<<dim3(4, 32, BB), 256, CG_SMEM>>>(x16, Wg16, bc, V16);
    conv_qk_kernel<<<dim3(2, 32, BB), 256, CONV_SMEM>>>(xh, xl, Wch, Wcl, bc,
                                                        Qh, Ql, Kh, Kl);
    qk_mma_kernel<<<dim3(32, BB), 256, QK_SMEM>>>(Qh, Ql, Kh, Kl, Sf, rmx);
    pv_mma_kernel<<<dim3(64, BB), 256, PV_SMEM>>>(Sf, V16, rmx, Yf);
    final_mma_kernel<<<dim3(4, 32, BB), 256, FIN_SMEM>>>(Yf, Wff, W_b,
                                                         bn_g, bn_b, bn_m, bn_v, x, out);
}

// round 16
// speedup vs baseline: 2.3801x; 1.0337x over previous
#include <cuda_runtime.h>
#include <cuda_bf16.h>
#include <cuda_fp16.h>
#include <cstdint>

#define BB 8
#define C_ 256
#define HW_ 4096
#define PHW_ 1024
#define EPS_ 1e-5f

// ---------------- helpers ----------------
__device__ __forceinline__ uint32_t smem_to_u32(const void* p) {
    uint32_t a;
    asm("{ .reg .u64 t; cvta.to.shared.u64 t, %1; cvt.u32.u64 %0, t; }" : "=r"(a) : "l"(p));
    return a;
}
__device__ __forceinline__ void ldsm4(uint32_t* r, uint32_t addr) {
    asm volatile("ldmatrix.sync.aligned.m8n8.x4.shared.b16 {%0,%1,%2,%3}, [%4];"
        : "=r"(r[0]), "=r"(r[1]), "=r"(r[2]), "=r"(r[3]) : "r"(addr));
}
__device__ __forceinline__ void ldsm4t(uint32_t* r, uint32_t addr) {
    asm volatile("ldmatrix.sync.aligned.m8n8.x4.trans.shared.b16 {%0,%1,%2,%3}, [%4];"
        : "=r"(r[0]), "=r"(r[1]), "=r"(r[2]), "=r"(r[3]) : "r"(addr));
}
__device__ __forceinline__ void mma16816(float* d, const uint32_t* a, uint32_t b0, uint32_t b1) {
    asm volatile("mma.sync.aligned.m16n8k16.row.col.f32.bf16.bf16.f32 "
        "{%0,%1,%2,%3}, {%4,%5,%6,%7}, {%8,%9}, {%0,%1,%2,%3};"
        : "+f"(d[0]), "+f"(d[1]), "+f"(d[2]), "+f"(d[3])
        : "r"(a[0]), "r"(a[1]), "r"(a[2]), "r"(a[3]), "r"(b0), "r"(b1));
}
__device__ __forceinline__ void mma16816h(float* d, const uint32_t* a, uint32_t b0, uint32_t b1) {
    asm volatile("mma.sync.aligned.m16n8k16.row.col.f32.f16.f16.f32 "
        "{%0,%1,%2,%3}, {%4,%5,%6,%7}, {%8,%9}, {%0,%1,%2,%3};"
        : "+f"(d[0]), "+f"(d[1]), "+f"(d[2]), "+f"(d[3])
        : "r"(a[0]), "r"(a[1]), "r"(a[2]), "r"(a[3]), "r"(b0), "r"(b1));
}
__device__ __forceinline__ uint32_t lds32(uint32_t addr) {
    uint32_t v;
    asm volatile("ld.shared.b32 %0, [%1];" : "=r"(v) : "r"(addr));
    return v;
}
__device__ __forceinline__ void cp16(uint32_t s, const void* g) {
    asm volatile("cp.async.cg.shared.global [%0], [%1], 16;" :: "r"(s), "l"(g));
}
#define CP_COMMIT() asm volatile("cp.async.commit_group;" ::: "memory")
#define CP_WAIT0()  asm volatile("cp.async.wait_group 0;" ::: "memory")
#define CP_WAIT1()  asm volatile("cp.async.wait_group 1;" ::: "memory")

__device__ __forceinline__ void split_bf16(float v, __nv_bfloat16& h, __nv_bfloat16& l) {
    h = __float2bfloat16(v);
    l = __float2bfloat16(v - __bfloat162float(h));
}
__device__ __forceinline__ void split2(float a, float b, uint32_t& hh, uint32_t& ll) {
    __nv_bfloat16 ha, la, hb, lb;
    split_bf16(a, ha, la); split_bf16(b, hb, lb);
    hh = (uint32_t)__bfloat16_as_ushort(ha) | ((uint32_t)__bfloat16_as_ushort(hb) << 16);
    ll = (uint32_t)__bfloat16_as_ushort(la) | ((uint32_t)__bfloat16_as_ushort(lb) << 16);
}

// A-fragment (m16k16) from [m][k] row-major smem, pitch P elems (16-bit)
__device__ __forceinline__ uint32_t a_addrP(uint32_t base, int row0, int k0, int lane, int P) {
    int r = row0 + (lane & 15), c = k0 + ((lane >> 4) << 3);
    return base + (uint32_t)((r * P + c) * 2);
}
// A-fragment (m16k16) from [k][m] storage via trans-ldmatrix, pitch P (16-bit)
__device__ __forceinline__ uint32_t at_addr(uint32_t base, int m0, int k0, int lane, int P) {
    int t = lane >> 3;
    int m = m0 + ((t & 1) << 3);
    int k = k0 + ((t >> 1) << 3) + (lane & 7);
    return base + (uint32_t)((k * P + m) * 2);
}
// B-fragment x4 (two n8k16 tiles) from [n][k] row-major smem, pitch P (16-bit)
__device__ __forceinline__ uint32_t b_addrP(uint32_t base, int n0, int k0, int lane, int P) {
    int r = n0 + (lane & 7) + ((lane >> 4) << 3), c = k0 + (((lane >> 3) & 1) << 3);
    return base + (uint32_t)((r * P + c) * 2);
}

// ---------------- scratch ----------------
__device__ __nv_bfloat16 d_xh[BB*C_*HW_], d_xl[BB*C_*HW_];
__device__ __half        d_x16[BB*C_*HW_];
__device__ __nv_bfloat16 d_Wch[384*256],  d_Wcl[384*256];
__device__ __half        d_Wg16[256*256];
__device__ float         d_bc[384];
__device__ __half        d_Wff[256*256];
__device__ __nv_bfloat16 d_Qh[BB*HW_*64],  d_Ql[BB*HW_*64];
__device__ __nv_bfloat16 d_Kh[BB*PHW_*64], d_Kl[BB*PHW_*64];
__device__ __half        d_V16[BB*C_*PHW_];
__device__ float         d_Sf[(size_t)BB*HW_*PHW_];
__device__ float         d_rmax[BB*HW_];
__device__ __half        d_Yf[BB*HW_*C_];

// ======================================================================
// xsplit + weight packing
// ======================================================================
__global__ __launch_bounds__(256) void xsplit_kernel(
    const float* __restrict__ x, __nv_bfloat16* __restrict__ xh,
    __nv_bfloat16* __restrict__ xl, __half* __restrict__ x16)
{
    size_t i = ((size_t)blockIdx.x * 256 + threadIdx.x) * 4;
    float4 v = *(const float4*)(x + i);
    uint32_t h0, l0, h1, l1;
    split2(v.x, v.y, h0, l0);
    split2(v.z, v.w, h1, l1);
    *(uint2*)(xh + i) = make_uint2(h0, h1);
    *(uint2*)(xl + i) = make_uint2(l0, l1);
    __half2 f0 = __floats2half2_rn(v.x, v.y);
    __half2 f1 = __floats2half2_rn(v.z, v.w);
    *(uint2*)(x16 + i) = make_uint2(*(uint32_t*)&f0, *(uint32_t*)&f1);
}

__global__ void wpack_conv_kernel(
    const float* __restrict__ g_w, const float* __restrict__ g_b,
    const float* __restrict__ th_w, const float* __restrict__ th_b,
    const float* __restrict__ ph_w, const float* __restrict__ ph_b,
    __nv_bfloat16* __restrict__ Wh, __nv_bfloat16* __restrict__ Wl,
    __half* __restrict__ Wg16, float* __restrict__ bc)
{
    int oc = blockIdx.x, k = threadIdx.x;
    float v;
    if (oc < 256)       v = g_w[oc * 256 + k];
    else if (oc < 320)  v = (k < 64) ? th_w[(oc - 256) * 64 + k] : 0.f;
    else                v = (k >= 64) ? ph_w[(oc - 320) * 192 + (k - 64)] : 0.f;
    __nv_bfloat16 h, l; split_bf16(v, h, l);
    Wh[oc * 256 + k] = h; Wl[oc * 256 + k] = l;
    if (oc < 256) Wg16[oc * 256 + k] = __float2half_rn(v);
    if (k == 0)
        bc[oc] = (oc < 256) ? g_b[oc] : (oc < 320) ? th_b[oc - 256] : ph_b[oc - 320];
}

__global__ void wpack_final_kernel(const float* __restrict__ w, __half* __restrict__ Wf)
{
    int i = blockIdx.x * 256 + threadIdx.x;
    Wf[i] = __float2half_rn(w[i]);
}

// ======================================================================
// conv_g (fp16 1-pass): V = pool(g_conv(x)) -> fp16.  (unchanged)
// ======================================================================
static constexpr int CG_STG  = 26624;
static constexpr int CG_SMEM = 2 * CG_STG;

__global__ __launch_bounds__(256, 2) void conv_g_kernel(
    const __half* __restrict__ x16, const __half* __restrict__ Wg,
    const float* __restrict__ bc, __half* __restrict__ V16)
{
    extern __shared__ char smem[];
    const uint32_t sb = smem_to_u32(smem);
    float* sRes = (float*)smem;
    const int tid = threadIdx.x, lane = tid & 31, wid = tid >> 5;
    const int wm = wid & 3, wn = wid >> 2;
    const int b = blockIdx.z, pxt = blockIdx.y, oc0 = blockIdx.x * 64;

    auto prefetch = [&](int c) {
        uint32_t base = sb + (c & 1) * CG_STG;
        const __half* gx = x16 + ((size_t)b * C_ + c * 64) * HW_ + pxt * 128;
        for (int idx = tid; idx < 1024; idx += 256) {
            int r = idx >> 4, u = idx & 15;
            cp16(base + (uint32_t)((r * 136 + u * 8) * 2), gx + (size_t)r * HW_ + u * 8);
        }
        const __half* gw = Wg + (size_t)oc0 * 256 + c * 64;
        for (int idx = tid; idx < 512; idx += 256) {
            int r = idx >> 3, u = idx & 7;
            cp16(base + 17408 + (uint32_t)((r * 72 + u * 8) * 2), gw + (size_t)r * 256 + u * 8);
        }
        CP_COMMIT();
    };

    float acc[2][4][4];
#pragma unroll
    for (int mt = 0; mt < 2; mt++)
#pragma unroll
        for (int nt = 0; nt < 4; nt++)
#pragma unroll
            for (int e = 0; e < 4; e++) acc[mt][nt][e] = 0.f;

    prefetch(0);
    for (int ck = 0; ck < 4; ck++) {
        if (ck + 1 < 4) { prefetch(ck + 1); CP_WAIT1(); } else CP_WAIT0();
        __syncthreads();
        const uint32_t xb = sb + (ck & 1) * CG_STG;
        const uint32_t wb = xb + 17408;
#pragma unroll
        for (int ks = 0; ks < 4; ks++) {
            const int k0 = ks * 16;
            uint32_t a[2][4], bb[2][4];
            ldsm4t(a[0], at_addr(xb, wm * 32,      k0, lane, 136));
            ldsm4t(a[1], at_addr(xb, wm * 32 + 16, k0, lane, 136));
            ldsm4(bb[0], b_addrP(wb, wn * 32,      k0, lane, 72));
            ldsm4(bb[1], b_addrP(wb, wn * 32 + 16, k0, lane, 72));
#pragma unroll
            for (int g = 0; g < 2; g++)
#pragma unroll
                for (int mt = 0; mt < 2; mt++) {
                    mma16816h(acc[mt][g*2],   a[mt], bb[g][0], bb[g][1]);
                    mma16816h(acc[mt][g*2+1], a[mt], bb[g][2], bb[g][3]);
                }
        }
        __syncthreads();
    }

#pragma unroll
    for (int mt = 0; mt < 2; mt++) {
        const int row = wm * 32 + mt * 16 + (lane >> 2);
#pragma unroll
        for (int nt = 0; nt < 4; nt++) {
            const int col = wn * 32 + nt * 8 + (lane & 3) * 2;
            sRes[row * 68 + col]       = acc[mt][nt][0];
            sRes[row * 68 + col + 1]   = acc[mt][nt][1];
            sRes[(row+8) * 68 + col]   = acc[mt][nt][2];
            sRes[(row+8) * 68 + col+1] = acc[mt][nt][3];
        }
    }
    __syncthreads();

    for (int t = tid; t < 32 * 64; t += 256) {
        int pw = t >> 6, o = t & 63, oc = oc0 + o;
        float v = fmaxf(fmaxf(sRes[(2*pw)*68 + o], sRes[(2*pw+1)*68 + o]),
                        fmaxf(sRes[(64+2*pw)*68 + o], sRes[(65+2*pw)*68 + o]))
                  + bc[oc];
        size_t oidx = ((size_t)b * C_ + oc) * PHW_ + pxt * 32 + pw;
        V16[oidx] = __float2half_rn(v);
    }
}

// ======================================================================
// conv_qk (bf16 3-pass): theta + phi convs.
// SKIPS zero-padded k-chunks: theta (blk 0) -> chunk 0 only (k 0..63);
// phi (blk 1) -> chunks 1..3 (k 64..255). Bit-identical to computing all 4.
// ======================================================================
static constexpr int CONV_STG  = 53248;
static constexpr int CONV_SMEM = 2 * CONV_STG;

__global__ __launch_bounds__(256, 2) void conv_qk_kernel(
    const __nv_bfloat16* __restrict__ xh, const __nv_bfloat16* __restrict__ xl,
    const __nv_bfloat16* __restrict__ Wh, const __nv_bfloat16* __restrict__ Wl,
    const float* __restrict__ bc,
    __nv_bfloat16* __restrict__ Qh, __nv_bfloat16* __restrict__ Ql,
    __nv_bfloat16* __restrict__ Kh, __nv_bfloat16* __restrict__ Kl)
{
    extern __shared__ char smem[];
    const uint32_t sb = smem_to_u32(smem);
    float* sRes = (float*)smem;
    const int tid = threadIdx.x, lane = tid & 31, wid = tid >> 5;
    const int wm = wid & 3, wn = wid >> 2;
    const int b = blockIdx.z, pxt = blockIdx.y, oc0 = 256 + blockIdx.x * 64;

    auto prefetch = [&](int c) {
        uint32_t base = sb + (c & 1) * CONV_STG;
        const __nv_bfloat16* gxh = xh + ((size_t)b * C_ + c * 64) * HW_ + pxt * 128;
        const __nv_bfloat16* gxl = xl + ((size_t)b * C_ + c * 64) * HW_ + pxt * 128;
        for (int idx = tid; idx < 1024; idx += 256) {
            int r = idx >> 4, u = idx & 15;
            uint32_t so = (uint32_t)((r * 136 + u * 8) * 2);
            cp16(base + so,         gxh + (size_t)r * HW_ + u * 8);
            cp16(base + 17408 + so, gxl + (size_t)r * HW_ + u * 8);
        }
        const __nv_bfloat16* gwh = Wh + (size_t)oc0 * 256 + c * 64;
        const __nv_bfloat16* gwl = Wl + (size_t)oc0 * 256 + c * 64;
        for (int idx = tid; idx < 512; idx += 256) {
            int r = idx >> 3, u = idx & 7;
            uint32_t so = (uint32_t)((r * 72 + u * 8) * 2);
            cp16(base + 34816 + so, gwh + (size_t)r * 256 + u * 8);
            cp16(base + 44032 + so, gwl + (size_t)r * 256 + u * 8);
        }
        CP_COMMIT();
    };

    float acc[2][4][4];
#pragma unroll
    for (int mt = 0; mt < 2; mt++)
#pragma unroll
        for (int nt = 0; nt < 4; nt++)
#pragma unroll
            for (int e = 0; e < 4; e++) acc[mt][nt][e] = 0.f;

    // theta: only k-chunk 0 has nonzero weights; phi: chunks 1..3
    const int ck_lo = (blockIdx.x == 0) ? 0 : 1;
    const int n_ck  = (blockIdx.x == 0) ? 1 : 3;

    prefetch(ck_lo);
    for (int ci = 0; ci < n_ck; ci++) {
        const int ck = ck_lo + ci;
        if (ci + 1 < n_ck) { prefetch(ck + 1); CP_WAIT1(); } else CP_WAIT0();
        __syncthreads();
        uint32_t base = sb + (ck & 1) * CONV_STG;
#pragma unroll
        for (int ks = 0; ks < 4; ks++) {
            const int k0 = ks * 16;
            uint32_t ah[2][4], al[2][4], bh[2][4], bl[2][4];
            ldsm4t(ah[0], at_addr(base, wm * 32,      k0, lane, 136));
            ldsm4t(ah[1], at_addr(base, wm * 32 + 16, k0, lane, 136));
            ldsm4(bh[0], b_addrP(base + 34816, wn * 32,      k0, lane, 72));
            ldsm4(bh[1], b_addrP(base + 34816, wn * 32 + 16, k0, lane, 72));
#pragma unroll
            for (int g = 0; g < 2; g++)
#pragma unroll
                for (int mt = 0; mt < 2; mt++) {
                    mma16816(acc[mt][g*2],   ah[mt], bh[g][0], bh[g][1]);
                    mma16816(acc[mt][g*2+1], ah[mt], bh[g][2], bh[g][3]);
                }
            ldsm4(bl[0], b_addrP(base + 44032, wn * 32,      k0, lane, 72));
            ldsm4(bl[1], b_addrP(base + 44032, wn * 32 + 16, k0, lane, 72));
#pragma unroll
            for (int g = 0; g < 2; g++)
#pragma unroll
                for (int mt = 0; mt < 2; mt++) {
                    mma16816(acc[mt][g*2],   ah[mt], bl[g][0], bl[g][1]);
                    mma16816(acc[mt][g*2+1], ah[mt], bl[g][2], bl[g][3]);
                }
            ldsm4t(al[0], at_addr(base + 17408, wm * 32,      k0, lane, 136));
            ldsm4t(al[1], at_addr(base + 17408, wm * 32 + 16, k0, lane, 136));
#pragma unroll
            for (int g = 0; g < 2; g++)
#pragma unroll
                for (int mt = 0; mt < 2; mt++) {
                    mma16816(acc[mt][g*2],   al[mt], bh[g][0], bh[g][1]);
                    mma16816(acc[mt][g*2+1], al[mt], bh[g][2], bh[g][3]);
                }
        }
        __syncthreads();
    }

#pragma unroll
    for (int mt = 0; mt < 2; mt++) {
        const int row = wm * 32 + mt * 16 + (lane >> 2);
#pragma unroll
        for (int nt = 0; nt < 4; nt++) {
            const int col = wn * 32 + nt * 8 + (lane & 3) * 2;
            sRes[row * 68 + col]       = acc[mt][nt][0];
            sRes[row * 68 + col + 1]   = acc[mt][nt][1];
            sRes[(row+8) * 68 + col]   = acc[mt][nt][2];
            sRes[(row+8) * 68 + col+1] = acc[mt][nt][3];
        }
    }
    __syncthreads();

    if (blockIdx.x == 0) {
        for (int t = tid; t < 128 * 64; t += 256) {
            int p = t >> 6, o = t & 63;
            float v = sRes[p * 68 + o] + bc[256 + o];
            __nv_bfloat16 h, l; split_bf16(v, h, l);
            size_t oidx = ((size_t)b * HW_ + pxt * 128 + p) * 64 + o;
            Qh[oidx] = h; Ql[oidx] = l;
        }
    } else {
        for (int t = tid; t < 32 * 64; t += 256) {
            int pw = t >> 6, o = t & 63;
            float v = fmaxf(fmaxf(sRes[(2*pw)*68 + o], sRes[(2*pw+1)*68 + o]),
                            fmaxf(sRes[(64+2*pw)*68 + o], sRes[(65+2*pw)*68 + o]))
                      + bc[320 + o];
            __nv_bfloat16 h, l; split_bf16(v, h, l);
            size_t oidx = ((size_t)b * PHW_ + pxt * 32 + pw) * 64 + o;
            Kh[oidx] = h; Kl[oidx] = l;
        }
    }
}

// ======================================================================
// qk_mma: split-bf16 3-pass. Stores RAW S fp32 + per-row max. (unchanged)
// ======================================================================
static constexpr int QK_SMEM = 110592 + 1024;

__global__ __launch_bounds__(256, 2) void qk_mma_kernel(
    const __nv_bfloat16* __restrict__ Qh, const __nv_bfloat16* __restrict__ Ql,
    const __nv_bfloat16* __restrict__ Kh, const __nv_bfloat16* __restrict__ Kl,
    float* __restrict__ Sf, float* __restrict__ rmax)
{
    extern __shared__ char smem[];
    const uint32_t sb = smem_to_u32(smem);
    __nv_bfloat16* sQ = (__nv_bfloat16*)smem;
    float* rs = (float*)(smem + 110592);
    const int tid = threadIdx.x, lane = tid & 31, wid = tid >> 5;
    const int wm = wid & 3, wn = wid >> 2;
    const int b = blockIdx.y, n0 = blockIdx.x * 128;

    auto prefetch = [&](int c) {
        uint32_t base = sb + 36864 + (c & 1) * 36864;
        const __nv_bfloat16* gkh = Kh + ((size_t)b * PHW_ + c * 128) * 64;
        const __nv_bfloat16* gkl = Kl + ((size_t)b * PHW_ + c * 128) * 64;
        for (int idx = tid; idx < 1024; idx += 256) {
            int r = idx >> 3, u = idx & 7;
            uint32_t so = (uint32_t)((r * 72 + u * 8) * 2);
            cp16(base + so,         gkh + r * 64 + u * 8);
            cp16(base + 18432 + so, gkl + r * 64 + u * 8);
        }
        CP_COMMIT();
    };

    prefetch(0);
    {
        const __nv_bfloat16* gqh = Qh + ((size_t)b * HW_ + n0) * 64;
        const __nv_bfloat16* gql = Ql + ((size_t)b * HW_ + n0) * 64;
        for (int idx = tid; idx < 1024; idx += 256) {
            int r = idx >> 3, u = idx & 7;
            *(uint4*)(sQ + r * 72 + u * 8)        = *(const uint4*)(gqh + r * 64 + u * 8);
            *(uint4*)(sQ + 9216 + r * 72 + u * 8) = *(const uint4*)(gql + r * 64 + u * 8);
        }
    }

    float rmx[2][2] = {{-1e30f, -1e30f}, {-1e30f, -1e30f}};

    for (int ck = 0; ck < 8; ck++) {
        const int m0 = ck * 128;
        if (ck + 1 < 8) { prefetch(ck + 1); CP_WAIT1(); } else CP_WAIT0();
        __syncthreads();
        uint32_t kb = sb + 36864 + (ck & 1) * 36864;

        float acc[2][8][4];
#pragma unroll
        for (int mt = 0; mt < 2; mt++)
#pragma unroll
            for (int nt = 0; nt < 8; nt++)
#pragma unroll
                for (int e = 0; e < 4; e++) acc[mt][nt][e] = 0.f;

#pragma unroll
        for (int ks = 0; ks < 4; ks++) {
            const int k0 = ks * 16;
            uint32_t ah[2][4], al[2][4];
            ldsm4(ah[0], a_addrP(sb,         wm * 32,      k0, lane, 72));
            ldsm4(ah[1], a_addrP(sb,         wm * 32 + 16, k0, lane, 72));
            ldsm4(al[0], a_addrP(sb + 18432, wm * 32,      k0, lane, 72));
            ldsm4(al[1], a_addrP(sb + 18432, wm * 32 + 16, k0, lane, 72));
#pragma unroll
            for (int g = 0; g < 4; g++) {
                uint32_t bh[4], bl[4];
                ldsm4(bh, b_addrP(kb,         wn * 64 + g * 16, k0, lane, 72));
                ldsm4(bl, b_addrP(kb + 18432, wn * 64 + g * 16, k0, lane, 72));
#pragma unroll
                for (int mt = 0; mt < 2; mt++) {
                    mma16816(acc[mt][g*2],   ah[mt], bh[0], bh[1]);
                    mma16816(acc[mt][g*2+1], ah[mt], bh[2], bh[3]);
                }
#pragma unroll
                for (int mt = 0; mt < 2; mt++) {
                    mma16816(acc[mt][g*2],   ah[mt], bl[0], bl[1]);
                    mma16816(acc[mt][g*2+1], ah[mt], bl[2], bl[3]);
                }
#pragma unroll
                for (int mt = 0; mt < 2; mt++) {
                    mma16816(acc[mt][g*2],   al[mt], bh[0], bh[1]);
                    mma16816(acc[mt][g*2+1], al[mt], bh[2], bh[3]);
                }
            }
        }

#pragma unroll
        for (int mt = 0; mt < 2; mt++) {
            const int row = n0 + wm * 32 + mt * 16 + (lane >> 2);
#pragma unroll
            for (int nt = 0; nt < 8; nt++) {
                float s0 = acc[mt][nt][0], s1 = acc[mt][nt][1];
                float s2 = acc[mt][nt][2], s3 = acc[mt][nt][3];
                rmx[mt][0] = fmaxf(rmx[mt][0], fmaxf(s0, s1));
                rmx[mt][1] = fmaxf(rmx[mt][1], fmaxf(s2, s3));
                const int col = m0 + wn * 64 + nt * 8 + (lane & 3) * 2;
                *(float2*)&Sf[((size_t)b * HW_ + row) * PHW_ + col] = make_float2(s0, s1);
                *(float2*)&Sf[((size_t)b * HW_ + row + 8) * PHW_ + col] = make_float2(s2, s3);
            }
        }
        __syncthreads();
    }

#pragma unroll
    for (int mt = 0; mt < 2; mt++)
#pragma unroll
        for (int hh = 0; hh < 2; hh++) {
            float m = rmx[mt][hh];
            m = fmaxf(m, __shfl_xor_sync(0xffffffffu, m, 1));
            m = fmaxf(m, __shfl_xor_sync(0xffffffffu, m, 2));
            if ((lane & 3) == 0)
                rs[wn * 128 + wm * 32 + mt * 16 + hh * 8 + (lane >> 2)] = m;
        }
    __syncthreads();
    if (tid < 128)
        rmax[(size_t)b * HW_ + n0 + tid] = fmaxf(rs[tid], rs[128 + tid]);
}

// ======================================================================
// pv_mma (fp16 1-pass): unchanged from R13/R14
// ======================================================================
static constexpr int PV_STG  = 29696;
static constexpr int PV_P16  = 2 * PV_STG;
static constexpr int PV_RS   = PV_P16 + 5120;
static constexpr int PV_SMEM = PV_RS + 256;

__global__ __launch_bounds__(256, 2) void pv_mma_kernel(
    const float* __restrict__ Sf, const __half* __restrict__ V16,
    const float* __restrict__ rmax, __half* __restrict__ Yf)
{
    extern __shared__ char smem[];
    const uint32_t sb = smem_to_u32(smem);
    const int tid = threadIdx.x, lane = tid & 31, wid = tid >> 5;
    const int wm = wid & 1, wn = wid >> 1;
    const int b = blockIdx.y, n0 = blockIdx.x * 64;

    auto prefetch = [&](int c) {
        uint32_t base = sb + (c & 1) * PV_STG;
        const float* gs = Sf + ((size_t)b * HW_ + n0) * PHW_ + c * 32;
        for (int idx = tid; idx < 512; idx += 256) {
            int r = idx >> 3, u = idx & 7;
            cp16(base + (uint32_t)((r * 36 + u * 4) * 4), gs + (size_t)r * PHW_ + u * 4);
        }
        const __half* gv = V16 + (size_t)b * C_ * PHW_ + c * 32;
        for (int idx = tid; idx < 1024; idx += 256) {
            int r = idx >> 2, u = idx & 3;
            cp16(base + 9216 + (uint32_t)((r * 40 + u * 8) * 2), gv + (size_t)r * PHW_ + u * 8);
        }
        CP_COMMIT();
    };

    const int crow = tid >> 2, cu = tid & 3;
    const float rmx = rmax[(size_t)b * HW_ + n0 + crow];
    float rsum_loc = 0.f;

    float acc[2][8][4];
#pragma unroll
    for (int mt = 0; mt < 2; mt++)
#pragma unroll
        for (int nt = 0; nt < 8; nt++)
#pragma unroll
            for (int e = 0; e < 4; e++) acc[mt][nt][e] = 0.f;

    prefetch(0);
    for (int ck = 0; ck < 32; ck++) {
        CP_WAIT0();
        __syncthreads();
        if (ck + 1 < 32) prefetch(ck + 1);
        {
            const float* srow = (const float*)(smem + (ck & 1) * PV_STG) + crow * 36 + cu * 8;
            float4 s0 = *(const float4*)(srow);
            float4 s1 = *(const float4*)(srow + 4);
            float p0 = __expf(s0.x - rmx), p1 = __expf(s0.y - rmx);
            float p2 = __expf(s0.z - rmx), p3 = __expf(s0.w - rmx);
            float p4 = __expf(s1.x - rmx), p5 = __expf(s1.y - rmx);
            float p6 = __expf(s1.z - rmx), p7 = __expf(s1.w - rmx);
            rsum_loc += (p0 + p1 + p2 + p3) + (p4 + p5 + p6 + p7);
            __half2 h0 = __floats2half2_rn(p0, p1), h1 = __floats2half2_rn(p2, p3);
            __half2 h2 = __floats2half2_rn(p4, p5), h3 = __floats2half2_rn(p6, p7);
            uint4 pk;
            pk.x = *(uint32_t*)&h0; pk.y = *(uint32_t*)&h1;
            pk.z = *(uint32_t*)&h2; pk.w = *(uint32_t*)&h3;
            *(uint4*)(smem + PV_P16 + (crow * 40 + cu * 8) * 2) = pk;
        }
        __syncthreads();
        const uint32_t pb = sb + PV_P16;
        const uint32_t vb = sb + (ck & 1) * PV_STG + 9216;
#pragma unroll
        for (int ks = 0; ks < 2; ks++) {
            const int k0 = ks * 16;
            uint32_t a[2][4], bh[4][4];
            ldsm4(a[0], a_addrP(pb, wm * 32,      k0, lane, 40));
            ldsm4(a[1], a_addrP(pb, wm * 32 + 16, k0, lane, 40));
#pragma unroll
            for (int g = 0; g < 4; g++)
                ldsm4(bh[g], b_addrP(vb, wn * 64 + g * 16, k0, lane, 40));
#pragma unroll
            for (int g = 0; g < 4; g++)
#pragma unroll
                for (int mt = 0; mt < 2; mt++) {
                    mma16816h(acc[mt][g*2],   a[mt], bh[g][0], bh[g][1]);
                    mma16816h(acc[mt][g*2+1], a[mt], bh[g][2], bh[g][3]);
                }
        }
    }

    {
        float s = rsum_loc;
        s += __shfl_xor_sync(0xffffffffu, s, 1);
        s += __shfl_xor_sync(0xffffffffu, s, 2);
        if (cu == 0) ((float*)(smem + PV_RS))[crow] = s;
    }
    __syncthreads();
    const float* rsArr = (const float*)(smem + PV_RS);

#pragma unroll
    for (int mt = 0; mt < 2; mt++) {
        const int rl = wm * 32 + mt * 16 + (lane >> 2);
        const int r0 = n0 + rl;
        const float i0 = 1.f / rsArr[rl];
        const float i1 = 1.f / rsArr[rl + 8];
#pragma unroll
        for (int nt = 0; nt < 8; nt++) {
            const int col = wn * 64 + nt * 8 + (lane & 3) * 2;
            __half2 p0 = __floats2half2_rn(acc[mt][nt][0] * i0, acc[mt][nt][1] * i0);
            __half2 p1 = __floats2half2_rn(acc[mt][nt][2] * i1, acc[mt][nt][3] * i1);
            *(__half2*)&Yf[((size_t)b * HW_ + r0) * C_ + col] = p0;
            *(__half2*)&Yf[((size_t)b * HW_ + r0 + 8) * C_ + col] = p1;
        }
    }
}

// ======================================================================
// final_mma (fp16 1-pass): unchanged
// ======================================================================
static constexpr int FIN_STG  = 27648;
static constexpr int FIN_SMEM = 2 * FIN_STG;

__global__ __launch_bounds__(256, 2) void final_mma_kernel(
    const __half* __restrict__ Yf, const __half* __restrict__ Wf,
    const float* __restrict__ Wb,
    const float* __restrict__ gamma, const float* __restrict__ beta,
    const float* __restrict__ mean, const float* __restrict__ var,
    const float* __restrict__ x, float* __restrict__ out)
{
    extern __shared__ char smem[];
    const uint32_t sb = smem_to_u32(smem);
    float* sRes = (float*)smem;
    const int tid = threadIdx.x, lane = tid & 31, wid = tid >> 5;
    const int wm = wid & 3, wn = wid >> 2;
    const int b = blockIdx.z, pxt = blockIdx.y, oc0 = blockIdx.x * 64;

    auto prefetch = [&](int c) {
        uint32_t base = sb + (c & 1) * FIN_STG;
        const __half* gA = Yf + ((size_t)b * HW_ + pxt * 128) * C_ + c * 64;
        for (int idx = tid; idx < 1024; idx += 256) {
            int r = idx >> 3, u = idx & 7;
            cp16(base + (uint32_t)((r * 72 + u * 8) * 2), gA + (size_t)r * C_ + u * 8);
        }
        const __half* gB = Wf + (size_t)oc0 * 256 + c * 64;
        for (int idx = tid; idx < 512; idx += 256) {
            int r = idx >> 3, u = idx & 7;
            cp16(base + 18432 + (uint32_t)((r * 72 + u * 8) * 2), gB + (size_t)r * 256 + u * 8);
        }
        CP_COMMIT();
    };

    float acc[2][4][4];
#pragma unroll
    for (int mt = 0; mt < 2; mt++)
#pragma unroll
        for (int nt = 0; nt < 4; nt++)
#pragma unroll
            for (int e = 0; e < 4; e++) acc[mt][nt][e] = 0.f;

    prefetch(0);
    for (int ck = 0; ck < 4; ck++) {
        if (ck + 1 < 4) { prefetch(ck + 1); CP_WAIT1(); } else CP_WAIT0();
        __syncthreads();
        uint32_t base = sb + (ck & 1) * FIN_STG;
#pragma unroll
        for (int ks = 0; ks < 4; ks++) {
            const int k0 = ks * 16;
            uint32_t a[2][4], bb[2][4];
            ldsm4(a[0], a_addrP(base, wm * 32,      k0, lane, 72));
            ldsm4(a[1], a_addrP(base, wm * 32 + 16, k0, lane, 72));
            ldsm4(bb[0], b_addrP(base + 18432, wn * 32,      k0, lane, 72));
            ldsm4(bb[1], b_addrP(base + 18432, wn * 32 + 16, k0, lane, 72));
#pragma unroll
            for (int g = 0; g < 2; g++)
#pragma unroll
                for (int mt = 0; mt < 2; mt++) {
                    mma16816h(acc[mt][g*2],   a[mt], bb[g][0], bb[g][1]);
                    mma16816h(acc[mt][g*2+1], a[mt], bb[g][2], bb[g][3]);
                }
        }
        __syncthreads();
    }

#pragma unroll
    for (int mt = 0; mt < 2; mt++) {
        const int row = wm * 32 + mt * 16 + (lane >> 2);
#pragma unroll
        for (int nt = 0; nt < 4; nt++) {
            const int col = wn * 32 + nt * 8 + (lane & 3) * 2;
            sRes[row * 68 + col]       = acc[mt][nt][0];
            sRes[row * 68 + col + 1]   = acc[mt][nt][1];
            sRes[(row+8) * 68 + col]   = acc[mt][nt][2];
            sRes[(row+8) * 68 + col+1] = acc[mt][nt][3];
        }
    }
    __syncthreads();

    for (int t = tid; t < 128 * 64; t += 256) {
        int o = t >> 7, p = t & 127;
        int oc = oc0 + o;
        float scale = gamma[oc] * rsqrtf(var[oc] + EPS_);
        size_t gidx = ((size_t)b * C_ + oc) * HW_ + pxt * 128 + p;
        out[gidx] = (sRes[p * 68 + o] + Wb[oc] - mean[oc]) * scale + beta[oc] + x[gidx];
    }
}

// ======================================================================
extern "C" void kernel_launch(void* const* d_in, const int* in_sizes, int n_in,
                              void* d_out, int out_size)
{
    const float* x       = (const float*)d_in[0];
    const float* g_w     = (const float*)d_in[1];
    const float* g_b     = (const float*)d_in[2];
    const float* theta_w = (const float*)d_in[3];
    const float* theta_b = (const float*)d_in[4];
    const float* phi_w   = (const float*)d_in[5];
    const float* phi_b   = (const float*)d_in[6];
    const float* W_w     = (const float*)d_in[7];
    const float* W_b     = (const float*)d_in[8];
    const float* bn_g    = (const float*)d_in[9];
    const float* bn_b    = (const float*)d_in[10];
    const float* bn_m    = (const float*)d_in[11];
    const float* bn_v    = (const float*)d_in[12];
    float* out = (float*)d_out;

    __nv_bfloat16 *xh, *xl, *Wch, *Wcl, *Qh, *Ql, *Kh, *Kl;
    float *Sf, *rmx, *bc;
    __half *x16, *Wg16, *Wff, *V16, *Yf;
    cudaGetSymbolAddress((void**)&xh,   d_xh);
    cudaGetSymbolAddress((void**)&xl,   d_xl);
    cudaGetSymbolAddress((void**)&x16,  d_x16);
    cudaGetSymbolAddress((void**)&Wch,  d_Wch);
    cudaGetSymbolAddress((void**)&Wcl,  d_Wcl);
    cudaGetSymbolAddress((void**)&Wg16, d_Wg16);
    cudaGetSymbolAddress((void**)&bc,   d_bc);
    cudaGetSymbolAddress((void**)&Wff,  d_Wff);
    cudaGetSymbolAddress((void**)&Qh,   d_Qh);
    cudaGetSymbolAddress((void**)&Ql,   d_Ql);
    cudaGetSymbolAddress((void**)&Kh,   d_Kh);
    cudaGetSymbolAddress((void**)&Kl,   d_Kl);
    cudaGetSymbolAddress((void**)&V16,  d_V16);
    cudaGetSymbolAddress((void**)&Sf,   d_Sf);
    cudaGetSymbolAddress((void**)&rmx,  d_rmax);
    cudaGetSymbolAddress((void**)&Yf,   d_Yf);

    cudaFuncSetAttribute(conv_g_kernel,    cudaFuncAttributeMaxDynamicSharedMemorySize, CG_SMEM);
    cudaFuncSetAttribute(conv_qk_kernel,   cudaFuncAttributeMaxDynamicSharedMemorySize, CONV_SMEM);
    cudaFuncSetAttribute(qk_mma_kernel,    cudaFuncAttributeMaxDynamicSharedMemorySize, QK_SMEM);
    cudaFuncSetAttribute(pv_mma_kernel,    cudaFuncAttributeMaxDynamicSharedMemorySize, PV_SMEM);
    cudaFuncSetAttribute(final_mma_kernel, cudaFuncAttributeMaxDynamicSharedMemorySize, FIN_SMEM);

    xsplit_kernel<<<BB * C_ * HW_ / 1024, 256>>>(x, xh, xl, x16);
    wpack_conv_kernel<<<384, 256>>>(g_w, g_b, theta_w, theta_b, phi_w, phi_b,
                                    Wch, Wcl, Wg16, bc);
    wpack_final_kernel<<<256, 256>>>(W_w, Wff);
    conv_g_kernel<<<dim3(4, 32, BB), 256, CG_SMEM>>>(x16, Wg16, bc, V16);
    conv_qk_kernel<<<dim3(2, 32, BB), 256, CONV_SMEM>>>(xh, xl, Wch, Wcl, bc,
                                                        Qh, Ql, Kh, Kl);
    qk_mma_kernel<<<dim3(32, BB), 256, QK_SMEM>>>(Qh, Ql, Kh, Kl, Sf, rmx);
    pv_mma_kernel<<<dim3(64, BB), 256, PV_SMEM>>>(Sf, V16, rmx, Yf);
    final_mma_kernel<<<dim3(4, 32, BB), 256, FIN_SMEM>>>(Yf, Wff, W_b,
                                                         bn_g, bn_b, bn_m, bn_v, x, out);
}

// round 17
// speedup vs baseline: 2.4416x; 1.0259x over previous
#include <cuda_runtime.h>
#include <cuda_bf16.h>
#include <cuda_fp16.h>
#include <cstdint>

#define BB 8
#define C_ 256
#define HW_ 4096
#define PHW_ 1024
#define EPS_ 1e-5f

// ---------------- helpers ----------------
__device__ __forceinline__ uint32_t smem_to_u32(const void* p) {
    uint32_t a;
    asm("{ .reg .u64 t; cvta.to.shared.u64 t, %1; cvt.u32.u64 %0, t; }" : "=r"(a) : "l"(p));
    return a;
}
__device__ __forceinline__ void ldsm4(uint32_t* r, uint32_t addr) {
    asm volatile("ldmatrix.sync.aligned.m8n8.x4.shared.b16 {%0,%1,%2,%3}, [%4];"
        : "=r"(r[0]), "=r"(r[1]), "=r"(r[2]), "=r"(r[3]) : "r"(addr));
}
__device__ __forceinline__ void ldsm4t(uint32_t* r, uint32_t addr) {
    asm volatile("ldmatrix.sync.aligned.m8n8.x4.trans.shared.b16 {%0,%1,%2,%3}, [%4];"
        : "=r"(r[0]), "=r"(r[1]), "=r"(r[2]), "=r"(r[3]) : "r"(addr));
}
__device__ __forceinline__ void mma16816(float* d, const uint32_t* a, uint32_t b0, uint32_t b1) {
    asm volatile("mma.sync.aligned.m16n8k16.row.col.f32.bf16.bf16.f32 "
        "{%0,%1,%2,%3}, {%4,%5,%6,%7}, {%8,%9}, {%0,%1,%2,%3};"
        : "+f"(d[0]), "+f"(d[1]), "+f"(d[2]), "+f"(d[3])
        : "r"(a[0]), "r"(a[1]), "r"(a[2]), "r"(a[3]), "r"(b0), "r"(b1));
}
__device__ __forceinline__ void mma16816h(float* d, const uint32_t* a, uint32_t b0, uint32_t b1) {
    asm volatile("mma.sync.aligned.m16n8k16.row.col.f32.f16.f16.f32 "
        "{%0,%1,%2,%3}, {%4,%5,%6,%7}, {%8,%9}, {%0,%1,%2,%3};"
        : "+f"(d[0]), "+f"(d[1]), "+f"(d[2]), "+f"(d[3])
        : "r"(a[0]), "r"(a[1]), "r"(a[2]), "r"(a[3]), "r"(b0), "r"(b1));
}
__device__ __forceinline__ void cp16(uint32_t s, const void* g) {
    asm volatile("cp.async.cg.shared.global [%0], [%1], 16;" :: "r"(s), "l"(g));
}
#define CP_COMMIT() asm volatile("cp.async.commit_group;" ::: "memory")
#define CP_WAIT0()  asm volatile("cp.async.wait_group 0;" ::: "memory")
#define CP_WAIT1()  asm volatile("cp.async.wait_group 1;" ::: "memory")

__device__ __forceinline__ void split_bf16(float v, __nv_bfloat16& h, __nv_bfloat16& l) {
    h = __float2bfloat16(v);
    l = __float2bfloat16(v - __bfloat162float(h));
}
__device__ __forceinline__ void split2(float a, float b, uint32_t& hh, uint32_t& ll) {
    __nv_bfloat16 ha, la, hb, lb;
    split_bf16(a, ha, la); split_bf16(b, hb, lb);
    hh = (uint32_t)__bfloat16_as_ushort(ha) | ((uint32_t)__bfloat16_as_ushort(hb) << 16);
    ll = (uint32_t)__bfloat16_as_ushort(la) | ((uint32_t)__bfloat16_as_ushort(lb) << 16);
}

// A-fragment (m16k16) from [m][k] row-major smem, pitch P elems (16-bit)
__device__ __forceinline__ uint32_t a_addrP(uint32_t base, int row0, int k0, int lane, int P) {
    int r = row0 + (lane & 15), c = k0 + ((lane >> 4) << 3);
    return base + (uint32_t)((r * P + c) * 2);
}
// A-fragment (m16k16) from [k][m] storage via trans-ldmatrix, pitch P (16-bit)
__device__ __forceinline__ uint32_t at_addr(uint32_t base, int m0, int k0, int lane, int P) {
    int t = lane >> 3;
    int m = m0 + ((t & 1) << 3);
    int k = k0 + ((t >> 1) << 3) + (lane & 7);
    return base + (uint32_t)((k * P + m) * 2);
}
// B-fragment x4 (two n8k16 tiles) from [n][k] row-major smem, pitch P (16-bit)
__device__ __forceinline__ uint32_t b_addrP(uint32_t base, int n0, int k0, int lane, int P) {
    int r = n0 + (lane & 7) + ((lane >> 4) << 3), c = k0 + (((lane >> 3) & 1) << 3);
    return base + (uint32_t)((r * P + c) * 2);
}

// ---------------- scratch ----------------
__device__ __nv_bfloat16 d_xh[BB*C_*HW_], d_xl[BB*C_*HW_];
__device__ __half        d_x16[BB*C_*HW_];
__device__ __nv_bfloat16 d_Wch[384*256],  d_Wcl[384*256];
__device__ __half        d_Wg16[256*256];
__device__ float         d_bc[384];
__device__ __half        d_Wff[256*256];
__device__ __nv_bfloat16 d_Qh[BB*HW_*64],  d_Ql[BB*HW_*64];
__device__ __nv_bfloat16 d_Kh[BB*PHW_*64], d_Kl[BB*PHW_*64];
__device__ __half        d_V16[BB*C_*PHW_];
__device__ float         d_Sf[(size_t)BB*HW_*PHW_];
__device__ float         d_rmax[2*BB*HW_];               // two K-halves
__device__ __half        d_Yf[BB*HW_*C_];

// ======================================================================
// xsplit + weight packing
// ======================================================================
__global__ __launch_bounds__(256) void xsplit_kernel(
    const float* __restrict__ x, __nv_bfloat16* __restrict__ xh,
    __nv_bfloat16* __restrict__ xl, __half* __restrict__ x16)
{
    size_t i = ((size_t)blockIdx.x * 256 + threadIdx.x) * 4;
    float4 v = *(const float4*)(x + i);
    uint32_t h0, l0, h1, l1;
    split2(v.x, v.y, h0, l0);
    split2(v.z, v.w, h1, l1);
    *(uint2*)(xh + i) = make_uint2(h0, h1);
    *(uint2*)(xl + i) = make_uint2(l0, l1);
    __half2 f0 = __floats2half2_rn(v.x, v.y);
    __half2 f1 = __floats2half2_rn(v.z, v.w);
    *(uint2*)(x16 + i) = make_uint2(*(uint32_t*)&f0, *(uint32_t*)&f1);
}

__global__ void wpack_conv_kernel(
    const float* __restrict__ g_w, const float* __restrict__ g_b,
    const float* __restrict__ th_w, const float* __restrict__ th_b,
    const float* __restrict__ ph_w, const float* __restrict__ ph_b,
    __nv_bfloat16* __restrict__ Wh, __nv_bfloat16* __restrict__ Wl,
    __half* __restrict__ Wg16, float* __restrict__ bc)
{
    int oc = blockIdx.x, k = threadIdx.x;
    float v;
    if (oc < 256)       v = g_w[oc * 256 + k];
    else if (oc < 320)  v = (k < 64) ? th_w[(oc - 256) * 64 + k] : 0.f;
    else                v = (k >= 64) ? ph_w[(oc - 320) * 192 + (k - 64)] : 0.f;
    __nv_bfloat16 h, l; split_bf16(v, h, l);
    Wh[oc * 256 + k] = h; Wl[oc * 256 + k] = l;
    if (oc < 256) Wg16[oc * 256 + k] = __float2half_rn(v);
    if (k == 0)
        bc[oc] = (oc < 256) ? g_b[oc] : (oc < 320) ? th_b[oc - 256] : ph_b[oc - 320];
}

__global__ void wpack_final_kernel(const float* __restrict__ w, __half* __restrict__ Wf)
{
    int i = blockIdx.x * 256 + threadIdx.x;
    Wf[i] = __float2half_rn(w[i]);
}

// ======================================================================
// conv_all: merged conv_g (blockIdx.x 0..3, fp16 1-pass) and
// conv_qk (blockIdx.x 4..5, bf16 3-pass, zero-chunk skipping).
// grid (6, 32, 8), block 256 (4m x 2n), 2 CTAs/SM (106 KB smem).
// ======================================================================
static constexpr int CG_STG    = 26624;
static constexpr int CONV_STG  = 53248;
static constexpr int CONV_SMEM = 2 * CONV_STG;

__global__ __launch_bounds__(256, 2) void conv_all_kernel(
    const __half* __restrict__ x16, const __half* __restrict__ Wg,
    const __nv_bfloat16* __restrict__ xh, const __nv_bfloat16* __restrict__ xl,
    const __nv_bfloat16* __restrict__ Wh, const __nv_bfloat16* __restrict__ Wl,
    const float* __restrict__ bc,
    __half* __restrict__ V16,
    __nv_bfloat16* __restrict__ Qh, __nv_bfloat16* __restrict__ Ql,
    __nv_bfloat16* __restrict__ Kh, __nv_bfloat16* __restrict__ Kl)
{
    extern __shared__ char smem[];
    const uint32_t sb = smem_to_u32(smem);
    float* sRes = (float*)smem;
    const int tid = threadIdx.x, lane = tid & 31, wid = tid >> 5;
    const int wm = wid & 3, wn = wid >> 2;
    const int b = blockIdx.z, pxt = blockIdx.y;

    float acc[2][4][4];
#pragma unroll
    for (int mt = 0; mt < 2; mt++)
#pragma unroll
        for (int nt = 0; nt < 4; nt++)
#pragma unroll
            for (int e = 0; e < 4; e++) acc[mt][nt][e] = 0.f;

    if (blockIdx.x < 4) {
        // ------------- conv_g path (fp16 1-pass) -------------
        const int oc0 = blockIdx.x * 64;

        auto prefetch = [&](int c) {
            uint32_t base = sb + (c & 1) * CG_STG;
            const __half* gx = x16 + ((size_t)b * C_ + c * 64) * HW_ + pxt * 128;
            for (int idx = tid; idx < 1024; idx += 256) {
                int r = idx >> 4, u = idx & 15;
                cp16(base + (uint32_t)((r * 136 + u * 8) * 2), gx + (size_t)r * HW_ + u * 8);
            }
            const __half* gw = Wg + (size_t)oc0 * 256 + c * 64;
            for (int idx = tid; idx < 512; idx += 256) {
                int r = idx >> 3, u = idx & 7;
                cp16(base + 17408 + (uint32_t)((r * 72 + u * 8) * 2), gw + (size_t)r * 256 + u * 8);
            }
            CP_COMMIT();
        };

        prefetch(0);
        for (int ck = 0; ck < 4; ck++) {
            if (ck + 1 < 4) { prefetch(ck + 1); CP_WAIT1(); } else CP_WAIT0();
            __syncthreads();
            const uint32_t xb = sb + (ck & 1) * CG_STG;
            const uint32_t wb = xb + 17408;
#pragma unroll
            for (int ks = 0; ks < 4; ks++) {
                const int k0 = ks * 16;
                uint32_t a[2][4], bb[2][4];
                ldsm4t(a[0], at_addr(xb, wm * 32,      k0, lane, 136));
                ldsm4t(a[1], at_addr(xb, wm * 32 + 16, k0, lane, 136));
                ldsm4(bb[0], b_addrP(wb, wn * 32,      k0, lane, 72));
                ldsm4(bb[1], b_addrP(wb, wn * 32 + 16, k0, lane, 72));
#pragma unroll
                for (int g = 0; g < 2; g++)
#pragma unroll
                    for (int mt = 0; mt < 2; mt++) {
                        mma16816h(acc[mt][g*2],   a[mt], bb[g][0], bb[g][1]);
                        mma16816h(acc[mt][g*2+1], a[mt], bb[g][2], bb[g][3]);
                    }
            }
            __syncthreads();
        }

#pragma unroll
        for (int mt = 0; mt < 2; mt++) {
            const int row = wm * 32 + mt * 16 + (lane >> 2);
#pragma unroll
            for (int nt = 0; nt < 4; nt++) {
                const int col = wn * 32 + nt * 8 + (lane & 3) * 2;
                sRes[row * 68 + col]       = acc[mt][nt][0];
                sRes[row * 68 + col + 1]   = acc[mt][nt][1];
                sRes[(row+8) * 68 + col]   = acc[mt][nt][2];
                sRes[(row+8) * 68 + col+1] = acc[mt][nt][3];
            }
        }
        __syncthreads();

        for (int t = tid; t < 32 * 64; t += 256) {
            int pw = t >> 6, o = t & 63, oc = oc0 + o;
            float v = fmaxf(fmaxf(sRes[(2*pw)*68 + o], sRes[(2*pw+1)*68 + o]),
                            fmaxf(sRes[(64+2*pw)*68 + o], sRes[(65+2*pw)*68 + o]))
                      + bc[oc];
            size_t oidx = ((size_t)b * C_ + oc) * PHW_ + pxt * 32 + pw;
            V16[oidx] = __float2half_rn(v);
        }
    } else {
        // ------------- conv_qk path (bf16 3-pass) -------------
        const int qx  = blockIdx.x - 4;          // 0 = theta, 1 = phi
        const int oc0 = 256 + qx * 64;

        auto prefetch = [&](int c) {
            uint32_t base = sb + (c & 1) * CONV_STG;
            const __nv_bfloat16* gxh = xh + ((size_t)b * C_ + c * 64) * HW_ + pxt * 128;
            const __nv_bfloat16* gxl = xl + ((size_t)b * C_ + c * 64) * HW_ + pxt * 128;
            for (int idx = tid; idx < 1024; idx += 256) {
                int r = idx >> 4, u = idx & 15;
                uint32_t so = (uint32_t)((r * 136 + u * 8) * 2);
                cp16(base + so,         gxh + (size_t)r * HW_ + u * 8);
                cp16(base + 17408 + so, gxl + (size_t)r * HW_ + u * 8);
            }
            const __nv_bfloat16* gwh = Wh + (size_t)oc0 * 256 + c * 64;
            const __nv_bfloat16* gwl = Wl + (size_t)oc0 * 256 + c * 64;
            for (int idx = tid; idx < 512; idx += 256) {
                int r = idx >> 3, u = idx & 7;
                uint32_t so = (uint32_t)((r * 72 + u * 8) * 2);
                cp16(base + 34816 + so, gwh + (size_t)r * 256 + u * 8);
                cp16(base + 44032 + so, gwl + (size_t)r * 256 + u * 8);
            }
            CP_COMMIT();
        };

        const int ck_lo = (qx == 0) ? 0 : 1;
        const int n_ck  = (qx == 0) ? 1 : 3;

        prefetch(ck_lo);
        for (int ci = 0; ci < n_ck; ci++) {
            const int ck = ck_lo + ci;
            if (ci + 1 < n_ck) { prefetch(ck + 1); CP_WAIT1(); } else CP_WAIT0();
            __syncthreads();
            uint32_t base = sb + (ck & 1) * CONV_STG;
#pragma unroll
            for (int ks = 0; ks < 4; ks++) {
                const int k0 = ks * 16;
                uint32_t ah[2][4], al[2][4], bh[2][4], bl[2][4];
                ldsm4t(ah[0], at_addr(base, wm * 32,      k0, lane, 136));
                ldsm4t(ah[1], at_addr(base, wm * 32 + 16, k0, lane, 136));
                ldsm4(bh[0], b_addrP(base + 34816, wn * 32,      k0, lane, 72));
                ldsm4(bh[1], b_addrP(base + 34816, wn * 32 + 16, k0, lane, 72));
#pragma unroll
                for (int g = 0; g < 2; g++)
#pragma unroll
                    for (int mt = 0; mt < 2; mt++) {
                        mma16816(acc[mt][g*2],   ah[mt], bh[g][0], bh[g][1]);
                        mma16816(acc[mt][g*2+1], ah[mt], bh[g][2], bh[g][3]);
                    }
                ldsm4(bl[0], b_addrP(base + 44032, wn * 32,      k0, lane, 72));
                ldsm4(bl[1], b_addrP(base + 44032, wn * 32 + 16, k0, lane, 72));
#pragma unroll
                for (int g = 0; g < 2; g++)
#pragma unroll
                    for (int mt = 0; mt < 2; mt++) {
                        mma16816(acc[mt][g*2],   ah[mt], bl[g][0], bl[g][1]);
                        mma16816(acc[mt][g*2+1], ah[mt], bl[g][2], bl[g][3]);
                    }
                ldsm4t(al[0], at_addr(base + 17408, wm * 32,      k0, lane, 136));
                ldsm4t(al[1], at_addr(base + 17408, wm * 32 + 16, k0, lane, 136));
#pragma unroll
                for (int g = 0; g < 2; g++)
#pragma unroll
                    for (int mt = 0; mt < 2; mt++) {
                        mma16816(acc[mt][g*2],   al[mt], bh[g][0], bh[g][1]);
                        mma16816(acc[mt][g*2+1], al[mt], bh[g][2], bh[g][3]);
                    }
            }
            __syncthreads();
        }

#pragma unroll
        for (int mt = 0; mt < 2; mt++) {
            const int row = wm * 32 + mt * 16 + (lane >> 2);
#pragma unroll
            for (int nt = 0; nt < 4; nt++) {
                const int col = wn * 32 + nt * 8 + (lane & 3) * 2;
                sRes[row * 68 + col]       = acc[mt][nt][0];
                sRes[row * 68 + col + 1]   = acc[mt][nt][1];
                sRes[(row+8) * 68 + col]   = acc[mt][nt][2];
                sRes[(row+8) * 68 + col+1] = acc[mt][nt][3];
            }
        }
        __syncthreads();

        if (qx == 0) {
            for (int t = tid; t < 128 * 64; t += 256) {
                int p = t >> 6, o = t & 63;
                float v = sRes[p * 68 + o] + bc[256 + o];
                __nv_bfloat16 h, l; split_bf16(v, h, l);
                size_t oidx = ((size_t)b * HW_ + pxt * 128 + p) * 64 + o;
                Qh[oidx] = h; Ql[oidx] = l;
            }
        } else {
            for (int t = tid; t < 32 * 64; t += 256) {
                int pw = t >> 6, o = t & 63;
                float v = fmaxf(fmaxf(sRes[(2*pw)*68 + o], sRes[(2*pw+1)*68 + o]),
                                fmaxf(sRes[(64+2*pw)*68 + o], sRes[(65+2*pw)*68 + o]))
                          + bc[320 + o];
                __nv_bfloat16 h, l; split_bf16(v, h, l);
                size_t oidx = ((size_t)b * PHW_ + pxt * 32 + pw) * 64 + o;
                Kh[oidx] = h; Kl[oidx] = l;
            }
        }
    }
}

// ======================================================================
// qk_mma: split-bf16 3-pass, SPLIT-K over 2 column halves.
// grid (32, 16): by>>1 = batch, by&1 = K-half (chunks half*4..half*4+3).
// Each half writes its own rmax plane; pv combines with fmax. Bit-identical.
// ======================================================================
static constexpr int QK_SMEM = 110592 + 1024;

__global__ __launch_bounds__(256, 2) void qk_mma_kernel(
    const __nv_bfloat16* __restrict__ Qh, const __nv_bfloat16* __restrict__ Ql,
    const __nv_bfloat16* __restrict__ Kh, const __nv_bfloat16* __restrict__ Kl,
    float* __restrict__ Sf, float* __restrict__ rmax)
{
    extern __shared__ char smem[];
    const uint32_t sb = smem_to_u32(smem);
    __nv_bfloat16* sQ = (__nv_bfloat16*)smem;
    float* rs = (float*)(smem + 110592);
    const int tid = threadIdx.x, lane = tid & 31, wid = tid >> 5;
    const int wm = wid & 3, wn = wid >> 2;
    const int b = blockIdx.y >> 1, half = blockIdx.y & 1;
    const int n0 = blockIdx.x * 128;
    const int ck_lo = half * 4;

    auto prefetch = [&](int c) {
        uint32_t base = sb + 36864 + (c & 1) * 36864;
        const __nv_bfloat16* gkh = Kh + ((size_t)b * PHW_ + c * 128) * 64;
        const __nv_bfloat16* gkl = Kl + ((size_t)b * PHW_ + c * 128) * 64;
        for (int idx = tid; idx < 1024; idx += 256) {
            int r = idx >> 3, u = idx & 7;
            uint32_t so = (uint32_t)((r * 72 + u * 8) * 2);
            cp16(base + so,         gkh + r * 64 + u * 8);
            cp16(base + 18432 + so, gkl + r * 64 + u * 8);
        }
        CP_COMMIT();
    };

    prefetch(ck_lo);
    {
        const __nv_bfloat16* gqh = Qh + ((size_t)b * HW_ + n0) * 64;
        const __nv_bfloat16* gql = Ql + ((size_t)b * HW_ + n0) * 64;
        for (int idx = tid; idx < 1024; idx += 256) {
            int r = idx >> 3, u = idx & 7;
            *(uint4*)(sQ + r * 72 + u * 8)        = *(const uint4*)(gqh + r * 64 + u * 8);
            *(uint4*)(sQ + 9216 + r * 72 + u * 8) = *(const uint4*)(gql + r * 64 + u * 8);
        }
    }

    float rmx[2][2] = {{-1e30f, -1e30f}, {-1e30f, -1e30f}};

    for (int ci = 0; ci < 4; ci++) {
        const int ck = ck_lo + ci;
        const int m0 = ck * 128;
        if (ci + 1 < 4) { prefetch(ck + 1); CP_WAIT1(); } else CP_WAIT0();
        __syncthreads();
        uint32_t kb = sb + 36864 + (ck & 1) * 36864;

        float acc[2][8][4];
#pragma unroll
        for (int mt = 0; mt < 2; mt++)
#pragma unroll
            for (int nt = 0; nt < 8; nt++)
#pragma unroll
                for (int e = 0; e < 4; e++) acc[mt][nt][e] = 0.f;

#pragma unroll
        for (int ks = 0; ks < 4; ks++) {
            const int k0 = ks * 16;
            uint32_t ah[2][4], al[2][4];
            ldsm4(ah[0], a_addrP(sb,         wm * 32,      k0, lane, 72));
            ldsm4(ah[1], a_addrP(sb,         wm * 32 + 16, k0, lane, 72));
            ldsm4(al[0], a_addrP(sb + 18432, wm * 32,      k0, lane, 72));
            ldsm4(al[1], a_addrP(sb + 18432, wm * 32 + 16, k0, lane, 72));
#pragma unroll
            for (int g = 0; g < 4; g++) {
                uint32_t bh[4], bl[4];
                ldsm4(bh, b_addrP(kb,         wn * 64 + g * 16, k0, lane, 72));
                ldsm4(bl, b_addrP(kb + 18432, wn * 64 + g * 16, k0, lane, 72));
#pragma unroll
                for (int mt = 0; mt < 2; mt++) {
                    mma16816(acc[mt][g*2],   ah[mt], bh[0], bh[1]);
                    mma16816(acc[mt][g*2+1], ah[mt], bh[2], bh[3]);
                }
#pragma unroll
                for (int mt = 0; mt < 2; mt++) {
                    mma16816(acc[mt][g*2],   ah[mt], bl[0], bl[1]);
                    mma16816(acc[mt][g*2+1], ah[mt], bl[2], bl[3]);
                }
#pragma unroll
                for (int mt = 0; mt < 2; mt++) {
                    mma16816(acc[mt][g*2],   al[mt], bh[0], bh[1]);
                    mma16816(acc[mt][g*2+1], al[mt], bh[2], bh[3]);
                }
            }
        }

#pragma unroll
        for (int mt = 0; mt < 2; mt++) {
            const int row = n0 + wm * 32 + mt * 16 + (lane >> 2);
#pragma unroll
            for (int nt = 0; nt < 8; nt++) {
                float s0 = acc[mt][nt][0], s1 = acc[mt][nt][1];
                float s2 = acc[mt][nt][2], s3 = acc[mt][nt][3];
                rmx[mt][0] = fmaxf(rmx[mt][0], fmaxf(s0, s1));
                rmx[mt][1] = fmaxf(rmx[mt][1], fmaxf(s2, s3));
                const int col = m0 + wn * 64 + nt * 8 + (lane & 3) * 2;
                *(float2*)&Sf[((size_t)b * HW_ + row) * PHW_ + col] = make_float2(s0, s1);
                *(float2*)&Sf[((size_t)b * HW_ + row + 8) * PHW_ + col] = make_float2(s2, s3);
            }
        }
        __syncthreads();
    }

#pragma unroll
    for (int mt = 0; mt < 2; mt++)
#pragma unroll
        for (int hh = 0; hh < 2; hh++) {
            float m = rmx[mt][hh];
            m = fmaxf(m, __shfl_xor_sync(0xffffffffu, m, 1));
            m = fmaxf(m, __shfl_xor_sync(0xffffffffu, m, 2));
            if ((lane & 3) == 0)
                rs[wn * 128 + wm * 32 + mt * 16 + hh * 8 + (lane >> 2)] = m;
        }
    __syncthreads();
    if (tid < 128)
        rmax[(size_t)half * (BB * HW_) + (size_t)b * HW_ + n0 + tid] =
            fmaxf(rs[tid], rs[128 + tid]);
}

// ======================================================================
// pv_mma (fp16 1-pass): rmax = fmax of the two K-half planes. Else unchanged.
// ======================================================================
static constexpr int PV_STG  = 29696;
static constexpr int PV_P16  = 2 * PV_STG;
static constexpr int PV_RS   = PV_P16 + 5120;
static constexpr int PV_SMEM = PV_RS + 256;

__global__ __launch_bounds__(256, 2) void pv_mma_kernel(
    const float* __restrict__ Sf, const __half* __restrict__ V16,
    const float* __restrict__ rmax, __half* __restrict__ Yf)
{
    extern __shared__ char smem[];
    const uint32_t sb = smem_to_u32(smem);
    const int tid = threadIdx.x, lane = tid & 31, wid = tid >> 5;
    const int wm = wid & 1, wn = wid >> 1;
    const int b = blockIdx.y, n0 = blockIdx.x * 64;

    auto prefetch = [&](int c) {
        uint32_t base = sb + (c & 1) * PV_STG;
        const float* gs = Sf + ((size_t)b * HW_ + n0) * PHW_ + c * 32;
        for (int idx = tid; idx < 512; idx += 256) {
            int r = idx >> 3, u = idx & 7;
            cp16(base + (uint32_t)((r * 36 + u * 4) * 4), gs + (size_t)r * PHW_ + u * 4);
        }
        const __half* gv = V16 + (size_t)b * C_ * PHW_ + c * 32;
        for (int idx = tid; idx < 1024; idx += 256) {
            int r = idx >> 2, u = idx & 3;
            cp16(base + 9216 + (uint32_t)((r * 40 + u * 8) * 2), gv + (size_t)r * PHW_ + u * 8);
        }
        CP_COMMIT();
    };

    const int crow = tid >> 2, cu = tid & 3;
    const size_t ridx = (size_t)b * HW_ + n0 + crow;
    const float rmx = fmaxf(rmax[ridx], rmax[(size_t)BB * HW_ + ridx]);
    float rsum_loc = 0.f;

    float acc[2][8][4];
#pragma unroll
    for (int mt = 0; mt < 2; mt++)
#pragma unroll
        for (int nt = 0; nt < 8; nt++)
#pragma unroll
            for (int e = 0; e < 4; e++) acc[mt][nt][e] = 0.f;

    prefetch(0);
    for (int ck = 0; ck < 32; ck++) {
        CP_WAIT0();
        __syncthreads();
        if (ck + 1 < 32) prefetch(ck + 1);
        {
            const float* srow = (const float*)(smem + (ck & 1) * PV_STG) + crow * 36 + cu * 8;
            float4 s0 = *(const float4*)(srow);
            float4 s1 = *(const float4*)(srow + 4);
            float p0 = __expf(s0.x - rmx), p1 = __expf(s0.y - rmx);
            float p2 = __expf(s0.z - rmx), p3 = __expf(s0.w - rmx);
            float p4 = __expf(s1.x - rmx), p5 = __expf(s1.y - rmx);
            float p6 = __expf(s1.z - rmx), p7 = __expf(s1.w - rmx);
            rsum_loc += (p0 + p1 + p2 + p3) + (p4 + p5 + p6 + p7);
            __half2 h0 = __floats2half2_rn(p0, p1), h1 = __floats2half2_rn(p2, p3);
            __half2 h2 = __floats2half2_rn(p4, p5), h3 = __floats2half2_rn(p6, p7);
            uint4 pk;
            pk.x = *(uint32_t*)&h0; pk.y = *(uint32_t*)&h1;
            pk.z = *(uint32_t*)&h2; pk.w = *(uint32_t*)&h3;
            *(uint4*)(smem + PV_P16 + (crow * 40 + cu * 8) * 2) = pk;
        }
        __syncthreads();
        const uint32_t pb = sb + PV_P16;
        const uint32_t vb = sb + (ck & 1) * PV_STG + 9216;
#pragma unroll
        for (int ks = 0; ks < 2; ks++) {
            const int k0 = ks * 16;
            uint32_t a[2][4], bh[4][4];
            ldsm4(a[0], a_addrP(pb, wm * 32,      k0, lane, 40));
            ldsm4(a[1], a_addrP(pb, wm * 32 + 16, k0, lane, 40));
#pragma unroll
            for (int g = 0; g < 4; g++)
                ldsm4(bh[g], b_addrP(vb, wn * 64 + g * 16, k0, lane, 40));
#pragma unroll
            for (int g = 0; g < 4; g++)
#pragma unroll
                for (int mt = 0; mt < 2; mt++) {
                    mma16816h(acc[mt][g*2],   a[mt], bh[g][0], bh[g][1]);
                    mma16816h(acc[mt][g*2+1], a[mt], bh[g][2], bh[g][3]);
                }
        }
    }

    {
        float s = rsum_loc;
        s += __shfl_xor_sync(0xffffffffu, s, 1);
        s += __shfl_xor_sync(0xffffffffu, s, 2);
        if (cu == 0) ((float*)(smem + PV_RS))[crow] = s;
    }
    __syncthreads();
    const float* rsArr = (const float*)(smem + PV_RS);

#pragma unroll
    for (int mt = 0; mt < 2; mt++) {
        const int rl = wm * 32 + mt * 16 + (lane >> 2);
        const int r0 = n0 + rl;
        const float i0 = 1.f / rsArr[rl];
        const float i1 = 1.f / rsArr[rl + 8];
#pragma unroll
        for (int nt = 0; nt < 8; nt++) {
            const int col = wn * 64 + nt * 8 + (lane & 3) * 2;
            __half2 p0 = __floats2half2_rn(acc[mt][nt][0] * i0, acc[mt][nt][1] * i0);
            __half2 p1 = __floats2half2_rn(acc[mt][nt][2] * i1, acc[mt][nt][3] * i1);
            *(__half2*)&Yf[((size_t)b * HW_ + r0) * C_ + col] = p0;
            *(__half2*)&Yf[((size_t)b * HW_ + r0 + 8) * C_ + col] = p1;
        }
    }
}

// ======================================================================
// final_mma (fp16 1-pass): unchanged
// ======================================================================
static constexpr int FIN_STG  = 27648;
static constexpr int FIN_SMEM = 2 * FIN_STG;

__global__ __launch_bounds__(256, 2) void final_mma_kernel(
    const __half* __restrict__ Yf, const __half* __restrict__ Wf,
    const float* __restrict__ Wb,
    const float* __restrict__ gamma, const float* __restrict__ beta,
    const float* __restrict__ mean, const float* __restrict__ var,
    const float* __restrict__ x, float* __restrict__ out)
{
    extern __shared__ char smem[];
    const uint32_t sb = smem_to_u32(smem);
    float* sRes = (float*)smem;
    const int tid = threadIdx.x, lane = tid & 31, wid = tid >> 5;
    const int wm = wid & 3, wn = wid >> 2;
    const int b = blockIdx.z, pxt = blockIdx.y, oc0 = blockIdx.x * 64;

    auto prefetch = [&](int c) {
        uint32_t base = sb + (c & 1) * FIN_STG;
        const __half* gA = Yf + ((size_t)b * HW_ + pxt * 128) * C_ + c * 64;
        for (int idx = tid; idx < 1024; idx += 256) {
            int r = idx >> 3, u = idx & 7;
            cp16(base + (uint32_t)((r * 72 + u * 8) * 2), gA + (size_t)r * C_ + u * 8);
        }
        const __half* gB = Wf + (size_t)oc0 * 256 + c * 64;
        for (int idx = tid; idx < 512; idx += 256) {
            int r = idx >> 3, u = idx & 7;
            cp16(base + 18432 + (uint32_t)((r * 72 + u * 8) * 2), gB + (size_t)r * 256 + u * 8);
        }
        CP_COMMIT();
    };

    float acc[2][4][4];
#pragma unroll
    for (int mt = 0; mt < 2; mt++)
#pragma unroll
        for (int nt = 0; nt < 4; nt++)
#pragma unroll
            for (int e = 0; e < 4; e++) acc[mt][nt][e] = 0.f;

    prefetch(0);
    for (int ck = 0; ck < 4; ck++) {
        if (ck + 1 < 4) { prefetch(ck + 1); CP_WAIT1(); } else CP_WAIT0();
        __syncthreads();
        uint32_t base = sb + (ck & 1) * FIN_STG;
#pragma unroll
        for (int ks = 0; ks < 4; ks++) {
            const int k0 = ks * 16;
            uint32_t a[2][4], bb[2][4];
            ldsm4(a[0], a_addrP(base, wm * 32,      k0, lane, 72));
            ldsm4(a[1], a_addrP(base, wm * 32 + 16, k0, lane, 72));
            ldsm4(bb[0], b_addrP(base + 18432, wn * 32,      k0, lane, 72));
            ldsm4(bb[1], b_addrP(base + 18432, wn * 32 + 16, k0, lane, 72));
#pragma unroll
            for (int g = 0; g < 2; g++)
#pragma unroll
                for (int mt = 0; mt < 2; mt++) {
                    mma16816h(acc[mt][g*2],   a[mt], bb[g][0], bb[g][1]);
                    mma16816h(acc[mt][g*2+1], a[mt], bb[g][2], bb[g][3]);
                }
        }
        __syncthreads();
    }

#pragma unroll
    for (int mt = 0; mt < 2; mt++) {
        const int row = wm * 32 + mt * 16 + (lane >> 2);
#pragma unroll
        for (int nt = 0; nt < 4; nt++) {
            const int col = wn * 32 + nt * 8 + (lane & 3) * 2;
            sRes[row * 68 + col]       = acc[mt][nt][0];
            sRes[row * 68 + col + 1]   = acc[mt][nt][1];
            sRes[(row+8) * 68 + col]   = acc[mt][nt][2];
            sRes[(row+8) * 68 + col+1] = acc[mt][nt][3];
        }
    }
    __syncthreads();

    for (int t = tid; t < 128 * 64; t += 256) {
        int o = t >> 7, p = t & 127;
        int oc = oc0 + o;
        float scale = gamma[oc] * rsqrtf(var[oc] + EPS_);
        size_t gidx = ((size_t)b * C_ + oc) * HW_ + pxt * 128 + p;
        out[gidx] = (sRes[p * 68 + o] + Wb[oc] - mean[oc]) * scale + beta[oc] + x[gidx];
    }
}

// ======================================================================
extern "C" void kernel_launch(void* const* d_in, const int* in_sizes, int n_in,
                              void* d_out, int out_size)
{
    const float* x       = (const float*)d_in[0];
    const float* g_w     = (const float*)d_in[1];
    const float* g_b     = (const float*)d_in[2];
    const float* theta_w = (const float*)d_in[3];
    const float* theta_b = (const float*)d_in[4];
    const float* phi_w   = (const float*)d_in[5];
    const float* phi_b   = (const float*)d_in[6];
    const float* W_w     = (const float*)d_in[7];
    const float* W_b     = (const float*)d_in[8];
    const float* bn_g    = (const float*)d_in[9];
    const float* bn_b    = (const float*)d_in[10];
    const float* bn_m    = (const float*)d_in[11];
    const float* bn_v    = (const float*)d_in[12];
    float* out = (float*)d_out;

    __nv_bfloat16 *xh, *xl, *Wch, *Wcl, *Qh, *Ql, *Kh, *Kl;
    float *Sf, *rmx, *bc;
    __half *x16, *Wg16, *Wff, *V16, *Yf;
    cudaGetSymbolAddress((void**)&xh,   d_xh);
    cudaGetSymbolAddress((void**)&xl,   d_xl);
    cudaGetSymbolAddress((void**)&x16,  d_x16);
    cudaGetSymbolAddress((void**)&Wch,  d_Wch);
    cudaGetSymbolAddress((void**)&Wcl,  d_Wcl);
    cudaGetSymbolAddress((void**)&Wg16, d_Wg16);
    cudaGetSymbolAddress((void**)&bc,   d_bc);
    cudaGetSymbolAddress((void**)&Wff,  d_Wff);
    cudaGetSymbolAddress((void**)&Qh,   d_Qh);
    cudaGetSymbolAddress((void**)&Ql,   d_Ql);
    cudaGetSymbolAddress((void**)&Kh,   d_Kh);
    cudaGetSymbolAddress((void**)&Kl,   d_Kl);
    cudaGetSymbolAddress((void**)&V16,  d_V16);
    cudaGetSymbolAddress((void**)&Sf,   d_Sf);
    cudaGetSymbolAddress((void**)&rmx,  d_rmax);
    cudaGetSymbolAddress((void**)&Yf,   d_Yf);

    cudaFuncSetAttribute(conv_all_kernel,  cudaFuncAttributeMaxDynamicSharedMemorySize, CONV_SMEM);
    cudaFuncSetAttribute(qk_mma_kernel,    cudaFuncAttributeMaxDynamicSharedMemorySize, QK_SMEM);
    cudaFuncSetAttribute(pv_mma_kernel,    cudaFuncAttributeMaxDynamicSharedMemorySize, PV_SMEM);
    cudaFuncSetAttribute(final_mma_kernel, cudaFuncAttributeMaxDynamicSharedMemorySize, FIN_SMEM);

    xsplit_kernel<<<BB * C_ * HW_ / 1024, 256>>>(x, xh, xl, x16);
    wpack_conv_kernel<<<384, 256>>>(g_w, g_b, theta_w, theta_b, phi_w, phi_b,
                                    Wch, Wcl, Wg16, bc);
    wpack_final_kernel<<<256, 256>>>(W_w, Wff);
    conv_all_kernel<<<dim3(6, 32, BB), 256, CONV_SMEM>>>(x16, Wg16, xh, xl, Wch, Wcl, bc,
                                                         V16, Qh, Ql, Kh, Kl);
    qk_mma_kernel<<<dim3(32, 2 * BB), 256, QK_SMEM>>>(Qh, Ql, Kh, Kl, Sf, rmx);
    pv_mma_kernel<<<dim3(64, BB), 256, PV_SMEM>>>(Sf, V16, rmx, Yf);
    final_mma_kernel<<<dim3(4, 32, BB), 256, FIN_SMEM>>>(Yf, Wff, W_b,
                                                         bn_g, bn_b, bn_m, bn_v, x, out);
}